// round 11
// baseline (speedup 1.0000x reference)
#include <cuda_runtime.h>
#include <cuda_fp16.h>
#include <cstdint>

#define NN 50000
#define DD 128
#define RR 8
#define EE 800000
#define EDD 32
#define NR (NN*RR)
#define M2 (RR*NN)

typedef unsigned long long u64;

// ---------------- scratch ----------------
__device__ float  g_deg[NR];                 // indexed by tr = r*NN + no
__device__ __half g_aggef[NR*EDD];           // [r][no][32]
__device__ __half g_aggx[(size_t)NR*DD];     // [r][no][128]
__device__ __half g_xh[(size_t)NN*DD];       // x in half
__device__ float  g_hpre[NN*DD];
__device__ float  g_hW2[NN*DD];
__device__ float  g_hs[NN*DD];
__device__ float  g_WeWlin1[RR*EDD*DD];
__device__ float  g_WeWlin2[EDD*DD];
__device__ float  g_beWlin1[RR*DD];
__device__ float  g_beWlin2[DD];
__device__ float  g_bias1[DD];
__device__ float  g_bias2[DD];
__device__ double g_s1a[DD], g_s2a[DD], g_s1b[DD], g_s2b[DD];
// CSR by tr
__device__ int   g_cnt[NR];
__device__ int   g_off[NR];
__device__ int   g_cur[NR];
__device__ int   g_bsum[512];
__device__ int4  g_csr4[EE];                 // {nin, eid, ew_bits, 0}

// ---------------- helpers ----------------
__device__ __forceinline__ uint32_t smem_u32(const void* p) {
    uint32_t a;
    asm("{ .reg .u64 t; cvta.to.shared.u64 t, %1; cvt.u32.u64 %0, t; }" : "=r"(a) : "l"(p));
    return a;
}
__device__ __forceinline__ u64 pack2(float lo, float hi) {
    u64 r; asm("mov.b64 %0, {%1, %2};" : "=l"(r) : "f"(lo), "f"(hi)); return r;
}
__device__ __forceinline__ u64 dup2(float v) {
    u64 r; asm("mov.b64 %0, {%1, %1};" : "=l"(r) : "f"(v)); return r;
}
__device__ __forceinline__ void unpack2(u64 v, float& lo, float& hi) {
    asm("mov.b64 {%0, %1}, %2;" : "=f"(lo), "=f"(hi) : "l"(v));
}
__device__ __forceinline__ void fma2(u64& d, u64 a, u64 b) {
    asm("fma.rn.f32x2 %0, %1, %2, %0;" : "+l"(d) : "l"(a), "l"(b));
}
__device__ __forceinline__ void mma_tf32(float* d, const uint32_t* a,
                                         uint32_t b0, uint32_t b1) {
    asm volatile(
        "mma.sync.aligned.m16n8k8.row.col.f32.tf32.tf32.f32 "
        "{%0,%1,%2,%3}, {%4,%5,%6,%7}, {%8,%9}, {%0,%1,%2,%3};"
        : "+f"(d[0]), "+f"(d[1]), "+f"(d[2]), "+f"(d[3])
        : "r"(a[0]), "r"(a[1]), "r"(a[2]), "r"(a[3]), "r"(b0), "r"(b1));
}
__device__ __forceinline__ void cpa16(uint32_t d, const void* s) {
    asm volatile("cp.async.ca.shared.global [%0], [%1], 16;" :: "r"(d), "l"(s) : "memory");
}

// ---------------- init: zero small buffers + x->half ----------------
__global__ __launch_bounds__(256) void init_k(const float* __restrict__ x) {
    size_t i = (size_t)blockIdx.x * blockDim.x + threadIdx.x;
    size_t stride = (size_t)gridDim.x * blockDim.x;
    float4 z = make_float4(0.f, 0.f, 0.f, 0.f);
    float4* d = (float4*)g_deg;
    for (size_t j = i; j < (size_t)NR / 4; j += stride) d[j] = z;
    int4* c = (int4*)g_cnt;
    int4 zi = make_int4(0, 0, 0, 0);
    for (size_t j = i; j < (size_t)NR / 4; j += stride) c[j] = zi;
    for (size_t j = i; j < (size_t)NN * 32; j += stride) {
        float4 v = ((const float4*)x)[j];
        __half2* dst = (__half2*)g_xh + j * 2;
        dst[0] = __floats2half2_rn(v.x, v.y);
        dst[1] = __floats2half2_rn(v.z, v.w);
    }
    if (i < DD) { g_s1a[i] = 0.0; g_s2a[i] = 0.0; g_s1b[i] = 0.0; g_s2b[i] = 0.0; }
}

// ---------------- prep: folds ----------------
__global__ __launch_bounds__(128) void prep_k(
    const float* __restrict__ l1_We, const float* __restrict__ l1_Wlin,
    const float* __restrict__ l1_be, const float* __restrict__ l1_blin,
    const float* __restrict__ l1_bself,
    const float* __restrict__ l2_We, const float* __restrict__ l2_Wlin,
    const float* __restrict__ l2_be, const float* __restrict__ l2_blin,
    const float* __restrict__ l2_bself)
{
    __shared__ float sWe[EDD * DD];
    __shared__ float sbe[DD];
    int r = blockIdx.x;
    int d = threadIdx.x;
    const float* We = (r < RR) ? l1_We : l2_We;
    const float* Wl = (r < RR) ? l1_Wlin : l2_Wlin;
    const float* be = (r < RR) ? l1_be : l2_be;
    for (int i = d; i < EDD * DD; i += 128) sWe[i] = We[i];
    sbe[d] = be[d];
    __syncthreads();
    float acc[EDD];
#pragma unroll
    for (int i = 0; i < EDD; i++) acc[i] = 0.f;
    float accb = 0.f;
    int rowoff = (r < RR) ? r * DD : 0;
    for (int k = 0; k < DD; k++) {
        float wl = Wl[(size_t)(rowoff + k) * DD + d];
        accb += sbe[k] * wl;
#pragma unroll
        for (int i = 0; i < EDD; i++) acc[i] += sWe[i * DD + k] * wl;
    }
    if (r < RR) {
#pragma unroll
        for (int i = 0; i < EDD; i++) g_WeWlin1[(size_t)(r * EDD + i) * DD + d] = acc[i];
        g_beWlin1[r * DD + d] = accb;
    } else {
#pragma unroll
        for (int i = 0; i < EDD; i++) g_WeWlin2[(size_t)i * DD + d] = acc[i];
        g_beWlin2[d] = accb;
        g_bias1[d] = l1_blin[d] + l1_bself[d];
        g_bias2[d] = l2_blin[d] + l2_bself[d];
    }
}

// ---------------- degree + histogram (by tr) ----------------
__global__ void deg_k(const int* __restrict__ nout, const int* __restrict__ rel,
                      const float* __restrict__ w) {
    int e = blockIdx.x * blockDim.x + threadIdx.x;
    if (e < EE) {
        int tr = rel[e] * NN + nout[e];
        atomicAdd(&g_deg[tr], w[e]);
        atomicAdd(&g_cnt[tr], 1);
    }
}

// ---------------- scan (exclusive prefix over g_cnt) ----------------
#define SCAN_BLK 1024
__global__ __launch_bounds__(1024) void scan1_k() {
    __shared__ int sh[SCAN_BLK];
    int t = threadIdx.x;
    int i = blockIdx.x * SCAN_BLK + t;
    sh[t] = (i < NR) ? g_cnt[i] : 0;
    __syncthreads();
    for (int s = 512; s > 0; s >>= 1) {
        if (t < s) sh[t] += sh[t + s];
        __syncthreads();
    }
    if (t == 0) g_bsum[blockIdx.x] = sh[0];
}
__global__ __launch_bounds__(512) void scan2_k() {
    __shared__ int sh[512];
    int t = threadIdx.x;
    int nb = (NR + SCAN_BLK - 1) / SCAN_BLK;
    int orig = (t < nb) ? g_bsum[t] : 0;
    sh[t] = orig;
    __syncthreads();
    for (int d = 1; d < 512; d <<= 1) {
        int x = (t >= d) ? sh[t - d] : 0;
        __syncthreads();
        sh[t] += x;
        __syncthreads();
    }
    if (t < nb) g_bsum[t] = sh[t] - orig;
}
__global__ __launch_bounds__(1024) void scan3_k() {
    __shared__ int sh[SCAN_BLK];
    int t = threadIdx.x;
    int i = blockIdx.x * SCAN_BLK + t;
    int orig = (i < NR) ? g_cnt[i] : 0;
    sh[t] = orig;
    __syncthreads();
    for (int d = 1; d < SCAN_BLK; d <<= 1) {
        int x = (t >= d) ? sh[t - d] : 0;
        __syncthreads();
        sh[t] += x;
        __syncthreads();
    }
    if (i < NR) {
        int excl = sh[t] - orig + g_bsum[blockIdx.x];
        g_off[i] = excl;
        g_cur[i] = excl;
    }
}
__global__ void place_k(const int* __restrict__ nin, const int* __restrict__ nout,
                        const int* __restrict__ rel, const float* __restrict__ w) {
    int e = blockIdx.x * blockDim.x + threadIdx.x;
    if (e < EE) {
        int tr = rel[e] * NN + nout[e];
        int pos = atomicAdd(&g_cur[tr], 1);
        g_csr4[pos] = make_int4(nin[e], e, __float_as_int(w[e] / g_deg[tr]), 0);
    }
}

// ---------------- agg1x: warp-per-tr CSR gather (x L2-resident) -----------
__global__ __launch_bounds__(256) void agg1x_k(const float* __restrict__ x,
                                               const float* __restrict__ ef) {
    int tid = threadIdx.x;
    int wid = tid >> 5;
    int lane = tid & 31;
    int c4 = lane << 2;
    int tr = blockIdx.x * 8 + wid;
    if (tr >= NR) return;

    int off = g_off[tr];
    int cnt = g_cnt[tr];
    float4 xa = make_float4(0.f, 0.f, 0.f, 0.f);
    float4 xb = make_float4(0.f, 0.f, 0.f, 0.f);
    float ea = 0.f, eb = 0.f;
    int j = 0;
    for (; j + 2 <= cnt; j += 2) {
        int4 c0 = __ldg(&g_csr4[off + j]);
        int4 c1 = __ldg(&g_csr4[off + j + 1]);
        float w0 = __int_as_float(c0.z), w1 = __int_as_float(c1.z);
        float4 x0 = __ldg((const float4*)&x[(size_t)c0.x * DD + c4]);
        float4 x1 = __ldg((const float4*)&x[(size_t)c1.x * DD + c4]);
        float f0 = __ldg(&ef[(size_t)c0.y * EDD + lane]);
        float f1 = __ldg(&ef[(size_t)c1.y * EDD + lane]);
        xa.x += w0 * x0.x; xa.y += w0 * x0.y; xa.z += w0 * x0.z; xa.w += w0 * x0.w;
        xb.x += w1 * x1.x; xb.y += w1 * x1.y; xb.z += w1 * x1.z; xb.w += w1 * x1.w;
        ea += w0 * f0; eb += w1 * f1;
    }
    if (j < cnt) {
        int4 c0 = __ldg(&g_csr4[off + j]);
        float w0 = __int_as_float(c0.z);
        float4 x0 = __ldg((const float4*)&x[(size_t)c0.x * DD + c4]);
        xa.x += w0 * x0.x; xa.y += w0 * x0.y; xa.z += w0 * x0.z; xa.w += w0 * x0.w;
        ea += w0 * __ldg(&ef[(size_t)c0.y * EDD + lane]);
    }
    xa.x += xb.x; xa.y += xb.y; xa.z += xb.z; xa.w += xb.w;
    __half2* dst = (__half2*)&g_aggx[(size_t)tr * DD + c4];
    dst[0] = __floats2half2_rn(xa.x, xa.y);
    dst[1] = __floats2half2_rn(xa.z, xa.w);
    g_aggef[(size_t)tr * EDD + lane] = __float2half_rn(ea + eb);
}

// ---------------- mma_L1: hpre = [aggx|aggef|x]@[Wlin1;WeWlin1;Wself1] ----
// K = 1408 (44 chunks); epilogue: +bias1 +mask*beW1, BN1 stats.
#define A_PADH 40
#define A_BYTES (128 * A_PADH * 2)
#define B_BYTES (32 * 132 * 4)
#define STG_BYTES (A_BYTES + B_BYTES)
#define MMAL1_SMEM (3 * STG_BYTES)
#define NCH_L1 44

__global__ void __launch_bounds__(256, 2) mma_L1_k(
    const float* __restrict__ Wlin1, const float* __restrict__ Wself1)
{
    extern __shared__ char smc[];
    __shared__ float sBe[RR * DD];
    __shared__ float sBias[DD];
    int tid = threadIdx.x;
    int m0 = blockIdx.x * 128;
    uint32_t sb = smem_u32(smc);

    for (int i = tid; i < RR * DD; i += 256) sBe[i] = g_beWlin1[i];
    if (tid < DD) sBias[tid] = g_bias1[tid];

    auto load_stage = [&](int s, int kc) {
        const __half* Asrc;
        const float* Bsrc;
        int astride;
        if (kc < 32) {
            int r = kc >> 2;
            Asrc = g_aggx + (size_t)r * NN * DD + (kc & 3) * 32;
            astride = DD;
            Bsrc = Wlin1 + (size_t)kc * 32 * DD;
        } else if (kc < 40) {
            int r = kc - 32;
            Asrc = g_aggef + (size_t)r * NN * EDD;
            astride = EDD;
            Bsrc = g_WeWlin1 + (size_t)r * EDD * DD;
        } else {
            Asrc = g_xh + (kc - 40) * 32;
            astride = DD;
            Bsrc = Wself1 + (size_t)(kc - 40) * 32 * DD;
        }
#pragma unroll
        for (int j = 0; j < 2; j++) {
            int p = tid + j * 256;
            int row = p >> 2;
            int kq = (p & 3) * 8;
            uint32_t doff = sb + s * STG_BYTES + row * (A_PADH * 2) + kq * 2;
            int m = m0 + row;
            if (m < NN) cpa16(doff, Asrc + (size_t)m * astride + kq);
            else {
                float4 z = make_float4(0.f, 0.f, 0.f, 0.f);
                *(float4*)(smc + s * STG_BYTES + row * (A_PADH * 2) + kq * 2) = z;
            }
        }
#pragma unroll
        for (int j = 0; j < 4; j++) {
            int p = tid + j * 256;
            int k = p >> 5;
            int n4 = (p & 31) << 2;
            uint32_t doff = sb + s * STG_BYTES + A_BYTES + (k * 132 + n4) * 4;
            cpa16(doff, Bsrc + (size_t)k * DD + n4);
        }
        asm volatile("cp.async.commit_group;" ::: "memory");
    };

    int wid = tid >> 5, lane = tid & 31;
    int g = lane >> 2, t = lane & 3;
    int wm = (wid & 3) * 32, wn = (wid >> 2) * 64;

    float acc[2][8][4];
#pragma unroll
    for (int mi = 0; mi < 2; mi++)
#pragma unroll
        for (int ni = 0; ni < 8; ni++) {
            acc[mi][ni][0] = 0.f; acc[mi][ni][1] = 0.f;
            acc[mi][ni][2] = 0.f; acc[mi][ni][3] = 0.f;
        }

    load_stage(0, 0);
    load_stage(1, 1);

    for (int kc = 0; kc < NCH_L1; kc++) {
        if (kc + 2 < NCH_L1) {
            load_stage((kc + 2) % 3, kc + 2);
            asm volatile("cp.async.wait_group 2;" ::: "memory");
        } else if (kc + 1 < NCH_L1) {
            asm volatile("cp.async.wait_group 1;" ::: "memory");
        } else {
            asm volatile("cp.async.wait_group 0;" ::: "memory");
        }
        __syncthreads();
        const __half* hA = (const __half*)(smc + (kc % 3) * STG_BYTES);
        const float* cB = (const float*)(smc + (kc % 3) * STG_BYTES + A_BYTES);
#pragma unroll
        for (int ks = 0; ks < 4; ks++) {
            int kb = ks * 8;
            uint32_t a[2][4];
#pragma unroll
            for (int mi = 0; mi < 2; mi++) {
                int bm = wm + mi * 16;
                a[mi][0] = __float_as_uint(__half2float(hA[(bm + g) * A_PADH + kb + t]));
                a[mi][1] = __float_as_uint(__half2float(hA[(bm + g + 8) * A_PADH + kb + t]));
                a[mi][2] = __float_as_uint(__half2float(hA[(bm + g) * A_PADH + kb + t + 4]));
                a[mi][3] = __float_as_uint(__half2float(hA[(bm + g + 8) * A_PADH + kb + t + 4]));
            }
#pragma unroll
            for (int ni = 0; ni < 8; ni++) {
                int bn = wn + ni * 8;
                uint32_t b0 = __float_as_uint(cB[(kb + t) * 132 + bn + g]);
                uint32_t b1 = __float_as_uint(cB[(kb + t + 4) * 132 + bn + g]);
                mma_tf32(acc[0][ni], a[0], b0, b1);
                mma_tf32(acc[1][ni], a[1], b0, b1);
            }
        }
        __syncthreads();
    }

    // epilogue: +bias1 + masked beW1, write hpre, BN1 stats
    float s1v[16], s2v[16];
#pragma unroll
    for (int i = 0; i < 16; i++) { s1v[i] = 0.f; s2v[i] = 0.f; }

#pragma unroll
    for (int mi = 0; mi < 2; mi++) {
#pragma unroll
        for (int hf = 0; hf < 2; hf++) {
            int mg = m0 + wm + mi * 16 + g + hf * 8;
            if (mg >= NN) continue;
            unsigned mask8 = 0;
#pragma unroll
            for (int r = 0; r < RR; r++)
                if (g_cnt[r * NN + mg] > 0) mask8 |= 1u << r;
#pragma unroll
            for (int ni = 0; ni < 8; ni++) {
                int c = wn + ni * 8 + 2 * t;
                float v0 = acc[mi][ni][hf * 2 + 0] + sBias[c];
                float v1 = acc[mi][ni][hf * 2 + 1] + sBias[c + 1];
#pragma unroll
                for (int r = 0; r < RR; r++) {
                    if ((mask8 >> r) & 1u) {
                        v0 += sBe[r * DD + c];
                        v1 += sBe[r * DD + c + 1];
                    }
                }
                *(float2*)&g_hpre[(size_t)mg * DD + c] = make_float2(v0, v1);
                s1v[ni * 2 + 0] += v0; s1v[ni * 2 + 1] += v1;
                s2v[ni * 2 + 0] += v0 * v0; s2v[ni * 2 + 1] += v1 * v1;
            }
        }
    }
    // reduce across g (lanes xor 4,8,16), then t-lanes atomic to global doubles
#pragma unroll
    for (int i = 0; i < 16; i++) {
#pragma unroll
        for (int d = 4; d <= 16; d <<= 1) {
            s1v[i] += __shfl_xor_sync(0xffffffffu, s1v[i], d);
            s2v[i] += __shfl_xor_sync(0xffffffffu, s2v[i], d);
        }
    }
    if (g == 0) {
#pragma unroll
        for (int ni = 0; ni < 8; ni++) {
            int c = wn + ni * 8 + 2 * t;
            atomicAdd(&g_s1a[c], (double)s1v[ni * 2 + 0]);
            atomicAdd(&g_s1a[c + 1], (double)s1v[ni * 2 + 1]);
            atomicAdd(&g_s2a[c], (double)s2v[ni * 2 + 0]);
            atomicAdd(&g_s2a[c + 1], (double)s2v[ni * 2 + 1]);
        }
    }
}

// ---------------- mma1: A = relu(bn1(hpre)) fused; BN1 finalize inline ----
#define A1_FLOATS (128*36)
#define B1_FLOATS (32*132)
#define STG1_FLOATS (A1_FLOATS + B1_FLOATS)
#define MMA1_SMEM (3 * STG1_FLOATS * 4)

__global__ void __launch_bounds__(256, 2) mma1_k(
    const float* __restrict__ B0, const float* __restrict__ B1,
    const float* __restrict__ l1g, const float* __restrict__ l1b)
{
    extern __shared__ float smf[];
    __shared__ float sSc[DD], sSh[DD];
    int tid = threadIdx.x;
    int m0 = blockIdx.x * 128;
    int rsel = blockIdx.y;

    const float* B = rsel ? B1 : B0;
    float* dst = rsel ? g_hs : g_hW2;
    const float* bias = rsel ? g_bias2 : nullptr;

    if (tid < DD) {
        double m = g_s1a[tid] / (double)NN;
        double var = g_s2a[tid] / (double)NN - m * m;
        float sc = __ldg(&l1g[tid]) * rsqrtf((float)var + 1e-5f);
        sSc[tid] = sc;
        sSh[tid] = __ldg(&l1b[tid]) - (float)m * sc;
    }

    uint32_t sb = smem_u32(smf);

    auto load_stage = [&](int s, int kc) {
        int k0 = kc * 32;
        float4 z = make_float4(0.f, 0.f, 0.f, 0.f);
#pragma unroll
        for (int j = 0; j < 4; j++) {
            int p = tid + j * 256;
            int row = p >> 3;
            int kq = (p & 7) << 2;
            int idx = s * STG1_FLOATS + row * 36 + kq;
            int m = m0 + row;
            if (m < NN) cpa16(sb + idx * 4, g_hpre + (size_t)m * DD + k0 + kq);
            else *(float4*)&smf[idx] = z;
        }
#pragma unroll
        for (int j = 0; j < 4; j++) {
            int p = tid + j * 256;
            int k = p >> 5;
            int n4 = (p & 31) << 2;
            int idx = s * STG1_FLOATS + A1_FLOATS + k * 132 + n4;
            cpa16(sb + idx * 4, B + (size_t)(k0 + k) * DD + n4);
        }
        asm volatile("cp.async.commit_group;" ::: "memory");
    };

    int wid = tid >> 5, lane = tid & 31;
    int g = lane >> 2, t = lane & 3;
    int wm = (wid & 3) * 32, wn = (wid >> 2) * 64;

    float acc[2][8][4];
#pragma unroll
    for (int mi = 0; mi < 2; mi++)
#pragma unroll
        for (int ni = 0; ni < 8; ni++) {
            acc[mi][ni][0] = 0.f; acc[mi][ni][1] = 0.f;
            acc[mi][ni][2] = 0.f; acc[mi][ni][3] = 0.f;
        }

    load_stage(0, 0);
    load_stage(1, 1);

    for (int kc = 0; kc < 4; kc++) {
        if (kc + 2 < 4) {
            load_stage((kc + 2) % 3, kc + 2);
            asm volatile("cp.async.wait_group 2;" ::: "memory");
        } else if (kc + 1 < 4) {
            asm volatile("cp.async.wait_group 1;" ::: "memory");
        } else {
            asm volatile("cp.async.wait_group 0;" ::: "memory");
        }
        __syncthreads();
        const float* cA = smf + (kc % 3) * STG1_FLOATS;
        const float* cB = cA + A1_FLOATS;
        int k0 = kc * 32;
#pragma unroll
        for (int ks = 0; ks < 4; ks++) {
            int kb = ks * 8;
            float sc0 = sSc[k0 + kb + t],     sh0 = sSh[k0 + kb + t];
            float sc4 = sSc[k0 + kb + t + 4], sh4 = sSh[k0 + kb + t + 4];
            uint32_t a[2][4];
#pragma unroll
            for (int mi = 0; mi < 2; mi++) {
                int bm = wm + mi * 16;
                a[mi][0] = __float_as_uint(fmaxf(0.f, cA[(bm + g) * 36 + kb + t] * sc0 + sh0));
                a[mi][1] = __float_as_uint(fmaxf(0.f, cA[(bm + g + 8) * 36 + kb + t] * sc0 + sh0));
                a[mi][2] = __float_as_uint(fmaxf(0.f, cA[(bm + g) * 36 + kb + t + 4] * sc4 + sh4));
                a[mi][3] = __float_as_uint(fmaxf(0.f, cA[(bm + g + 8) * 36 + kb + t + 4] * sc4 + sh4));
            }
#pragma unroll
            for (int ni = 0; ni < 8; ni++) {
                int bn = wn + ni * 8;
                uint32_t b0 = __float_as_uint(cB[(kb + t) * 132 + bn + g]);
                uint32_t b1 = __float_as_uint(cB[(kb + t + 4) * 132 + bn + g]);
                mma_tf32(acc[0][ni], a[0], b0, b1);
                mma_tf32(acc[1][ni], a[1], b0, b1);
            }
        }
        __syncthreads();
    }

#pragma unroll
    for (int mi = 0; mi < 2; mi++) {
#pragma unroll
        for (int ni = 0; ni < 8; ni++) {
            int mg = m0 + wm + mi * 16 + g;
            int c = wn + ni * 8 + 2 * t;
            float2 v0 = make_float2(acc[mi][ni][0], acc[mi][ni][1]);
            float2 v1 = make_float2(acc[mi][ni][2], acc[mi][ni][3]);
            if (bias) {
                float b0 = bias[c], b1 = bias[c + 1];
                v0.x += b0; v0.y += b1; v1.x += b0; v1.y += b1;
            }
            if (mg < NN) *(float2*)&dst[(size_t)mg * DD + c] = v0;
            if (mg + 8 < NN) *(float2*)&dst[(size_t)(mg + 8) * DD + c] = v1;
        }
    }
}

// ---------------- agg2: warp-per-node layer-2 assembly + BN2 stats --------
#define AGG2_BLOCKS 1184
__global__ __launch_bounds__(256) void agg2_k(float* __restrict__ out) {
    __shared__ __align__(16) float sW2[EDD * DD];
    __shared__ __align__(16) float sBe2[DD];
    __shared__ float sRed[2][DD];
    int tid = threadIdx.x;
    int wid = tid >> 5;
    int lane = tid & 31;
    int c4 = lane << 2;
    for (int i = tid; i < EDD * DD; i += 256) sW2[i] = g_WeWlin2[i];
    if (tid < DD) { sBe2[tid] = g_beWlin2[tid]; sRed[0][tid] = 0.f; sRed[1][tid] = 0.f; }
    __syncthreads();

    float s1[4] = {0.f, 0.f, 0.f, 0.f};
    float s2[4] = {0.f, 0.f, 0.f, 0.f};

    for (int no = blockIdx.x * 8 + wid; no < NN; no += AGG2_BLOCKS * 8) {
        float4 hsv = __ldg((const float4*)&g_hs[(size_t)no * DD + c4]);
#pragma unroll
        for (int r = 0; r < RR; r++) {
            int tr = r * NN + no;
            float4 acc = hsv;
            int off = g_off[tr];
            int cnt = g_cnt[tr];
            if (cnt > 0) {
                float4 be = *(float4*)&sBe2[c4];
                acc.x += be.x; acc.y += be.y; acc.z += be.z; acc.w += be.w;
            }
            for (int j = 0; j < cnt; j++) {
                int4 cs = __ldg(&g_csr4[off + j]);
                float w = __int_as_float(cs.z);
                float4 hv = __ldg((const float4*)&g_hW2[(size_t)cs.x * DD + c4]);
                acc.x += w * hv.x; acc.y += w * hv.y;
                acc.z += w * hv.z; acc.w += w * hv.w;
            }

            float aef = __half2float(g_aggef[(size_t)tr * EDD + lane]);
            u64 a01 = pack2(acc.x, acc.y), a23 = pack2(acc.z, acc.w);
#pragma unroll
            for (int i = 0; i < EDD; i++) {
                float a = __shfl_sync(0xffffffffu, aef, i);
                u64 ad = dup2(a);
                const u64* wp = (const u64*)&sW2[i * DD + c4];
                fma2(a01, ad, wp[0]);
                fma2(a23, ad, wp[1]);
            }
            unpack2(a01, acc.x, acc.y);
            unpack2(a23, acc.z, acc.w);

            *(float4*)&out[(size_t)tr * DD + c4] = acc;
            s1[0] += acc.x; s1[1] += acc.y; s1[2] += acc.z; s1[3] += acc.w;
            s2[0] += acc.x * acc.x; s2[1] += acc.y * acc.y;
            s2[2] += acc.z * acc.z; s2[3] += acc.w * acc.w;
        }
    }

#pragma unroll
    for (int i = 0; i < 4; i++) {
        atomicAdd(&sRed[0][c4 + i], s1[i]);
        atomicAdd(&sRed[1][c4 + i], s2[i]);
    }
    __syncthreads();
    if (tid < DD) {
        atomicAdd(&g_s1b[tid], (double)sRed[0][tid]);
        atomicAdd(&g_s2b[tid], (double)sRed[1][tid]);
    }
}

// ---------------- bnrelu_o: BN2 finalize inline + apply -------------------
__global__ __launch_bounds__(256) void bnrelu_o_k(float* __restrict__ out,
                                                  const float* __restrict__ l2g,
                                                  const float* __restrict__ l2b) {
    __shared__ float sSc[DD], sSh[DD];
    if (threadIdx.x < DD) {
        int d = threadIdx.x;
        double m = g_s1b[d] / (double)M2;
        double var = g_s2b[d] / (double)M2 - m * m;
        float sc = __ldg(&l2g[d]) * rsqrtf((float)var + 1e-5f);
        sSc[d] = sc;
        sSh[d] = __ldg(&l2b[d]) - (float)m * sc;
    }
    __syncthreads();
    int i = blockIdx.x * 256 + threadIdx.x;
    if (i >= M2 * 32) return;
    int c = (i & 31) << 2;
    float4 v = ((const float4*)out)[i];
    v.x = fmaxf(0.f, v.x * sSc[c + 0] + sSh[c + 0]);
    v.y = fmaxf(0.f, v.y * sSc[c + 1] + sSh[c + 1]);
    v.z = fmaxf(0.f, v.z * sSc[c + 2] + sSh[c + 2]);
    v.w = fmaxf(0.f, v.w * sSc[c + 3] + sSh[c + 3]);
    ((float4*)out)[i] = v;
}

// ---------------- launch ----------------
extern "C" void kernel_launch(void* const* d_in, const int* in_sizes, int n_in,
                              void* d_out, int out_size) {
    (void)in_sizes; (void)n_in; (void)out_size;
    const float* x        = (const float*)d_in[0];
    const int*   node_in  = (const int*)d_in[1];
    const int*   node_out = (const int*)d_in[2];
    const int*   relation = (const int*)d_in[3];
    const float* ew       = (const float*)d_in[4];
    const float* ef       = (const float*)d_in[5];
    const float* l1_Wlin  = (const float*)d_in[6];
    const float* l1_blin  = (const float*)d_in[7];
    const float* l1_Wself = (const float*)d_in[8];
    const float* l1_bself = (const float*)d_in[9];
    const float* l1_Wedge = (const float*)d_in[10];
    const float* l1_bedge = (const float*)d_in[11];
    const float* l1_g     = (const float*)d_in[12];
    const float* l1_b     = (const float*)d_in[13];
    const float* l2_Wlin  = (const float*)d_in[14];
    const float* l2_blin  = (const float*)d_in[15];
    const float* l2_Wself = (const float*)d_in[16];
    const float* l2_bself = (const float*)d_in[17];
    const float* l2_Wedge = (const float*)d_in[18];
    const float* l2_bedge = (const float*)d_in[19];
    const float* l2_g     = (const float*)d_in[20];
    const float* l2_b     = (const float*)d_in[21];
    float* out = (float*)d_out;

    int gmm = (NN + 127) / 128;   // 391
    int nsb = (NR + SCAN_BLK - 1) / SCAN_BLK;  // 391

    static int configured = 0;
    if (!configured) {
        cudaFuncSetAttribute(mma_L1_k, cudaFuncAttributeMaxDynamicSharedMemorySize,
                             MMAL1_SMEM);
        cudaFuncSetAttribute(mma1_k, cudaFuncAttributeMaxDynamicSharedMemorySize,
                             MMA1_SMEM);
        configured = 1;
    }

    init_k<<<512, 256>>>(x);
    prep_k<<<RR + 1, 128>>>(l1_Wedge, l1_Wlin, l1_bedge, l1_blin, l1_bself,
                            l2_Wedge, l2_Wlin, l2_bedge, l2_blin, l2_bself);
    deg_k<<<EE / 256, 256>>>(node_out, relation, ew);
    scan1_k<<<nsb, 1024>>>();
    scan2_k<<<1, 512>>>();
    scan3_k<<<nsb, 1024>>>();
    place_k<<<EE / 256, 256>>>(node_in, node_out, relation, ew);
    agg1x_k<<<NR / 8, 256>>>(x, ef);
    mma_L1_k<<<gmm, 256, MMAL1_SMEM>>>(l1_Wlin, l1_Wself);
    mma1_k<<<dim3(gmm, 2), 256, MMA1_SMEM>>>(l2_Wlin, l2_Wself, l1_g, l1_b);
    agg2_k<<<AGG2_BLOCKS, 256>>>(out);
    bnrelu_o_k<<<(M2 * 32) / 256, 256>>>(out, l2_g, l2_b);
}

// round 12
// speedup vs baseline: 1.0446x; 1.0446x over previous
#include <cuda_runtime.h>
#include <cuda_fp16.h>
#include <cstdint>

#define NN 50000
#define DD 128
#define RR 8
#define EE 800000
#define EDD 32
#define NR (NN*RR)
#define M2 (RR*NN)

typedef unsigned long long u64;

// ---------------- scratch ----------------
__device__ float  g_deg[NR];
__device__ __half g_aggef[NR*EDD];           // [r][no][32]
__device__ __half g_aggx[(size_t)NR*DD];     // [r][no][128]
__device__ __half g_xh[(size_t)NN*DD];
__device__ float  g_hpre[NN*DD];
__device__ float  g_hW2[NN*DD];
__device__ float  g_hs[NN*DD];
__device__ float  g_WeWlin1[RR*EDD*DD];
__device__ float  g_WeWlin2[EDD*DD];
__device__ float  g_beWlin1[RR*DD];
__device__ float  g_beWlin2[DD];
__device__ float  g_bias1[DD];
__device__ float  g_bias2[DD];
__device__ double g_s1a[DD], g_s2a[DD], g_s1b[DD], g_s2b[DD];
// CSR by tr
__device__ int   g_cnt[NR];
__device__ int   g_off[NR];
__device__ int   g_cur[NR];
__device__ int   g_bsum[512];
__device__ int4  g_csr4[EE];                 // {nin, eid, ew_bits, 0}

// ---------------- helpers ----------------
__device__ __forceinline__ uint32_t smem_u32(const void* p) {
    uint32_t a;
    asm("{ .reg .u64 t; cvta.to.shared.u64 t, %1; cvt.u32.u64 %0, t; }" : "=r"(a) : "l"(p));
    return a;
}
__device__ __forceinline__ u64 pack2(float lo, float hi) {
    u64 r; asm("mov.b64 %0, {%1, %2};" : "=l"(r) : "f"(lo), "f"(hi)); return r;
}
__device__ __forceinline__ u64 dup2(float v) {
    u64 r; asm("mov.b64 %0, {%1, %1};" : "=l"(r) : "f"(v)); return r;
}
__device__ __forceinline__ void unpack2(u64 v, float& lo, float& hi) {
    asm("mov.b64 {%0, %1}, %2;" : "=f"(lo), "=f"(hi) : "l"(v));
}
__device__ __forceinline__ void fma2(u64& d, u64 a, u64 b) {
    asm("fma.rn.f32x2 %0, %1, %2, %0;" : "+l"(d) : "l"(a), "l"(b));
}
__device__ __forceinline__ void mma_tf32(float* d, const uint32_t* a,
                                         uint32_t b0, uint32_t b1) {
    asm volatile(
        "mma.sync.aligned.m16n8k8.row.col.f32.tf32.tf32.f32 "
        "{%0,%1,%2,%3}, {%4,%5,%6,%7}, {%8,%9}, {%0,%1,%2,%3};"
        : "+f"(d[0]), "+f"(d[1]), "+f"(d[2]), "+f"(d[3])
        : "r"(a[0]), "r"(a[1]), "r"(a[2]), "r"(a[3]), "r"(b0), "r"(b1));
}
__device__ __forceinline__ void cpa16(uint32_t d, const void* s) {
    asm volatile("cp.async.ca.shared.global [%0], [%1], 16;" :: "r"(d), "l"(s) : "memory");
}

// ---------------- init: zero small buffers + x->half ----------------
__global__ __launch_bounds__(256) void init_k(const float* __restrict__ x) {
    size_t i = (size_t)blockIdx.x * blockDim.x + threadIdx.x;
    size_t stride = (size_t)gridDim.x * blockDim.x;
    float4 z = make_float4(0.f, 0.f, 0.f, 0.f);
    float4* d = (float4*)g_deg;
    for (size_t j = i; j < (size_t)NR / 4; j += stride) d[j] = z;
    int4* c = (int4*)g_cnt;
    int4 zi = make_int4(0, 0, 0, 0);
    for (size_t j = i; j < (size_t)NR / 4; j += stride) c[j] = zi;
    for (size_t j = i; j < (size_t)NN * 32; j += stride) {
        float4 v = ((const float4*)x)[j];
        __half2* dst = (__half2*)g_xh + j * 2;
        dst[0] = __floats2half2_rn(v.x, v.y);
        dst[1] = __floats2half2_rn(v.z, v.w);
    }
    if (i < DD) { g_s1a[i] = 0.0; g_s2a[i] = 0.0; g_s1b[i] = 0.0; g_s2b[i] = 0.0; }
}

// ---------------- prep: folds ----------------
__global__ __launch_bounds__(128) void prep_k(
    const float* __restrict__ l1_We, const float* __restrict__ l1_Wlin,
    const float* __restrict__ l1_be, const float* __restrict__ l1_blin,
    const float* __restrict__ l1_bself,
    const float* __restrict__ l2_We, const float* __restrict__ l2_Wlin,
    const float* __restrict__ l2_be, const float* __restrict__ l2_blin,
    const float* __restrict__ l2_bself)
{
    __shared__ float sWe[EDD * DD];
    __shared__ float sbe[DD];
    int r = blockIdx.x;
    int d = threadIdx.x;
    const float* We = (r < RR) ? l1_We : l2_We;
    const float* Wl = (r < RR) ? l1_Wlin : l2_Wlin;
    const float* be = (r < RR) ? l1_be : l2_be;
    for (int i = d; i < EDD * DD; i += 128) sWe[i] = We[i];
    sbe[d] = be[d];
    __syncthreads();
    float acc[EDD];
#pragma unroll
    for (int i = 0; i < EDD; i++) acc[i] = 0.f;
    float accb = 0.f;
    int rowoff = (r < RR) ? r * DD : 0;
    for (int k = 0; k < DD; k++) {
        float wl = Wl[(size_t)(rowoff + k) * DD + d];
        accb += sbe[k] * wl;
#pragma unroll
        for (int i = 0; i < EDD; i++) acc[i] += sWe[i * DD + k] * wl;
    }
    if (r < RR) {
#pragma unroll
        for (int i = 0; i < EDD; i++) g_WeWlin1[(size_t)(r * EDD + i) * DD + d] = acc[i];
        g_beWlin1[r * DD + d] = accb;
    } else {
#pragma unroll
        for (int i = 0; i < EDD; i++) g_WeWlin2[(size_t)i * DD + d] = acc[i];
        g_beWlin2[d] = accb;
        g_bias1[d] = l1_blin[d] + l1_bself[d];
        g_bias2[d] = l2_blin[d] + l2_bself[d];
    }
}

// ---------------- degree + histogram (by tr) ----------------
__global__ void deg_k(const int* __restrict__ nout, const int* __restrict__ rel,
                      const float* __restrict__ w) {
    int e = blockIdx.x * blockDim.x + threadIdx.x;
    if (e < EE) {
        int tr = rel[e] * NN + nout[e];
        atomicAdd(&g_deg[tr], w[e]);
        atomicAdd(&g_cnt[tr], 1);
    }
}

// ---------------- scan (exclusive prefix over g_cnt) ----------------
#define SCAN_BLK 1024
__global__ __launch_bounds__(1024) void scan1_k() {
    __shared__ int sh[SCAN_BLK];
    int t = threadIdx.x;
    int i = blockIdx.x * SCAN_BLK + t;
    sh[t] = (i < NR) ? g_cnt[i] : 0;
    __syncthreads();
    for (int s = 512; s > 0; s >>= 1) {
        if (t < s) sh[t] += sh[t + s];
        __syncthreads();
    }
    if (t == 0) g_bsum[blockIdx.x] = sh[0];
}
__global__ __launch_bounds__(512) void scan2_k() {
    __shared__ int sh[512];
    int t = threadIdx.x;
    int nb = (NR + SCAN_BLK - 1) / SCAN_BLK;
    int orig = (t < nb) ? g_bsum[t] : 0;
    sh[t] = orig;
    __syncthreads();
    for (int d = 1; d < 512; d <<= 1) {
        int x = (t >= d) ? sh[t - d] : 0;
        __syncthreads();
        sh[t] += x;
        __syncthreads();
    }
    if (t < nb) g_bsum[t] = sh[t] - orig;
}
__global__ __launch_bounds__(1024) void scan3_k() {
    __shared__ int sh[SCAN_BLK];
    int t = threadIdx.x;
    int i = blockIdx.x * SCAN_BLK + t;
    int orig = (i < NR) ? g_cnt[i] : 0;
    sh[t] = orig;
    __syncthreads();
    for (int d = 1; d < SCAN_BLK; d <<= 1) {
        int x = (t >= d) ? sh[t - d] : 0;
        __syncthreads();
        sh[t] += x;
        __syncthreads();
    }
    if (i < NR) {
        int excl = sh[t] - orig + g_bsum[blockIdx.x];
        g_off[i] = excl;
        g_cur[i] = excl;
    }
}
__global__ void place_k(const int* __restrict__ nin, const int* __restrict__ nout,
                        const int* __restrict__ rel, const float* __restrict__ w) {
    int e = blockIdx.x * blockDim.x + threadIdx.x;
    if (e < EE) {
        int tr = rel[e] * NN + nout[e];
        int pos = atomicAdd(&g_cur[tr], 1);
        g_csr4[pos] = make_int4(nin[e], e, __float_as_int(w[e] / g_deg[tr]), 0);
    }
}

// ---------------- agg1x: warp-per-tr CSR gather (x L2-resident) -----------
__global__ __launch_bounds__(256) void agg1x_k(const float* __restrict__ x,
                                               const float* __restrict__ ef) {
    int tid = threadIdx.x;
    int wid = tid >> 5;
    int lane = tid & 31;
    int c4 = lane << 2;
    int tr = blockIdx.x * 8 + wid;
    if (tr >= NR) return;

    int off = g_off[tr];
    int cnt = g_cnt[tr];
    float4 xa = make_float4(0.f, 0.f, 0.f, 0.f);
    float4 xb = make_float4(0.f, 0.f, 0.f, 0.f);
    float ea = 0.f, eb = 0.f;
    int j = 0;
    for (; j + 2 <= cnt; j += 2) {
        int4 c0 = __ldg(&g_csr4[off + j]);
        int4 c1 = __ldg(&g_csr4[off + j + 1]);
        float w0 = __int_as_float(c0.z), w1 = __int_as_float(c1.z);
        float4 x0 = __ldg((const float4*)&x[(size_t)c0.x * DD + c4]);
        float4 x1 = __ldg((const float4*)&x[(size_t)c1.x * DD + c4]);
        float f0 = __ldg(&ef[(size_t)c0.y * EDD + lane]);
        float f1 = __ldg(&ef[(size_t)c1.y * EDD + lane]);
        xa.x += w0 * x0.x; xa.y += w0 * x0.y; xa.z += w0 * x0.z; xa.w += w0 * x0.w;
        xb.x += w1 * x1.x; xb.y += w1 * x1.y; xb.z += w1 * x1.z; xb.w += w1 * x1.w;
        ea += w0 * f0; eb += w1 * f1;
    }
    if (j < cnt) {
        int4 c0 = __ldg(&g_csr4[off + j]);
        float w0 = __int_as_float(c0.z);
        float4 x0 = __ldg((const float4*)&x[(size_t)c0.x * DD + c4]);
        xa.x += w0 * x0.x; xa.y += w0 * x0.y; xa.z += w0 * x0.z; xa.w += w0 * x0.w;
        ea += w0 * __ldg(&ef[(size_t)c0.y * EDD + lane]);
    }
    xa.x += xb.x; xa.y += xb.y; xa.z += xb.z; xa.w += xb.w;
    __half2* dst = (__half2*)&g_aggx[(size_t)tr * DD + c4];
    dst[0] = __floats2half2_rn(xa.x, xa.y);
    dst[1] = __floats2half2_rn(xa.z, xa.w);
    g_aggef[(size_t)tr * EDD + lane] = __float2half_rn(ea + eb);
}

// ---------------- mma_L1: hpre = [aggx|aggef|x]@[Wlin1;WeWlin1;Wself1] ----
// K = 1408 (44 chunks); minimal store-only epilogue (register-neutral).
#define A_PADH 40
#define A_BYTES (128 * A_PADH * 2)
#define B_BYTES (32 * 132 * 4)
#define STG_BYTES (A_BYTES + B_BYTES)
#define MMAL1_SMEM (3 * STG_BYTES)
#define NCH_L1 44

__global__ void __launch_bounds__(256, 2) mma_L1_k(
    const float* __restrict__ Wlin1, const float* __restrict__ Wself1)
{
    extern __shared__ char smc[];
    int tid = threadIdx.x;
    int m0 = blockIdx.x * 128;
    uint32_t sb = smem_u32(smc);

    auto load_stage = [&](int s, int kc) {
        const __half* Asrc;
        const float* Bsrc;
        int astride;
        if (kc < 32) {
            int r = kc >> 2;
            Asrc = g_aggx + (size_t)r * NN * DD + (kc & 3) * 32;
            astride = DD;
            Bsrc = Wlin1 + (size_t)kc * 32 * DD;
        } else if (kc < 40) {
            int r = kc - 32;
            Asrc = g_aggef + (size_t)r * NN * EDD;
            astride = EDD;
            Bsrc = g_WeWlin1 + (size_t)r * EDD * DD;
        } else {
            Asrc = g_xh + (kc - 40) * 32;
            astride = DD;
            Bsrc = Wself1 + (size_t)(kc - 40) * 32 * DD;
        }
#pragma unroll
        for (int j = 0; j < 2; j++) {
            int p = tid + j * 256;
            int row = p >> 2;
            int kq = (p & 3) * 8;
            uint32_t doff = sb + s * STG_BYTES + row * (A_PADH * 2) + kq * 2;
            int m = m0 + row;
            if (m < NN) cpa16(doff, Asrc + (size_t)m * astride + kq);
            else {
                float4 z = make_float4(0.f, 0.f, 0.f, 0.f);
                *(float4*)(smc + s * STG_BYTES + row * (A_PADH * 2) + kq * 2) = z;
            }
        }
#pragma unroll
        for (int j = 0; j < 4; j++) {
            int p = tid + j * 256;
            int k = p >> 5;
            int n4 = (p & 31) << 2;
            uint32_t doff = sb + s * STG_BYTES + A_BYTES + (k * 132 + n4) * 4;
            cpa16(doff, Bsrc + (size_t)k * DD + n4);
        }
        asm volatile("cp.async.commit_group;" ::: "memory");
    };

    int wid = tid >> 5, lane = tid & 31;
    int g = lane >> 2, t = lane & 3;
    int wm = (wid & 3) * 32, wn = (wid >> 2) * 64;

    float acc[2][8][4];
#pragma unroll
    for (int mi = 0; mi < 2; mi++)
#pragma unroll
        for (int ni = 0; ni < 8; ni++) {
            acc[mi][ni][0] = 0.f; acc[mi][ni][1] = 0.f;
            acc[mi][ni][2] = 0.f; acc[mi][ni][3] = 0.f;
        }

    load_stage(0, 0);
    load_stage(1, 1);

    for (int kc = 0; kc < NCH_L1; kc++) {
        if (kc + 2 < NCH_L1) {
            load_stage((kc + 2) % 3, kc + 2);
            asm volatile("cp.async.wait_group 2;" ::: "memory");
        } else if (kc + 1 < NCH_L1) {
            asm volatile("cp.async.wait_group 1;" ::: "memory");
        } else {
            asm volatile("cp.async.wait_group 0;" ::: "memory");
        }
        __syncthreads();
        const __half* hA = (const __half*)(smc + (kc % 3) * STG_BYTES);
        const float* cB = (const float*)(smc + (kc % 3) * STG_BYTES + A_BYTES);
#pragma unroll
        for (int ks = 0; ks < 4; ks++) {
            int kb = ks * 8;
            uint32_t a[2][4];
#pragma unroll
            for (int mi = 0; mi < 2; mi++) {
                int bm = wm + mi * 16;
                a[mi][0] = __float_as_uint(__half2float(hA[(bm + g) * A_PADH + kb + t]));
                a[mi][1] = __float_as_uint(__half2float(hA[(bm + g + 8) * A_PADH + kb + t]));
                a[mi][2] = __float_as_uint(__half2float(hA[(bm + g) * A_PADH + kb + t + 4]));
                a[mi][3] = __float_as_uint(__half2float(hA[(bm + g + 8) * A_PADH + kb + t + 4]));
            }
#pragma unroll
            for (int ni = 0; ni < 8; ni++) {
                int bn = wn + ni * 8;
                uint32_t b0 = __float_as_uint(cB[(kb + t) * 132 + bn + g]);
                uint32_t b1 = __float_as_uint(cB[(kb + t + 4) * 132 + bn + g]);
                mma_tf32(acc[0][ni], a[0], b0, b1);
                mma_tf32(acc[1][ni], a[1], b0, b1);
            }
        }
        __syncthreads();
    }

#pragma unroll
    for (int mi = 0; mi < 2; mi++) {
#pragma unroll
        for (int ni = 0; ni < 8; ni++) {
            int mg = m0 + wm + mi * 16 + g;
            int c = wn + ni * 8 + 2 * t;
            if (mg < NN)
                *(float2*)&g_hpre[(size_t)mg * DD + c] =
                    make_float2(acc[mi][ni][0], acc[mi][ni][1]);
            if (mg + 8 < NN)
                *(float2*)&g_hpre[(size_t)(mg + 8) * DD + c] =
                    make_float2(acc[mi][ni][2], acc[mi][ni][3]);
        }
    }
}

// ---------------- epi1: hpre += bias1 + mask*beW1 ; BN1 stats -------------
#define EPI1_BLOCKS 1184
__global__ __launch_bounds__(256) void epi1_k() {
    __shared__ __align__(16) float sBe[RR * DD];
    __shared__ float sBias[DD];
    __shared__ float sRed[2][DD];
    int tid = threadIdx.x;
    int wid = tid >> 5;
    int lane = tid & 31;
    int c4 = lane << 2;
    for (int i = tid; i < RR * DD; i += 256) sBe[i] = g_beWlin1[i];
    if (tid < DD) { sBias[tid] = g_bias1[tid]; sRed[0][tid] = 0.f; sRed[1][tid] = 0.f; }
    __syncthreads();

    float s1[4] = {0.f, 0.f, 0.f, 0.f};
    float s2[4] = {0.f, 0.f, 0.f, 0.f};

    for (int m = blockIdx.x * 8 + wid; m < NN; m += EPI1_BLOCKS * 8) {
        int cbit = (lane < RR) ? (g_cnt[lane * NN + m] > 0) : 0;
        unsigned mask8 = __ballot_sync(0xffffffffu, cbit) & 0xFFu;

        float4 v = *(float4*)&g_hpre[(size_t)m * DD + c4];
        v.x += sBias[c4 + 0]; v.y += sBias[c4 + 1];
        v.z += sBias[c4 + 2]; v.w += sBias[c4 + 3];
#pragma unroll
        for (int r = 0; r < RR; r++) {
            if ((mask8 >> r) & 1u) {
                float4 be = *(float4*)&sBe[r * DD + c4];
                v.x += be.x; v.y += be.y; v.z += be.z; v.w += be.w;
            }
        }
        *(float4*)&g_hpre[(size_t)m * DD + c4] = v;
        s1[0] += v.x; s1[1] += v.y; s1[2] += v.z; s1[3] += v.w;
        s2[0] += v.x * v.x; s2[1] += v.y * v.y;
        s2[2] += v.z * v.z; s2[3] += v.w * v.w;
    }

#pragma unroll
    for (int i = 0; i < 4; i++) {
        atomicAdd(&sRed[0][c4 + i], s1[i]);
        atomicAdd(&sRed[1][c4 + i], s2[i]);
    }
    __syncthreads();
    if (tid < DD) {
        atomicAdd(&g_s1a[tid], (double)sRed[0][tid]);
        atomicAdd(&g_s2a[tid], (double)sRed[1][tid]);
    }
}

// ---------------- mma1: A = relu(bn1(hpre)) fused; BN1 finalize inline ----
#define A1_FLOATS (128*36)
#define B1_FLOATS (32*132)
#define STG1_FLOATS (A1_FLOATS + B1_FLOATS)
#define MMA1_SMEM (3 * STG1_FLOATS * 4)

__global__ void __launch_bounds__(256, 2) mma1_k(
    const float* __restrict__ B0, const float* __restrict__ B1,
    const float* __restrict__ l1g, const float* __restrict__ l1b)
{
    extern __shared__ float smf[];
    __shared__ float sSc[DD], sSh[DD];
    int tid = threadIdx.x;
    int m0 = blockIdx.x * 128;
    int rsel = blockIdx.y;

    const float* B = rsel ? B1 : B0;
    float* dst = rsel ? g_hs : g_hW2;
    const float* bias = rsel ? g_bias2 : nullptr;

    if (tid < DD) {
        double m = g_s1a[tid] / (double)NN;
        double var = g_s2a[tid] / (double)NN - m * m;
        float sc = __ldg(&l1g[tid]) * rsqrtf((float)var + 1e-5f);
        sSc[tid] = sc;
        sSh[tid] = __ldg(&l1b[tid]) - (float)m * sc;
    }

    uint32_t sb = smem_u32(smf);

    auto load_stage = [&](int s, int kc) {
        int k0 = kc * 32;
        float4 z = make_float4(0.f, 0.f, 0.f, 0.f);
#pragma unroll
        for (int j = 0; j < 4; j++) {
            int p = tid + j * 256;
            int row = p >> 3;
            int kq = (p & 7) << 2;
            int idx = s * STG1_FLOATS + row * 36 + kq;
            int m = m0 + row;
            if (m < NN) cpa16(sb + idx * 4, g_hpre + (size_t)m * DD + k0 + kq);
            else *(float4*)&smf[idx] = z;
        }
#pragma unroll
        for (int j = 0; j < 4; j++) {
            int p = tid + j * 256;
            int k = p >> 5;
            int n4 = (p & 31) << 2;
            int idx = s * STG1_FLOATS + A1_FLOATS + k * 132 + n4;
            cpa16(sb + idx * 4, B + (size_t)(k0 + k) * DD + n4);
        }
        asm volatile("cp.async.commit_group;" ::: "memory");
    };

    int wid = tid >> 5, lane = tid & 31;
    int g = lane >> 2, t = lane & 3;
    int wm = (wid & 3) * 32, wn = (wid >> 2) * 64;

    float acc[2][8][4];
#pragma unroll
    for (int mi = 0; mi < 2; mi++)
#pragma unroll
        for (int ni = 0; ni < 8; ni++) {
            acc[mi][ni][0] = 0.f; acc[mi][ni][1] = 0.f;
            acc[mi][ni][2] = 0.f; acc[mi][ni][3] = 0.f;
        }

    load_stage(0, 0);
    load_stage(1, 1);

    for (int kc = 0; kc < 4; kc++) {
        if (kc + 2 < 4) {
            load_stage((kc + 2) % 3, kc + 2);
            asm volatile("cp.async.wait_group 2;" ::: "memory");
        } else if (kc + 1 < 4) {
            asm volatile("cp.async.wait_group 1;" ::: "memory");
        } else {
            asm volatile("cp.async.wait_group 0;" ::: "memory");
        }
        __syncthreads();
        const float* cA = smf + (kc % 3) * STG1_FLOATS;
        const float* cB = cA + A1_FLOATS;
        int k0 = kc * 32;
#pragma unroll
        for (int ks = 0; ks < 4; ks++) {
            int kb = ks * 8;
            float sc0 = sSc[k0 + kb + t],     sh0 = sSh[k0 + kb + t];
            float sc4 = sSc[k0 + kb + t + 4], sh4 = sSh[k0 + kb + t + 4];
            uint32_t a[2][4];
#pragma unroll
            for (int mi = 0; mi < 2; mi++) {
                int bm = wm + mi * 16;
                a[mi][0] = __float_as_uint(fmaxf(0.f, cA[(bm + g) * 36 + kb + t] * sc0 + sh0));
                a[mi][1] = __float_as_uint(fmaxf(0.f, cA[(bm + g + 8) * 36 + kb + t] * sc0 + sh0));
                a[mi][2] = __float_as_uint(fmaxf(0.f, cA[(bm + g) * 36 + kb + t + 4] * sc4 + sh4));
                a[mi][3] = __float_as_uint(fmaxf(0.f, cA[(bm + g + 8) * 36 + kb + t + 4] * sc4 + sh4));
            }
#pragma unroll
            for (int ni = 0; ni < 8; ni++) {
                int bn = wn + ni * 8;
                uint32_t b0 = __float_as_uint(cB[(kb + t) * 132 + bn + g]);
                uint32_t b1 = __float_as_uint(cB[(kb + t + 4) * 132 + bn + g]);
                mma_tf32(acc[0][ni], a[0], b0, b1);
                mma_tf32(acc[1][ni], a[1], b0, b1);
            }
        }
        __syncthreads();
    }

#pragma unroll
    for (int mi = 0; mi < 2; mi++) {
#pragma unroll
        for (int ni = 0; ni < 8; ni++) {
            int mg = m0 + wm + mi * 16 + g;
            int c = wn + ni * 8 + 2 * t;
            float2 v0 = make_float2(acc[mi][ni][0], acc[mi][ni][1]);
            float2 v1 = make_float2(acc[mi][ni][2], acc[mi][ni][3]);
            if (bias) {
                float b0 = bias[c], b1 = bias[c + 1];
                v0.x += b0; v0.y += b1; v1.x += b0; v1.y += b1;
            }
            if (mg < NN) *(float2*)&dst[(size_t)mg * DD + c] = v0;
            if (mg + 8 < NN) *(float2*)&dst[(size_t)(mg + 8) * DD + c] = v1;
        }
    }
}

// ---------------- agg2: warp-per-node layer-2 assembly + BN2 stats --------
#define AGG2_BLOCKS 1184
__global__ __launch_bounds__(256) void agg2_k(float* __restrict__ out) {
    __shared__ __align__(16) float sW2[EDD * DD];
    __shared__ __align__(16) float sBe2[DD];
    __shared__ float sRed[2][DD];
    int tid = threadIdx.x;
    int wid = tid >> 5;
    int lane = tid & 31;
    int c4 = lane << 2;
    for (int i = tid; i < EDD * DD; i += 256) sW2[i] = g_WeWlin2[i];
    if (tid < DD) { sBe2[tid] = g_beWlin2[tid]; sRed[0][tid] = 0.f; sRed[1][tid] = 0.f; }
    __syncthreads();

    float s1[4] = {0.f, 0.f, 0.f, 0.f};
    float s2[4] = {0.f, 0.f, 0.f, 0.f};

    for (int no = blockIdx.x * 8 + wid; no < NN; no += AGG2_BLOCKS * 8) {
        float4 hsv = __ldg((const float4*)&g_hs[(size_t)no * DD + c4]);
#pragma unroll
        for (int r = 0; r < RR; r++) {
            int tr = r * NN + no;
            float4 acc = hsv;
            int off = g_off[tr];
            int cnt = g_cnt[tr];
            if (cnt > 0) {
                float4 be = *(float4*)&sBe2[c4];
                acc.x += be.x; acc.y += be.y; acc.z += be.z; acc.w += be.w;
            }
            for (int j = 0; j < cnt; j++) {
                int4 cs = __ldg(&g_csr4[off + j]);
                float w = __int_as_float(cs.z);
                float4 hv = __ldg((const float4*)&g_hW2[(size_t)cs.x * DD + c4]);
                acc.x += w * hv.x; acc.y += w * hv.y;
                acc.z += w * hv.z; acc.w += w * hv.w;
            }

            float aef = __half2float(g_aggef[(size_t)tr * EDD + lane]);
            u64 a01 = pack2(acc.x, acc.y), a23 = pack2(acc.z, acc.w);
#pragma unroll
            for (int i = 0; i < EDD; i++) {
                float a = __shfl_sync(0xffffffffu, aef, i);
                u64 ad = dup2(a);
                const u64* wp = (const u64*)&sW2[i * DD + c4];
                fma2(a01, ad, wp[0]);
                fma2(a23, ad, wp[1]);
            }
            unpack2(a01, acc.x, acc.y);
            unpack2(a23, acc.z, acc.w);

            *(float4*)&out[(size_t)tr * DD + c4] = acc;
            s1[0] += acc.x; s1[1] += acc.y; s1[2] += acc.z; s1[3] += acc.w;
            s2[0] += acc.x * acc.x; s2[1] += acc.y * acc.y;
            s2[2] += acc.z * acc.z; s2[3] += acc.w * acc.w;
        }
    }

#pragma unroll
    for (int i = 0; i < 4; i++) {
        atomicAdd(&sRed[0][c4 + i], s1[i]);
        atomicAdd(&sRed[1][c4 + i], s2[i]);
    }
    __syncthreads();
    if (tid < DD) {
        atomicAdd(&g_s1b[tid], (double)sRed[0][tid]);
        atomicAdd(&g_s2b[tid], (double)sRed[1][tid]);
    }
}

// ---------------- bnrelu_o: BN2 finalize inline + apply -------------------
__global__ __launch_bounds__(256) void bnrelu_o_k(float* __restrict__ out,
                                                  const float* __restrict__ l2g,
                                                  const float* __restrict__ l2b) {
    __shared__ float sSc[DD], sSh[DD];
    if (threadIdx.x < DD) {
        int d = threadIdx.x;
        double m = g_s1b[d] / (double)M2;
        double var = g_s2b[d] / (double)M2 - m * m;
        float sc = __ldg(&l2g[d]) * rsqrtf((float)var + 1e-5f);
        sSc[d] = sc;
        sSh[d] = __ldg(&l2b[d]) - (float)m * sc;
    }
    __syncthreads();
    int i = blockIdx.x * 256 + threadIdx.x;
    if (i >= M2 * 32) return;
    int c = (i & 31) << 2;
    float4 v = ((const float4*)out)[i];
    v.x = fmaxf(0.f, v.x * sSc[c + 0] + sSh[c + 0]);
    v.y = fmaxf(0.f, v.y * sSc[c + 1] + sSh[c + 1]);
    v.z = fmaxf(0.f, v.z * sSc[c + 2] + sSh[c + 2]);
    v.w = fmaxf(0.f, v.w * sSc[c + 3] + sSh[c + 3]);
    ((float4*)out)[i] = v;
}

// ---------------- launch ----------------
extern "C" void kernel_launch(void* const* d_in, const int* in_sizes, int n_in,
                              void* d_out, int out_size) {
    (void)in_sizes; (void)n_in; (void)out_size;
    const float* x        = (const float*)d_in[0];
    const int*   node_in  = (const int*)d_in[1];
    const int*   node_out = (const int*)d_in[2];
    const int*   relation = (const int*)d_in[3];
    const float* ew       = (const float*)d_in[4];
    const float* ef       = (const float*)d_in[5];
    const float* l1_Wlin  = (const float*)d_in[6];
    const float* l1_blin  = (const float*)d_in[7];
    const float* l1_Wself = (const float*)d_in[8];
    const float* l1_bself = (const float*)d_in[9];
    const float* l1_Wedge = (const float*)d_in[10];
    const float* l1_bedge = (const float*)d_in[11];
    const float* l1_g     = (const float*)d_in[12];
    const float* l1_b     = (const float*)d_in[13];
    const float* l2_Wlin  = (const float*)d_in[14];
    const float* l2_blin  = (const float*)d_in[15];
    const float* l2_Wself = (const float*)d_in[16];
    const float* l2_bself = (const float*)d_in[17];
    const float* l2_Wedge = (const float*)d_in[18];
    const float* l2_bedge = (const float*)d_in[19];
    const float* l2_g     = (const float*)d_in[20];
    const float* l2_b     = (const float*)d_in[21];
    float* out = (float*)d_out;

    int gmm = (NN + 127) / 128;   // 391
    int nsb = (NR + SCAN_BLK - 1) / SCAN_BLK;  // 391

    static int configured = 0;
    if (!configured) {
        cudaFuncSetAttribute(mma_L1_k, cudaFuncAttributeMaxDynamicSharedMemorySize,
                             MMAL1_SMEM);
        cudaFuncSetAttribute(mma1_k, cudaFuncAttributeMaxDynamicSharedMemorySize,
                             MMA1_SMEM);
        configured = 1;
    }

    init_k<<<512, 256>>>(x);
    prep_k<<<RR + 1, 128>>>(l1_Wedge, l1_Wlin, l1_bedge, l1_blin, l1_bself,
                            l2_Wedge, l2_Wlin, l2_bedge, l2_blin, l2_bself);
    deg_k<<<EE / 256, 256>>>(node_out, relation, ew);
    scan1_k<<<nsb, 1024>>>();
    scan2_k<<<1, 512>>>();
    scan3_k<<<nsb, 1024>>>();
    place_k<<<EE / 256, 256>>>(node_in, node_out, relation, ew);
    agg1x_k<<<NR / 8, 256>>>(x, ef);
    mma_L1_k<<<gmm, 256, MMAL1_SMEM>>>(l1_Wlin, l1_Wself);
    epi1_k<<<EPI1_BLOCKS, 256>>>();
    mma1_k<<<dim3(gmm, 2), 256, MMA1_SMEM>>>(l2_Wlin, l2_Wself, l1_g, l1_b);
    agg2_k<<<AGG2_BLOCKS, 256>>>(out);
    bnrelu_o_k<<<(M2 * 32) / 256, 256>>>(out, l2_g, l2_b);
}

// round 13
// speedup vs baseline: 1.2663x; 1.2123x over previous
#include <cuda_runtime.h>
#include <cuda_fp16.h>
#include <cstdint>

#define NN 50000
#define DD 128
#define RR 8
#define EE 800000
#define EDD 32
#define NR (NN*RR)
#define M2 (RR*NN)

typedef unsigned long long u64;

// ---------------- scratch ----------------
__device__ float  g_deg[NR];                 // indexed by tr = r*NN + no
__device__ __half g_aggef[NR*EDD];           // [r][no][32]
__device__ __half g_aggx[(size_t)NR*DD];     // [r][no][128]
__device__ __half g_xh[(size_t)NN*DD];       // x in half
__device__ float  g_hpre[NN*DD];
__device__ float  g_hW2[NN*DD];
__device__ float  g_hs[NN*DD];
__device__ float  g_WeWlin1[RR*EDD*DD];
__device__ float  g_WeWlin2[EDD*DD];
__device__ float  g_beWlin1[RR*DD];
__device__ float  g_beWlin2[DD];
__device__ float  g_bias1[DD];
__device__ float  g_bias2[DD];
__device__ double g_s1a[DD], g_s2a[DD], g_s1b[DD], g_s2b[DD];
__device__ float  g_sc1[DD], g_sh1[DD], g_sc2[DD], g_sh2[DD];
// CSR by tr
__device__ int   g_cnt[NR];
__device__ int   g_off[NR];
__device__ int   g_cur[NR];
__device__ int   g_bsum[512];
__device__ int   g_csr_nin[EE];
__device__ int   g_csr_eid[EE];
__device__ float g_csr_ew[EE];

// ---------------- helpers ----------------
__device__ __forceinline__ uint32_t smem_u32(const void* p) {
    uint32_t a;
    asm("{ .reg .u64 t; cvta.to.shared.u64 t, %1; cvt.u32.u64 %0, t; }" : "=r"(a) : "l"(p));
    return a;
}
__device__ __forceinline__ u64 pack2(float lo, float hi) {
    u64 r; asm("mov.b64 %0, {%1, %2};" : "=l"(r) : "f"(lo), "f"(hi)); return r;
}
__device__ __forceinline__ u64 dup2(float v) {
    u64 r; asm("mov.b64 %0, {%1, %1};" : "=l"(r) : "f"(v)); return r;
}
__device__ __forceinline__ void unpack2(u64 v, float& lo, float& hi) {
    asm("mov.b64 {%0, %1}, %2;" : "=f"(lo), "=f"(hi) : "l"(v));
}
__device__ __forceinline__ void fma2(u64& d, u64 a, u64 b) {
    asm("fma.rn.f32x2 %0, %1, %2, %0;" : "+l"(d) : "l"(a), "l"(b));
}
__device__ __forceinline__ void mma_tf32(float* d, const uint32_t* a,
                                         uint32_t b0, uint32_t b1) {
    asm volatile(
        "mma.sync.aligned.m16n8k8.row.col.f32.tf32.tf32.f32 "
        "{%0,%1,%2,%3}, {%4,%5,%6,%7}, {%8,%9}, {%0,%1,%2,%3};"
        : "+f"(d[0]), "+f"(d[1]), "+f"(d[2]), "+f"(d[3])
        : "r"(a[0]), "r"(a[1]), "r"(a[2]), "r"(a[3]), "r"(b0), "r"(b1));
}
__device__ __forceinline__ void cpa16(uint32_t d, const void* s) {
    asm volatile("cp.async.ca.shared.global [%0], [%1], 16;" :: "r"(d), "l"(s) : "memory");
}

// ---------------- zero (small buffers only) ----------------
__global__ void zero_k() {
    size_t i = (size_t)blockIdx.x * blockDim.x + threadIdx.x;
    size_t stride = (size_t)gridDim.x * blockDim.x;
    float4 z = make_float4(0.f, 0.f, 0.f, 0.f);
    float4* d = (float4*)g_deg;
    for (size_t j = i; j < (size_t)NR / 4; j += stride) d[j] = z;
    int4* c = (int4*)g_cnt;
    int4 zi = make_int4(0, 0, 0, 0);
    for (size_t j = i; j < (size_t)NR / 4; j += stride) c[j] = zi;
    if (i < DD) { g_s1a[i] = 0.0; g_s2a[i] = 0.0; g_s1b[i] = 0.0; g_s2b[i] = 0.0; }
}

// ---------------- x -> half ----------------
__global__ __launch_bounds__(256) void xhalf_k(const float* __restrict__ x) {
    int i = blockIdx.x * 256 + threadIdx.x;
    if (i >= NN * 32) return;
    float4 v = ((const float4*)x)[i];
    __half2* dst = (__half2*)g_xh + (size_t)i * 2;
    dst[0] = __floats2half2_rn(v.x, v.y);
    dst[1] = __floats2half2_rn(v.z, v.w);
}

// ---------------- prep: folds ----------------
__global__ __launch_bounds__(128) void prep_k(
    const float* __restrict__ l1_We, const float* __restrict__ l1_Wlin,
    const float* __restrict__ l1_be, const float* __restrict__ l1_blin,
    const float* __restrict__ l1_bself,
    const float* __restrict__ l2_We, const float* __restrict__ l2_Wlin,
    const float* __restrict__ l2_be, const float* __restrict__ l2_blin,
    const float* __restrict__ l2_bself)
{
    __shared__ float sWe[EDD * DD];
    __shared__ float sbe[DD];
    int r = blockIdx.x;
    int d = threadIdx.x;
    const float* We = (r < RR) ? l1_We : l2_We;
    const float* Wl = (r < RR) ? l1_Wlin : l2_Wlin;
    const float* be = (r < RR) ? l1_be : l2_be;
    for (int i = d; i < EDD * DD; i += 128) sWe[i] = We[i];
    sbe[d] = be[d];
    __syncthreads();
    float acc[EDD];
#pragma unroll
    for (int i = 0; i < EDD; i++) acc[i] = 0.f;
    float accb = 0.f;
    int rowoff = (r < RR) ? r * DD : 0;
    for (int k = 0; k < DD; k++) {
        float wl = Wl[(size_t)(rowoff + k) * DD + d];
        accb += sbe[k] * wl;
#pragma unroll
        for (int i = 0; i < EDD; i++) acc[i] += sWe[i * DD + k] * wl;
    }
    if (r < RR) {
#pragma unroll
        for (int i = 0; i < EDD; i++) g_WeWlin1[(size_t)(r * EDD + i) * DD + d] = acc[i];
        g_beWlin1[r * DD + d] = accb;
    } else {
#pragma unroll
        for (int i = 0; i < EDD; i++) g_WeWlin2[(size_t)i * DD + d] = acc[i];
        g_beWlin2[d] = accb;
        g_bias1[d] = l1_blin[d] + l1_bself[d];
        g_bias2[d] = l2_blin[d] + l2_bself[d];
    }
}

// ---------------- degree + histogram (by tr) ----------------
__global__ void deg_k(const int* __restrict__ nout, const int* __restrict__ rel,
                      const float* __restrict__ w) {
    int e = blockIdx.x * blockDim.x + threadIdx.x;
    if (e < EE) {
        int tr = rel[e] * NN + nout[e];
        atomicAdd(&g_deg[tr], w[e]);
        atomicAdd(&g_cnt[tr], 1);
    }
}

// ---------------- scan (exclusive prefix over g_cnt) ----------------
#define SCAN_BLK 1024
__global__ __launch_bounds__(1024) void scan1_k() {
    __shared__ int sh[SCAN_BLK];
    int t = threadIdx.x;
    int i = blockIdx.x * SCAN_BLK + t;
    sh[t] = (i < NR) ? g_cnt[i] : 0;
    __syncthreads();
    for (int s = 512; s > 0; s >>= 1) {
        if (t < s) sh[t] += sh[t + s];
        __syncthreads();
    }
    if (t == 0) g_bsum[blockIdx.x] = sh[0];
}
__global__ __launch_bounds__(512) void scan2_k() {
    __shared__ int sh[512];
    int t = threadIdx.x;
    int nb = (NR + SCAN_BLK - 1) / SCAN_BLK;
    int orig = (t < nb) ? g_bsum[t] : 0;
    sh[t] = orig;
    __syncthreads();
    for (int d = 1; d < 512; d <<= 1) {
        int x = (t >= d) ? sh[t - d] : 0;
        __syncthreads();
        sh[t] += x;
        __syncthreads();
    }
    if (t < nb) g_bsum[t] = sh[t] - orig;
}
__global__ __launch_bounds__(1024) void scan3_k() {
    __shared__ int sh[SCAN_BLK];
    int t = threadIdx.x;
    int i = blockIdx.x * SCAN_BLK + t;
    int orig = (i < NR) ? g_cnt[i] : 0;
    sh[t] = orig;
    __syncthreads();
    for (int d = 1; d < SCAN_BLK; d <<= 1) {
        int x = (t >= d) ? sh[t - d] : 0;
        __syncthreads();
        sh[t] += x;
        __syncthreads();
    }
    if (i < NR) {
        int excl = sh[t] - orig + g_bsum[blockIdx.x];
        g_off[i] = excl;
        g_cur[i] = excl;
    }
}
__global__ void place_k(const int* __restrict__ nin, const int* __restrict__ nout,
                        const int* __restrict__ rel, const float* __restrict__ w) {
    int e = blockIdx.x * blockDim.x + threadIdx.x;
    if (e < EE) {
        int tr = rel[e] * NN + nout[e];
        int pos = atomicAdd(&g_cur[tr], 1);
        g_csr_nin[pos] = nin[e];
        g_csr_eid[pos] = e;
        g_csr_ew[pos] = w[e] / g_deg[tr];
    }
}

// ---------------- agg1x: warp-per-tr CSR gather (x L2-resident) -----------
__global__ __launch_bounds__(256) void agg1x_k(const float* __restrict__ x,
                                               const float* __restrict__ ef) {
    int tid = threadIdx.x;
    int wid = tid >> 5;
    int lane = tid & 31;
    int c4 = lane << 2;
    int tr = blockIdx.x * 8 + wid;
    if (tr >= NR) return;

    int off = g_off[tr];
    int cnt = g_cnt[tr];
    float4 xacc = make_float4(0.f, 0.f, 0.f, 0.f);
    float eacc = 0.f;
    for (int j = 0; j < cnt; j++) {
        int nin  = __ldg(&g_csr_nin[off + j]);
        int eid  = __ldg(&g_csr_eid[off + j]);
        float w  = __ldg(&g_csr_ew[off + j]);
        float4 xv = __ldg((const float4*)&x[(size_t)nin * DD + c4]);
        xacc.x += w * xv.x; xacc.y += w * xv.y;
        xacc.z += w * xv.z; xacc.w += w * xv.w;
        eacc += w * __ldg(&ef[(size_t)eid * EDD + lane]);
    }
    __half2* dst = (__half2*)&g_aggx[(size_t)tr * DD + c4];
    dst[0] = __floats2half2_rn(xacc.x, xacc.y);
    dst[1] = __floats2half2_rn(xacc.z, xacc.w);
    g_aggef[(size_t)tr * EDD + lane] = __float2half_rn(eacc);
}

// ---------------- mma_L1: hpre = [aggx|aggef|x]@[Wlin1;WeWlin1;Wself1] ----
// K = 1408 (44 chunks); A stored half in smem; store-only epilogue.
#define A_PADH 40
#define A_BYTES (128 * A_PADH * 2)
#define B_BYTES (32 * 132 * 4)
#define STG_BYTES (A_BYTES + B_BYTES)
#define MMAL1_SMEM (3 * STG_BYTES)
#define NCH_L1 44

__global__ void __launch_bounds__(256, 2) mma_L1_k(
    const float* __restrict__ Wlin1, const float* __restrict__ Wself1)
{
    extern __shared__ char smc[];
    int tid = threadIdx.x;
    int m0 = blockIdx.x * 128;
    uint32_t sb = smem_u32(smc);

    auto load_stage = [&](int s, int kc) {
        const __half* Asrc;
        const float* Bsrc;
        int astride;
        if (kc < 32) {
            int r = kc >> 2;
            Asrc = g_aggx + (size_t)r * NN * DD + (kc & 3) * 32;
            astride = DD;
            Bsrc = Wlin1 + (size_t)kc * 32 * DD;
        } else if (kc < 40) {
            int r = kc - 32;
            Asrc = g_aggef + (size_t)r * NN * EDD;
            astride = EDD;
            Bsrc = g_WeWlin1 + (size_t)r * EDD * DD;
        } else {
            Asrc = g_xh + (kc - 40) * 32;
            astride = DD;
            Bsrc = Wself1 + (size_t)(kc - 40) * 32 * DD;
        }
#pragma unroll
        for (int j = 0; j < 2; j++) {
            int p = tid + j * 256;
            int row = p >> 2;
            int kq = (p & 3) * 8;
            uint32_t doff = sb + s * STG_BYTES + row * (A_PADH * 2) + kq * 2;
            int m = m0 + row;
            if (m < NN) cpa16(doff, Asrc + (size_t)m * astride + kq);
            else {
                float4 z = make_float4(0.f, 0.f, 0.f, 0.f);
                *(float4*)(smc + s * STG_BYTES + row * (A_PADH * 2) + kq * 2) = z;
            }
        }
#pragma unroll
        for (int j = 0; j < 4; j++) {
            int p = tid + j * 256;
            int k = p >> 5;
            int n4 = (p & 31) << 2;
            uint32_t doff = sb + s * STG_BYTES + A_BYTES + (k * 132 + n4) * 4;
            cpa16(doff, Bsrc + (size_t)k * DD + n4);
        }
        asm volatile("cp.async.commit_group;" ::: "memory");
    };

    int wid = tid >> 5, lane = tid & 31;
    int g = lane >> 2, t = lane & 3;
    int wm = (wid & 3) * 32, wn = (wid >> 2) * 64;

    float acc[2][8][4];
#pragma unroll
    for (int mi = 0; mi < 2; mi++)
#pragma unroll
        for (int ni = 0; ni < 8; ni++) {
            acc[mi][ni][0] = 0.f; acc[mi][ni][1] = 0.f;
            acc[mi][ni][2] = 0.f; acc[mi][ni][3] = 0.f;
        }

    load_stage(0, 0);
    load_stage(1, 1);

    for (int kc = 0; kc < NCH_L1; kc++) {
        if (kc + 2 < NCH_L1) {
            load_stage((kc + 2) % 3, kc + 2);
            asm volatile("cp.async.wait_group 2;" ::: "memory");
        } else if (kc + 1 < NCH_L1) {
            asm volatile("cp.async.wait_group 1;" ::: "memory");
        } else {
            asm volatile("cp.async.wait_group 0;" ::: "memory");
        }
        __syncthreads();
        const __half* hA = (const __half*)(smc + (kc % 3) * STG_BYTES);
        const float* cB = (const float*)(smc + (kc % 3) * STG_BYTES + A_BYTES);
#pragma unroll
        for (int ks = 0; ks < 4; ks++) {
            int kb = ks * 8;
            uint32_t a[2][4];
#pragma unroll
            for (int mi = 0; mi < 2; mi++) {
                int bm = wm + mi * 16;
                a[mi][0] = __float_as_uint(__half2float(hA[(bm + g) * A_PADH + kb + t]));
                a[mi][1] = __float_as_uint(__half2float(hA[(bm + g + 8) * A_PADH + kb + t]));
                a[mi][2] = __float_as_uint(__half2float(hA[(bm + g) * A_PADH + kb + t + 4]));
                a[mi][3] = __float_as_uint(__half2float(hA[(bm + g + 8) * A_PADH + kb + t + 4]));
            }
#pragma unroll
            for (int ni = 0; ni < 8; ni++) {
                int bn = wn + ni * 8;
                uint32_t b0 = __float_as_uint(cB[(kb + t) * 132 + bn + g]);
                uint32_t b1 = __float_as_uint(cB[(kb + t + 4) * 132 + bn + g]);
                mma_tf32(acc[0][ni], a[0], b0, b1);
                mma_tf32(acc[1][ni], a[1], b0, b1);
            }
        }
        __syncthreads();
    }

#pragma unroll
    for (int mi = 0; mi < 2; mi++) {
#pragma unroll
        for (int ni = 0; ni < 8; ni++) {
            int mg = m0 + wm + mi * 16 + g;
            int c = wn + ni * 8 + 2 * t;
            if (mg < NN)
                *(float2*)&g_hpre[(size_t)mg * DD + c] =
                    make_float2(acc[mi][ni][0], acc[mi][ni][1]);
            if (mg + 8 < NN)
                *(float2*)&g_hpre[(size_t)(mg + 8) * DD + c] =
                    make_float2(acc[mi][ni][2], acc[mi][ni][3]);
        }
    }
}

// ---------------- epi1: hpre += bias1 + mask*beW1 ; BN1 stats -------------
#define EPI1_BLOCKS 1184
__global__ __launch_bounds__(256) void epi1_k() {
    __shared__ __align__(16) float sBe[RR * DD];
    __shared__ float sBias[DD];
    __shared__ float sRed[2][DD];
    int tid = threadIdx.x;
    int wid = tid >> 5;
    int lane = tid & 31;
    int c4 = lane << 2;
    for (int i = tid; i < RR * DD; i += 256) sBe[i] = g_beWlin1[i];
    if (tid < DD) { sBias[tid] = g_bias1[tid]; sRed[0][tid] = 0.f; sRed[1][tid] = 0.f; }
    __syncthreads();

    float s1[4] = {0.f, 0.f, 0.f, 0.f};
    float s2[4] = {0.f, 0.f, 0.f, 0.f};

    for (int m = blockIdx.x * 8 + wid; m < NN; m += EPI1_BLOCKS * 8) {
        int cbit = (lane < RR) ? (g_cnt[lane * NN + m] > 0) : 0;
        unsigned mask8 = __ballot_sync(0xffffffffu, cbit) & 0xFFu;

        float4 v = *(float4*)&g_hpre[(size_t)m * DD + c4];
        v.x += sBias[c4 + 0]; v.y += sBias[c4 + 1];
        v.z += sBias[c4 + 2]; v.w += sBias[c4 + 3];
#pragma unroll
        for (int r = 0; r < RR; r++) {
            if ((mask8 >> r) & 1u) {
                float4 be = *(float4*)&sBe[r * DD + c4];
                v.x += be.x; v.y += be.y; v.z += be.z; v.w += be.w;
            }
        }
        *(float4*)&g_hpre[(size_t)m * DD + c4] = v;
        s1[0] += v.x; s1[1] += v.y; s1[2] += v.z; s1[3] += v.w;
        s2[0] += v.x * v.x; s2[1] += v.y * v.y;
        s2[2] += v.z * v.z; s2[3] += v.w * v.w;
    }

#pragma unroll
    for (int i = 0; i < 4; i++) {
        atomicAdd(&sRed[0][c4 + i], s1[i]);
        atomicAdd(&sRed[1][c4 + i], s2[i]);
    }
    __syncthreads();
    if (tid < DD) {
        atomicAdd(&g_s1a[tid], (double)sRed[0][tid]);
        atomicAdd(&g_s2a[tid], (double)sRed[1][tid]);
    }
}

// ---------------- BN finalize (float consts for consumers) ----------------
__global__ void bnfin_k(int sel, float nrows, const float* __restrict__ g,
                        const float* __restrict__ b) {
    int d = threadIdx.x;
    double s1 = sel ? g_s1b[d] : g_s1a[d];
    double s2 = sel ? g_s2b[d] : g_s2a[d];
    double m = s1 / (double)nrows;
    double var = s2 / (double)nrows - m * m;
    float sc = g[d] * rsqrtf((float)var + 1e-5f);
    float sh = b[d] - (float)m * sc;
    if (sel) { g_sc2[d] = sc; g_sh2[d] = sh; }
    else     { g_sc1[d] = sc; g_sh1[d] = sh; }
}

// ---------------- mma1: A = relu(bn1(hpre)) fused at fragment load --------
#define A1_FLOATS (128*36)
#define B1_FLOATS (32*132)
#define STG1_FLOATS (A1_FLOATS + B1_FLOATS)
#define MMA1_SMEM (3 * STG1_FLOATS * 4)

__global__ void __launch_bounds__(256, 2) mma1_k(
    const float* __restrict__ B0, const float* __restrict__ B1)
{
    extern __shared__ float smf[];
    __shared__ float sSc[DD], sSh[DD];
    int tid = threadIdx.x;
    int m0 = blockIdx.x * 128;
    int rsel = blockIdx.y;

    const float* B = rsel ? B1 : B0;
    float* dst = rsel ? g_hs : g_hW2;
    const float* bias = rsel ? g_bias2 : nullptr;

    if (tid < DD) { sSc[tid] = g_sc1[tid]; sSh[tid] = g_sh1[tid]; }

    uint32_t sb = smem_u32(smf);

    auto load_stage = [&](int s, int kc) {
        int k0 = kc * 32;
        float4 z = make_float4(0.f, 0.f, 0.f, 0.f);
#pragma unroll
        for (int j = 0; j < 4; j++) {
            int p = tid + j * 256;
            int row = p >> 3;
            int kq = (p & 7) << 2;
            int idx = s * STG1_FLOATS + row * 36 + kq;
            int m = m0 + row;
            if (m < NN) cpa16(sb + idx * 4, g_hpre + (size_t)m * DD + k0 + kq);
            else *(float4*)&smf[idx] = z;
        }
#pragma unroll
        for (int j = 0; j < 4; j++) {
            int p = tid + j * 256;
            int k = p >> 5;
            int n4 = (p & 31) << 2;
            int idx = s * STG1_FLOATS + A1_FLOATS + k * 132 + n4;
            cpa16(sb + idx * 4, B + (size_t)(k0 + k) * DD + n4);
        }
        asm volatile("cp.async.commit_group;" ::: "memory");
    };

    int wid = tid >> 5, lane = tid & 31;
    int g = lane >> 2, t = lane & 3;
    int wm = (wid & 3) * 32, wn = (wid >> 2) * 64;

    float acc[2][8][4];
#pragma unroll
    for (int mi = 0; mi < 2; mi++)
#pragma unroll
        for (int ni = 0; ni < 8; ni++) {
            acc[mi][ni][0] = 0.f; acc[mi][ni][1] = 0.f;
            acc[mi][ni][2] = 0.f; acc[mi][ni][3] = 0.f;
        }

    load_stage(0, 0);
    load_stage(1, 1);

    for (int kc = 0; kc < 4; kc++) {
        if (kc + 2 < 4) {
            load_stage((kc + 2) % 3, kc + 2);
            asm volatile("cp.async.wait_group 2;" ::: "memory");
        } else if (kc + 1 < 4) {
            asm volatile("cp.async.wait_group 1;" ::: "memory");
        } else {
            asm volatile("cp.async.wait_group 0;" ::: "memory");
        }
        __syncthreads();
        const float* cA = smf + (kc % 3) * STG1_FLOATS;
        const float* cB = cA + A1_FLOATS;
        int k0 = kc * 32;
#pragma unroll
        for (int ks = 0; ks < 4; ks++) {
            int kb = ks * 8;
            float sc0 = sSc[k0 + kb + t],     sh0 = sSh[k0 + kb + t];
            float sc4 = sSc[k0 + kb + t + 4], sh4 = sSh[k0 + kb + t + 4];
            uint32_t a[2][4];
#pragma unroll
            for (int mi = 0; mi < 2; mi++) {
                int bm = wm + mi * 16;
                a[mi][0] = __float_as_uint(fmaxf(0.f, cA[(bm + g) * 36 + kb + t] * sc0 + sh0));
                a[mi][1] = __float_as_uint(fmaxf(0.f, cA[(bm + g + 8) * 36 + kb + t] * sc0 + sh0));
                a[mi][2] = __float_as_uint(fmaxf(0.f, cA[(bm + g) * 36 + kb + t + 4] * sc4 + sh4));
                a[mi][3] = __float_as_uint(fmaxf(0.f, cA[(bm + g + 8) * 36 + kb + t + 4] * sc4 + sh4));
            }
#pragma unroll
            for (int ni = 0; ni < 8; ni++) {
                int bn = wn + ni * 8;
                uint32_t b0 = __float_as_uint(cB[(kb + t) * 132 + bn + g]);
                uint32_t b1 = __float_as_uint(cB[(kb + t + 4) * 132 + bn + g]);
                mma_tf32(acc[0][ni], a[0], b0, b1);
                mma_tf32(acc[1][ni], a[1], b0, b1);
            }
        }
        __syncthreads();
    }

#pragma unroll
    for (int mi = 0; mi < 2; mi++) {
#pragma unroll
        for (int ni = 0; ni < 8; ni++) {
            int mg = m0 + wm + mi * 16 + g;
            int c = wn + ni * 8 + 2 * t;
            float2 v0 = make_float2(acc[mi][ni][0], acc[mi][ni][1]);
            float2 v1 = make_float2(acc[mi][ni][2], acc[mi][ni][3]);
            if (bias) {
                float b0 = bias[c], b1 = bias[c + 1];
                v0.x += b0; v0.y += b1; v1.x += b0; v1.y += b1;
            }
            if (mg < NN) *(float2*)&dst[(size_t)mg * DD + c] = v0;
            if (mg + 8 < NN) *(float2*)&dst[(size_t)(mg + 8) * DD + c] = v1;
        }
    }
}

// ---------------- agg2: warp-per-node layer-2 assembly + BN2 stats --------
// fast path: cnt==0 -> out[tr] = hs[no] exactly (beW2 masked, ef-term == 0)
#define AGG2_BLOCKS 1184
__global__ __launch_bounds__(256) void agg2_k(float* __restrict__ out) {
    __shared__ __align__(16) float sW2[EDD * DD];
    __shared__ __align__(16) float sBe2[DD];
    __shared__ float sRed[2][DD];
    int tid = threadIdx.x;
    int wid = tid >> 5;
    int lane = tid & 31;
    int c4 = lane << 2;
    for (int i = tid; i < EDD * DD; i += 256) sW2[i] = g_WeWlin2[i];
    if (tid < DD) { sBe2[tid] = g_beWlin2[tid]; sRed[0][tid] = 0.f; sRed[1][tid] = 0.f; }
    __syncthreads();

    float s1[4] = {0.f, 0.f, 0.f, 0.f};
    float s2[4] = {0.f, 0.f, 0.f, 0.f};

    for (int no = blockIdx.x * 8 + wid; no < NN; no += AGG2_BLOCKS * 8) {
        float4 hsv = __ldg((const float4*)&g_hs[(size_t)no * DD + c4]);
#pragma unroll
        for (int r = 0; r < RR; r++) {
            int tr = r * NN + no;
            int cnt = g_cnt[tr];
            if (cnt == 0) {
                *(float4*)&out[(size_t)tr * DD + c4] = hsv;
                s1[0] += hsv.x; s1[1] += hsv.y; s1[2] += hsv.z; s1[3] += hsv.w;
                s2[0] += hsv.x * hsv.x; s2[1] += hsv.y * hsv.y;
                s2[2] += hsv.z * hsv.z; s2[3] += hsv.w * hsv.w;
                continue;
            }
            int off = g_off[tr];
            float4 acc = hsv;
            {
                float4 be = *(float4*)&sBe2[c4];
                acc.x += be.x; acc.y += be.y; acc.z += be.z; acc.w += be.w;
            }
            for (int j = 0; j < cnt; j++) {
                int nin = __ldg(&g_csr_nin[off + j]);
                float w = __ldg(&g_csr_ew[off + j]);
                float4 hv = __ldg((const float4*)&g_hW2[(size_t)nin * DD + c4]);
                acc.x += w * hv.x; acc.y += w * hv.y;
                acc.z += w * hv.z; acc.w += w * hv.w;
            }

            float aef = __half2float(g_aggef[(size_t)tr * EDD + lane]);
            u64 a01 = pack2(acc.x, acc.y), a23 = pack2(acc.z, acc.w);
#pragma unroll
            for (int i = 0; i < EDD; i++) {
                float a = __shfl_sync(0xffffffffu, aef, i);
                u64 ad = dup2(a);
                const u64* wp = (const u64*)&sW2[i * DD + c4];
                fma2(a01, ad, wp[0]);
                fma2(a23, ad, wp[1]);
            }
            unpack2(a01, acc.x, acc.y);
            unpack2(a23, acc.z, acc.w);

            *(float4*)&out[(size_t)tr * DD + c4] = acc;
            s1[0] += acc.x; s1[1] += acc.y; s1[2] += acc.z; s1[3] += acc.w;
            s2[0] += acc.x * acc.x; s2[1] += acc.y * acc.y;
            s2[2] += acc.z * acc.z; s2[3] += acc.w * acc.w;
        }
    }

#pragma unroll
    for (int i = 0; i < 4; i++) {
        atomicAdd(&sRed[0][c4 + i], s1[i]);
        atomicAdd(&sRed[1][c4 + i], s2[i]);
    }
    __syncthreads();
    if (tid < DD) {
        atomicAdd(&g_s1b[tid], (double)sRed[0][tid]);
        atomicAdd(&g_s2b[tid], (double)sRed[1][tid]);
    }
}

// ---------------- bnrelu_o: apply BN2 (float consts) ----------------------
__global__ __launch_bounds__(256) void bnrelu_o_k(float* __restrict__ out) {
    int i = blockIdx.x * 256 + threadIdx.x;
    if (i >= M2 * 32) return;
    int c = (i & 31) << 2;
    float4 v = ((const float4*)out)[i];
    v.x = fmaxf(0.f, v.x * g_sc2[c + 0] + g_sh2[c + 0]);
    v.y = fmaxf(0.f, v.y * g_sc2[c + 1] + g_sh2[c + 1]);
    v.z = fmaxf(0.f, v.z * g_sc2[c + 2] + g_sh2[c + 2]);
    v.w = fmaxf(0.f, v.w * g_sc2[c + 3] + g_sh2[c + 3]);
    ((float4*)out)[i] = v;
}

// ---------------- launch ----------------
extern "C" void kernel_launch(void* const* d_in, const int* in_sizes, int n_in,
                              void* d_out, int out_size) {
    (void)in_sizes; (void)n_in; (void)out_size;
    const float* x        = (const float*)d_in[0];
    const int*   node_in  = (const int*)d_in[1];
    const int*   node_out = (const int*)d_in[2];
    const int*   relation = (const int*)d_in[3];
    const float* ew       = (const float*)d_in[4];
    const float* ef       = (const float*)d_in[5];
    const float* l1_Wlin  = (const float*)d_in[6];
    const float* l1_blin  = (const float*)d_in[7];
    const float* l1_Wself = (const float*)d_in[8];
    const float* l1_bself = (const float*)d_in[9];
    const float* l1_Wedge = (const float*)d_in[10];
    const float* l1_bedge = (const float*)d_in[11];
    const float* l1_g     = (const float*)d_in[12];
    const float* l1_b     = (const float*)d_in[13];
    const float* l2_Wlin  = (const float*)d_in[14];
    const float* l2_blin  = (const float*)d_in[15];
    const float* l2_Wself = (const float*)d_in[16];
    const float* l2_bself = (const float*)d_in[17];
    const float* l2_Wedge = (const float*)d_in[18];
    const float* l2_bedge = (const float*)d_in[19];
    const float* l2_g     = (const float*)d_in[20];
    const float* l2_b     = (const float*)d_in[21];
    float* out = (float*)d_out;

    int gmm = (NN + 127) / 128;   // 391
    int nsb = (NR + SCAN_BLK - 1) / SCAN_BLK;  // 391

    static int configured = 0;
    if (!configured) {
        cudaFuncSetAttribute(mma_L1_k, cudaFuncAttributeMaxDynamicSharedMemorySize,
                             MMAL1_SMEM);
        cudaFuncSetAttribute(mma1_k, cudaFuncAttributeMaxDynamicSharedMemorySize,
                             MMA1_SMEM);
        configured = 1;
    }

    zero_k<<<512, 256>>>();
    xhalf_k<<<(NN * 32 + 255) / 256, 256>>>(x);
    prep_k<<<RR + 1, 128>>>(l1_Wedge, l1_Wlin, l1_bedge, l1_blin, l1_bself,
                            l2_Wedge, l2_Wlin, l2_bedge, l2_blin, l2_bself);
    deg_k<<<EE / 256, 256>>>(node_out, relation, ew);
    scan1_k<<<nsb, 1024>>>();
    scan2_k<<<1, 512>>>();
    scan3_k<<<nsb, 1024>>>();
    place_k<<<EE / 256, 256>>>(node_in, node_out, relation, ew);
    agg1x_k<<<NR / 8, 256>>>(x, ef);
    mma_L1_k<<<gmm, 256, MMAL1_SMEM>>>(l1_Wlin, l1_Wself);
    epi1_k<<<EPI1_BLOCKS, 256>>>();
    bnfin_k<<<1, 128>>>(0, (float)NN, l1_g, l1_b);
    mma1_k<<<dim3(gmm, 2), 256, MMA1_SMEM>>>(l2_Wlin, l2_Wself);
    agg2_k<<<AGG2_BLOCKS, 256>>>(out);
    bnfin_k<<<1, 128>>>(1, (float)M2, l2_g, l2_b);
    bnrelu_o_k<<<(M2 * 32) / 256, 256>>>(out);
}

// round 14
// speedup vs baseline: 1.3591x; 1.0732x over previous
#include <cuda_runtime.h>
#include <cuda_fp16.h>
#include <cstdint>

#define NN 50000
#define DD 128
#define RR 8
#define EE 800000
#define EDD 32
#define NR (NN*RR)
#define M2 (RR*NN)
#define K1 1408

typedef unsigned long long u64;

// ---------------- scratch ----------------
__device__ float  g_deg[NR];                 // indexed by tr = r*NN + no
__device__ __half g_aggef[NR*EDD];           // [r][no][32]
__device__ __half g_aggx[(size_t)NR*DD];     // [r][no][128]
__device__ __half g_xh[(size_t)NN*DD];       // x in half
__device__ __half g_B1t[(size_t)DD*K1];      // [n][k] transposed fused B1, half
__device__ float  g_hpre[NN*DD];
__device__ float  g_hW2[NN*DD];
__device__ float  g_hs[NN*DD];
__device__ float  g_WeWlin1[RR*EDD*DD];
__device__ float  g_WeWlin2[EDD*DD];
__device__ float  g_beWlin1[RR*DD];
__device__ float  g_beWlin2[DD];
__device__ float  g_bias1[DD];
__device__ float  g_bias2[DD];
__device__ double g_s1a[DD], g_s2a[DD], g_s1b[DD], g_s2b[DD];
__device__ float  g_sc1[DD], g_sh1[DD], g_sc2[DD], g_sh2[DD];
// CSR by tr
__device__ int   g_cnt[NR];
__device__ int   g_off[NR];
__device__ int   g_cur[NR];
__device__ int   g_bsum[512];
__device__ int   g_csr_nin[EE];
__device__ int   g_csr_eid[EE];
__device__ float g_csr_ew[EE];

// ---------------- helpers ----------------
__device__ __forceinline__ uint32_t smem_u32(const void* p) {
    uint32_t a;
    asm("{ .reg .u64 t; cvta.to.shared.u64 t, %1; cvt.u32.u64 %0, t; }" : "=r"(a) : "l"(p));
    return a;
}
__device__ __forceinline__ u64 pack2(float lo, float hi) {
    u64 r; asm("mov.b64 %0, {%1, %2};" : "=l"(r) : "f"(lo), "f"(hi)); return r;
}
__device__ __forceinline__ u64 dup2(float v) {
    u64 r; asm("mov.b64 %0, {%1, %1};" : "=l"(r) : "f"(v)); return r;
}
__device__ __forceinline__ void unpack2(u64 v, float& lo, float& hi) {
    asm("mov.b64 {%0, %1}, %2;" : "=f"(lo), "=f"(hi) : "l"(v));
}
__device__ __forceinline__ void fma2(u64& d, u64 a, u64 b) {
    asm("fma.rn.f32x2 %0, %1, %2, %0;" : "+l"(d) : "l"(a), "l"(b));
}
__device__ __forceinline__ void mma_tf32(float* d, const uint32_t* a,
                                         uint32_t b0, uint32_t b1) {
    asm volatile(
        "mma.sync.aligned.m16n8k8.row.col.f32.tf32.tf32.f32 "
        "{%0,%1,%2,%3}, {%4,%5,%6,%7}, {%8,%9}, {%0,%1,%2,%3};"
        : "+f"(d[0]), "+f"(d[1]), "+f"(d[2]), "+f"(d[3])
        : "r"(a[0]), "r"(a[1]), "r"(a[2]), "r"(a[3]), "r"(b0), "r"(b1));
}
__device__ __forceinline__ void mma_f16(float* d, const uint32_t* a,
                                        uint32_t b0, uint32_t b1) {
    asm volatile(
        "mma.sync.aligned.m16n8k16.row.col.f32.f16.f16.f32 "
        "{%0,%1,%2,%3}, {%4,%5,%6,%7}, {%8,%9}, {%0,%1,%2,%3};"
        : "+f"(d[0]), "+f"(d[1]), "+f"(d[2]), "+f"(d[3])
        : "r"(a[0]), "r"(a[1]), "r"(a[2]), "r"(a[3]), "r"(b0), "r"(b1));
}
__device__ __forceinline__ void cpa16(uint32_t d, const void* s) {
    asm volatile("cp.async.ca.shared.global [%0], [%1], 16;" :: "r"(d), "l"(s) : "memory");
}

// ---------------- zero (small buffers only) ----------------
__global__ void zero_k() {
    size_t i = (size_t)blockIdx.x * blockDim.x + threadIdx.x;
    size_t stride = (size_t)gridDim.x * blockDim.x;
    float4 z = make_float4(0.f, 0.f, 0.f, 0.f);
    float4* d = (float4*)g_deg;
    for (size_t j = i; j < (size_t)NR / 4; j += stride) d[j] = z;
    int4* c = (int4*)g_cnt;
    int4 zi = make_int4(0, 0, 0, 0);
    for (size_t j = i; j < (size_t)NR / 4; j += stride) c[j] = zi;
    if (i < DD) { g_s1a[i] = 0.0; g_s2a[i] = 0.0; g_s1b[i] = 0.0; g_s2b[i] = 0.0; }
}

// ---------------- x -> half ----------------
__global__ __launch_bounds__(256) void xhalf_k(const float* __restrict__ x) {
    int i = blockIdx.x * 256 + threadIdx.x;
    if (i >= NN * 32) return;
    float4 v = ((const float4*)x)[i];
    __half2* dst = (__half2*)g_xh + (size_t)i * 2;
    dst[0] = __floats2half2_rn(v.x, v.y);
    dst[1] = __floats2half2_rn(v.z, v.w);
}

// ---------------- prep: folds ----------------
__global__ __launch_bounds__(128) void prep_k(
    const float* __restrict__ l1_We, const float* __restrict__ l1_Wlin,
    const float* __restrict__ l1_be, const float* __restrict__ l1_blin,
    const float* __restrict__ l1_bself,
    const float* __restrict__ l2_We, const float* __restrict__ l2_Wlin,
    const float* __restrict__ l2_be, const float* __restrict__ l2_blin,
    const float* __restrict__ l2_bself)
{
    __shared__ float sWe[EDD * DD];
    __shared__ float sbe[DD];
    int r = blockIdx.x;
    int d = threadIdx.x;
    const float* We = (r < RR) ? l1_We : l2_We;
    const float* Wl = (r < RR) ? l1_Wlin : l2_Wlin;
    const float* be = (r < RR) ? l1_be : l2_be;
    for (int i = d; i < EDD * DD; i += 128) sWe[i] = We[i];
    sbe[d] = be[d];
    __syncthreads();
    float acc[EDD];
#pragma unroll
    for (int i = 0; i < EDD; i++) acc[i] = 0.f;
    float accb = 0.f;
    int rowoff = (r < RR) ? r * DD : 0;
    for (int k = 0; k < DD; k++) {
        float wl = Wl[(size_t)(rowoff + k) * DD + d];
        accb += sbe[k] * wl;
#pragma unroll
        for (int i = 0; i < EDD; i++) acc[i] += sWe[i * DD + k] * wl;
    }
    if (r < RR) {
#pragma unroll
        for (int i = 0; i < EDD; i++) g_WeWlin1[(size_t)(r * EDD + i) * DD + d] = acc[i];
        g_beWlin1[r * DD + d] = accb;
    } else {
#pragma unroll
        for (int i = 0; i < EDD; i++) g_WeWlin2[(size_t)i * DD + d] = acc[i];
        g_beWlin2[d] = accb;
        g_bias1[d] = l1_blin[d] + l1_bself[d];
        g_bias2[d] = l2_blin[d] + l2_bself[d];
    }
}

// ---------------- prepBt: Bt[n][k] half, fused [Wlin1;WeWlin1;Wself1] ----
__global__ __launch_bounds__(128) void prepBt_k(const float* __restrict__ Wlin1,
                                                const float* __restrict__ Wself1) {
    int n = blockIdx.x;
    for (int k = threadIdx.x; k < K1; k += 128) {
        float v;
        if (k < 1024)      v = Wlin1[(size_t)k * DD + n];
        else if (k < 1280) v = g_WeWlin1[(size_t)(k - 1024) * DD + n];
        else               v = Wself1[(size_t)(k - 1280) * DD + n];
        g_B1t[(size_t)n * K1 + k] = __float2half_rn(v);
    }
}

// ---------------- degree + histogram (by tr) ----------------
__global__ void deg_k(const int* __restrict__ nout, const int* __restrict__ rel,
                      const float* __restrict__ w) {
    int e = blockIdx.x * blockDim.x + threadIdx.x;
    if (e < EE) {
        int tr = rel[e] * NN + nout[e];
        atomicAdd(&g_deg[tr], w[e]);
        atomicAdd(&g_cnt[tr], 1);
    }
}

// ---------------- scan (exclusive prefix over g_cnt) ----------------
#define SCAN_BLK 1024
__global__ __launch_bounds__(1024) void scan1_k() {
    __shared__ int sh[SCAN_BLK];
    int t = threadIdx.x;
    int i = blockIdx.x * SCAN_BLK + t;
    sh[t] = (i < NR) ? g_cnt[i] : 0;
    __syncthreads();
    for (int s = 512; s > 0; s >>= 1) {
        if (t < s) sh[t] += sh[t + s];
        __syncthreads();
    }
    if (t == 0) g_bsum[blockIdx.x] = sh[0];
}
__global__ __launch_bounds__(512) void scan2_k() {
    __shared__ int sh[512];
    int t = threadIdx.x;
    int nb = (NR + SCAN_BLK - 1) / SCAN_BLK;
    int orig = (t < nb) ? g_bsum[t] : 0;
    sh[t] = orig;
    __syncthreads();
    for (int d = 1; d < 512; d <<= 1) {
        int x = (t >= d) ? sh[t - d] : 0;
        __syncthreads();
        sh[t] += x;
        __syncthreads();
    }
    if (t < nb) g_bsum[t] = sh[t] - orig;
}
__global__ __launch_bounds__(1024) void scan3_k() {
    __shared__ int sh[SCAN_BLK];
    int t = threadIdx.x;
    int i = blockIdx.x * SCAN_BLK + t;
    int orig = (i < NR) ? g_cnt[i] : 0;
    sh[t] = orig;
    __syncthreads();
    for (int d = 1; d < SCAN_BLK; d <<= 1) {
        int x = (t >= d) ? sh[t - d] : 0;
        __syncthreads();
        sh[t] += x;
        __syncthreads();
    }
    if (i < NR) {
        int excl = sh[t] - orig + g_bsum[blockIdx.x];
        g_off[i] = excl;
        g_cur[i] = excl;
    }
}
__global__ void place_k(const int* __restrict__ nin, const int* __restrict__ nout,
                        const int* __restrict__ rel, const float* __restrict__ w) {
    int e = blockIdx.x * blockDim.x + threadIdx.x;
    if (e < EE) {
        int tr = rel[e] * NN + nout[e];
        int pos = atomicAdd(&g_cur[tr], 1);
        g_csr_nin[pos] = nin[e];
        g_csr_eid[pos] = e;
        g_csr_ew[pos] = w[e] / g_deg[tr];
    }
}

// ---------------- agg1x: warp-per-tr CSR gather (x L2-resident) -----------
__global__ __launch_bounds__(256) void agg1x_k(const float* __restrict__ x,
                                               const float* __restrict__ ef) {
    int tid = threadIdx.x;
    int wid = tid >> 5;
    int lane = tid & 31;
    int c4 = lane << 2;
    int tr = blockIdx.x * 8 + wid;
    if (tr >= NR) return;

    int off = g_off[tr];
    int cnt = g_cnt[tr];
    float4 xacc = make_float4(0.f, 0.f, 0.f, 0.f);
    float eacc = 0.f;
    for (int j = 0; j < cnt; j++) {
        int nin  = __ldg(&g_csr_nin[off + j]);
        int eid  = __ldg(&g_csr_eid[off + j]);
        float w  = __ldg(&g_csr_ew[off + j]);
        float4 xv = __ldg((const float4*)&x[(size_t)nin * DD + c4]);
        xacc.x += w * xv.x; xacc.y += w * xv.y;
        xacc.z += w * xv.z; xacc.w += w * xv.w;
        eacc += w * __ldg(&ef[(size_t)eid * EDD + lane]);
    }
    __half2* dst = (__half2*)&g_aggx[(size_t)tr * DD + c4];
    dst[0] = __floats2half2_rn(xacc.x, xacc.y);
    dst[1] = __floats2half2_rn(xacc.z, xacc.w);
    g_aggef[(size_t)tr * EDD + lane] = __float2half_rn(eacc);
}

// ---------------- mma_L1: hpre = [aggx|aggef|x] @ B1t, fp16 m16n8k16 -----
// K = 1408 (44 chunks of 32); A and B both half in smem.
#define A_PADH 40
#define B_PADH 40
#define A_BYTES (128 * A_PADH * 2)           /* 10240 */
#define BH_BYTES (128 * B_PADH * 2)          /* 10240 */
#define STG_BYTES (A_BYTES + BH_BYTES)       /* 20480 */
#define MMAL1_SMEM (3 * STG_BYTES)           /* 61440 */
#define NCH_L1 44

__global__ void __launch_bounds__(256, 2) mma_L1_k() {
    extern __shared__ char smc[];
    int tid = threadIdx.x;
    int m0 = blockIdx.x * 128;
    uint32_t sb = smem_u32(smc);

    auto load_stage = [&](int s, int kc) {
        const __half* Asrc;
        int astride;
        if (kc < 32) {
            int r = kc >> 2;
            Asrc = g_aggx + (size_t)r * NN * DD + (kc & 3) * 32;
            astride = DD;
        } else if (kc < 40) {
            int r = kc - 32;
            Asrc = g_aggef + (size_t)r * NN * EDD;
            astride = EDD;
        } else {
            Asrc = g_xh + (kc - 40) * 32;
            astride = DD;
        }
        // A: 128 rows x 32 halves, 512 x 16B, 2 iters
#pragma unroll
        for (int j = 0; j < 2; j++) {
            int p = tid + j * 256;
            int row = p >> 2;
            int kq = (p & 3) * 8;
            uint32_t doff = sb + s * STG_BYTES + row * (A_PADH * 2) + kq * 2;
            int m = m0 + row;
            if (m < NN) cpa16(doff, Asrc + (size_t)m * astride + kq);
            else {
                float4 z = make_float4(0.f, 0.f, 0.f, 0.f);
                *(float4*)(smc + s * STG_BYTES + row * (A_PADH * 2) + kq * 2) = z;
            }
        }
        // B: 128 n-rows x 32 halves from g_B1t[n][kc*32 ...], 512 x 16B
        const __half* Bsrc = g_B1t + (size_t)kc * 32;
#pragma unroll
        for (int j = 0; j < 2; j++) {
            int p = tid + j * 256;
            int n = p >> 2;
            int kq = (p & 3) * 8;
            uint32_t doff = sb + s * STG_BYTES + A_BYTES + n * (B_PADH * 2) + kq * 2;
            cpa16(doff, Bsrc + (size_t)n * K1 + kq);
        }
        asm volatile("cp.async.commit_group;" ::: "memory");
    };

    int wid = tid >> 5, lane = tid & 31;
    int g = lane >> 2, t = lane & 3;
    int wm = (wid & 3) * 32, wn = (wid >> 2) * 64;

    float acc[2][8][4];
#pragma unroll
    for (int mi = 0; mi < 2; mi++)
#pragma unroll
        for (int ni = 0; ni < 8; ni++) {
            acc[mi][ni][0] = 0.f; acc[mi][ni][1] = 0.f;
            acc[mi][ni][2] = 0.f; acc[mi][ni][3] = 0.f;
        }

    load_stage(0, 0);
    load_stage(1, 1);

    for (int kc = 0; kc < NCH_L1; kc++) {
        if (kc + 2 < NCH_L1) {
            load_stage((kc + 2) % 3, kc + 2);
            asm volatile("cp.async.wait_group 2;" ::: "memory");
        } else if (kc + 1 < NCH_L1) {
            asm volatile("cp.async.wait_group 1;" ::: "memory");
        } else {
            asm volatile("cp.async.wait_group 0;" ::: "memory");
        }
        __syncthreads();
        const __half* hA = (const __half*)(smc + (kc % 3) * STG_BYTES);
        const __half* hB = (const __half*)(smc + (kc % 3) * STG_BYTES + A_BYTES);
#pragma unroll
        for (int ks = 0; ks < 2; ks++) {          // two K=16 steps per chunk
            int kb = ks * 16;
            uint32_t a[2][4];
#pragma unroll
            for (int mi = 0; mi < 2; mi++) {
                int bm = wm + mi * 16;
                a[mi][0] = *(const uint32_t*)&hA[(bm + g) * A_PADH + kb + 2 * t];
                a[mi][1] = *(const uint32_t*)&hA[(bm + g + 8) * A_PADH + kb + 2 * t];
                a[mi][2] = *(const uint32_t*)&hA[(bm + g) * A_PADH + kb + 2 * t + 8];
                a[mi][3] = *(const uint32_t*)&hA[(bm + g + 8) * A_PADH + kb + 2 * t + 8];
            }
#pragma unroll
            for (int ni = 0; ni < 8; ni++) {
                int bn = wn + ni * 8;
                uint32_t b0 = *(const uint32_t*)&hB[(bn + g) * B_PADH + kb + 2 * t];
                uint32_t b1 = *(const uint32_t*)&hB[(bn + g) * B_PADH + kb + 2 * t + 8];
                mma_f16(acc[0][ni], a[0], b0, b1);
                mma_f16(acc[1][ni], a[1], b0, b1);
            }
        }
        __syncthreads();
    }

#pragma unroll
    for (int mi = 0; mi < 2; mi++) {
#pragma unroll
        for (int ni = 0; ni < 8; ni++) {
            int mg = m0 + wm + mi * 16 + g;
            int c = wn + ni * 8 + 2 * t;
            if (mg < NN)
                *(float2*)&g_hpre[(size_t)mg * DD + c] =
                    make_float2(acc[mi][ni][0], acc[mi][ni][1]);
            if (mg + 8 < NN)
                *(float2*)&g_hpre[(size_t)(mg + 8) * DD + c] =
                    make_float2(acc[mi][ni][2], acc[mi][ni][3]);
        }
    }
}

// ---------------- epi1: hpre += bias1 + mask*beW1 ; BN1 stats -------------
#define EPI1_BLOCKS 1184
__global__ __launch_bounds__(256) void epi1_k() {
    __shared__ __align__(16) float sBe[RR * DD];
    __shared__ float sBias[DD];
    __shared__ float sRed[2][DD];
    int tid = threadIdx.x;
    int wid = tid >> 5;
    int lane = tid & 31;
    int c4 = lane << 2;
    for (int i = tid; i < RR * DD; i += 256) sBe[i] = g_beWlin1[i];
    if (tid < DD) { sBias[tid] = g_bias1[tid]; sRed[0][tid] = 0.f; sRed[1][tid] = 0.f; }
    __syncthreads();

    float s1[4] = {0.f, 0.f, 0.f, 0.f};
    float s2[4] = {0.f, 0.f, 0.f, 0.f};

    for (int m = blockIdx.x * 8 + wid; m < NN; m += EPI1_BLOCKS * 8) {
        int cbit = (lane < RR) ? (g_cnt[lane * NN + m] > 0) : 0;
        unsigned mask8 = __ballot_sync(0xffffffffu, cbit) & 0xFFu;

        float4 v = *(float4*)&g_hpre[(size_t)m * DD + c4];
        v.x += sBias[c4 + 0]; v.y += sBias[c4 + 1];
        v.z += sBias[c4 + 2]; v.w += sBias[c4 + 3];
#pragma unroll
        for (int r = 0; r < RR; r++) {
            if ((mask8 >> r) & 1u) {
                float4 be = *(float4*)&sBe[r * DD + c4];
                v.x += be.x; v.y += be.y; v.z += be.z; v.w += be.w;
            }
        }
        *(float4*)&g_hpre[(size_t)m * DD + c4] = v;
        s1[0] += v.x; s1[1] += v.y; s1[2] += v.z; s1[3] += v.w;
        s2[0] += v.x * v.x; s2[1] += v.y * v.y;
        s2[2] += v.z * v.z; s2[3] += v.w * v.w;
    }

#pragma unroll
    for (int i = 0; i < 4; i++) {
        atomicAdd(&sRed[0][c4 + i], s1[i]);
        atomicAdd(&sRed[1][c4 + i], s2[i]);
    }
    __syncthreads();
    if (tid < DD) {
        atomicAdd(&g_s1a[tid], (double)sRed[0][tid]);
        atomicAdd(&g_s2a[tid], (double)sRed[1][tid]);
    }
}

// ---------------- BN finalize (float consts for consumers) ----------------
__global__ void bnfin_k(int sel, float nrows, const float* __restrict__ g,
                        const float* __restrict__ b) {
    int d = threadIdx.x;
    double s1 = sel ? g_s1b[d] : g_s1a[d];
    double s2 = sel ? g_s2b[d] : g_s2a[d];
    double m = s1 / (double)nrows;
    double var = s2 / (double)nrows - m * m;
    float sc = g[d] * rsqrtf((float)var + 1e-5f);
    float sh = b[d] - (float)m * sc;
    if (sel) { g_sc2[d] = sc; g_sh2[d] = sh; }
    else     { g_sc1[d] = sc; g_sh1[d] = sh; }
}

// ---------------- mma1: A = relu(bn1(hpre)) fused at fragment load --------
#define A1_FLOATS (128*36)
#define B1_FLOATS (32*132)
#define STG1_FLOATS (A1_FLOATS + B1_FLOATS)
#define MMA1_SMEM (3 * STG1_FLOATS * 4)

__global__ void __launch_bounds__(256, 2) mma1_k(
    const float* __restrict__ B0, const float* __restrict__ B1)
{
    extern __shared__ float smf[];
    __shared__ float sSc[DD], sSh[DD];
    int tid = threadIdx.x;
    int m0 = blockIdx.x * 128;
    int rsel = blockIdx.y;

    const float* B = rsel ? B1 : B0;
    float* dst = rsel ? g_hs : g_hW2;
    const float* bias = rsel ? g_bias2 : nullptr;

    if (tid < DD) { sSc[tid] = g_sc1[tid]; sSh[tid] = g_sh1[tid]; }

    uint32_t sb = smem_u32(smf);

    auto load_stage = [&](int s, int kc) {
        int k0 = kc * 32;
        float4 z = make_float4(0.f, 0.f, 0.f, 0.f);
#pragma unroll
        for (int j = 0; j < 4; j++) {
            int p = tid + j * 256;
            int row = p >> 3;
            int kq = (p & 7) << 2;
            int idx = s * STG1_FLOATS + row * 36 + kq;
            int m = m0 + row;
            if (m < NN) cpa16(sb + idx * 4, g_hpre + (size_t)m * DD + k0 + kq);
            else *(float4*)&smf[idx] = z;
        }
#pragma unroll
        for (int j = 0; j < 4; j++) {
            int p = tid + j * 256;
            int k = p >> 5;
            int n4 = (p & 31) << 2;
            int idx = s * STG1_FLOATS + A1_FLOATS + k * 132 + n4;
            cpa16(sb + idx * 4, B + (size_t)(k0 + k) * DD + n4);
        }
        asm volatile("cp.async.commit_group;" ::: "memory");
    };

    int wid = tid >> 5, lane = tid & 31;
    int g = lane >> 2, t = lane & 3;
    int wm = (wid & 3) * 32, wn = (wid >> 2) * 64;

    float acc[2][8][4];
#pragma unroll
    for (int mi = 0; mi < 2; mi++)
#pragma unroll
        for (int ni = 0; ni < 8; ni++) {
            acc[mi][ni][0] = 0.f; acc[mi][ni][1] = 0.f;
            acc[mi][ni][2] = 0.f; acc[mi][ni][3] = 0.f;
        }

    load_stage(0, 0);
    load_stage(1, 1);

    for (int kc = 0; kc < 4; kc++) {
        if (kc + 2 < 4) {
            load_stage((kc + 2) % 3, kc + 2);
            asm volatile("cp.async.wait_group 2;" ::: "memory");
        } else if (kc + 1 < 4) {
            asm volatile("cp.async.wait_group 1;" ::: "memory");
        } else {
            asm volatile("cp.async.wait_group 0;" ::: "memory");
        }
        __syncthreads();
        const float* cA = smf + (kc % 3) * STG1_FLOATS;
        const float* cB = cA + A1_FLOATS;
        int k0 = kc * 32;
#pragma unroll
        for (int ks = 0; ks < 4; ks++) {
            int kb = ks * 8;
            float sc0 = sSc[k0 + kb + t],     sh0 = sSh[k0 + kb + t];
            float sc4 = sSc[k0 + kb + t + 4], sh4 = sSh[k0 + kb + t + 4];
            uint32_t a[2][4];
#pragma unroll
            for (int mi = 0; mi < 2; mi++) {
                int bm = wm + mi * 16;
                a[mi][0] = __float_as_uint(fmaxf(0.f, cA[(bm + g) * 36 + kb + t] * sc0 + sh0));
                a[mi][1] = __float_as_uint(fmaxf(0.f, cA[(bm + g + 8) * 36 + kb + t] * sc0 + sh0));
                a[mi][2] = __float_as_uint(fmaxf(0.f, cA[(bm + g) * 36 + kb + t + 4] * sc4 + sh4));
                a[mi][3] = __float_as_uint(fmaxf(0.f, cA[(bm + g + 8) * 36 + kb + t + 4] * sc4 + sh4));
            }
#pragma unroll
            for (int ni = 0; ni < 8; ni++) {
                int bn = wn + ni * 8;
                uint32_t b0 = __float_as_uint(cB[(kb + t) * 132 + bn + g]);
                uint32_t b1 = __float_as_uint(cB[(kb + t + 4) * 132 + bn + g]);
                mma_tf32(acc[0][ni], a[0], b0, b1);
                mma_tf32(acc[1][ni], a[1], b0, b1);
            }
        }
        __syncthreads();
    }

#pragma unroll
    for (int mi = 0; mi < 2; mi++) {
#pragma unroll
        for (int ni = 0; ni < 8; ni++) {
            int mg = m0 + wm + mi * 16 + g;
            int c = wn + ni * 8 + 2 * t;
            float2 v0 = make_float2(acc[mi][ni][0], acc[mi][ni][1]);
            float2 v1 = make_float2(acc[mi][ni][2], acc[mi][ni][3]);
            if (bias) {
                float b0 = bias[c], b1 = bias[c + 1];
                v0.x += b0; v0.y += b1; v1.x += b0; v1.y += b1;
            }
            if (mg < NN) *(float2*)&dst[(size_t)mg * DD + c] = v0;
            if (mg + 8 < NN) *(float2*)&dst[(size_t)(mg + 8) * DD + c] = v1;
        }
    }
}

// ---------------- agg2: warp-per-node layer-2 assembly + BN2 stats --------
#define AGG2_BLOCKS 1184
__global__ __launch_bounds__(256) void agg2_k(float* __restrict__ out) {
    __shared__ __align__(16) float sW2[EDD * DD];
    __shared__ __align__(16) float sBe2[DD];
    __shared__ float sRed[2][DD];
    int tid = threadIdx.x;
    int wid = tid >> 5;
    int lane = tid & 31;
    int c4 = lane << 2;
    for (int i = tid; i < EDD * DD; i += 256) sW2[i] = g_WeWlin2[i];
    if (tid < DD) { sBe2[tid] = g_beWlin2[tid]; sRed[0][tid] = 0.f; sRed[1][tid] = 0.f; }
    __syncthreads();

    float s1[4] = {0.f, 0.f, 0.f, 0.f};
    float s2[4] = {0.f, 0.f, 0.f, 0.f};

    for (int no = blockIdx.x * 8 + wid; no < NN; no += AGG2_BLOCKS * 8) {
        float4 hsv = __ldg((const float4*)&g_hs[(size_t)no * DD + c4]);
#pragma unroll
        for (int r = 0; r < RR; r++) {
            int tr = r * NN + no;
            int cnt = g_cnt[tr];
            if (cnt == 0) {
                *(float4*)&out[(size_t)tr * DD + c4] = hsv;
                s1[0] += hsv.x; s1[1] += hsv.y; s1[2] += hsv.z; s1[3] += hsv.w;
                s2[0] += hsv.x * hsv.x; s2[1] += hsv.y * hsv.y;
                s2[2] += hsv.z * hsv.z; s2[3] += hsv.w * hsv.w;
                continue;
            }
            int off = g_off[tr];
            float4 acc = hsv;
            {
                float4 be = *(float4*)&sBe2[c4];
                acc.x += be.x; acc.y += be.y; acc.z += be.z; acc.w += be.w;
            }
            for (int j = 0; j < cnt; j++) {
                int nin = __ldg(&g_csr_nin[off + j]);
                float w = __ldg(&g_csr_ew[off + j]);
                float4 hv = __ldg((const float4*)&g_hW2[(size_t)nin * DD + c4]);
                acc.x += w * hv.x; acc.y += w * hv.y;
                acc.z += w * hv.z; acc.w += w * hv.w;
            }

            float aef = __half2float(g_aggef[(size_t)tr * EDD + lane]);
            u64 a01 = pack2(acc.x, acc.y), a23 = pack2(acc.z, acc.w);
#pragma unroll
            for (int i = 0; i < EDD; i++) {
                float a = __shfl_sync(0xffffffffu, aef, i);
                u64 ad = dup2(a);
                const u64* wp = (const u64*)&sW2[i * DD + c4];
                fma2(a01, ad, wp[0]);
                fma2(a23, ad, wp[1]);
            }
            unpack2(a01, acc.x, acc.y);
            unpack2(a23, acc.z, acc.w);

            *(float4*)&out[(size_t)tr * DD + c4] = acc;
            s1[0] += acc.x; s1[1] += acc.y; s1[2] += acc.z; s1[3] += acc.w;
            s2[0] += acc.x * acc.x; s2[1] += acc.y * acc.y;
            s2[2] += acc.z * acc.z; s2[3] += acc.w * acc.w;
        }
    }

#pragma unroll
    for (int i = 0; i < 4; i++) {
        atomicAdd(&sRed[0][c4 + i], s1[i]);
        atomicAdd(&sRed[1][c4 + i], s2[i]);
    }
    __syncthreads();
    if (tid < DD) {
        atomicAdd(&g_s1b[tid], (double)sRed[0][tid]);
        atomicAdd(&g_s2b[tid], (double)sRed[1][tid]);
    }
}

// ---------------- bnrelu_o: apply BN2 (float consts) ----------------------
__global__ __launch_bounds__(256) void bnrelu_o_k(float* __restrict__ out) {
    int i = blockIdx.x * 256 + threadIdx.x;
    if (i >= M2 * 32) return;
    int c = (i & 31) << 2;
    float4 v = ((const float4*)out)[i];
    v.x = fmaxf(0.f, v.x * g_sc2[c + 0] + g_sh2[c + 0]);
    v.y = fmaxf(0.f, v.y * g_sc2[c + 1] + g_sh2[c + 1]);
    v.z = fmaxf(0.f, v.z * g_sc2[c + 2] + g_sh2[c + 2]);
    v.w = fmaxf(0.f, v.w * g_sc2[c + 3] + g_sh2[c + 3]);
    ((float4*)out)[i] = v;
}

// ---------------- launch ----------------
extern "C" void kernel_launch(void* const* d_in, const int* in_sizes, int n_in,
                              void* d_out, int out_size) {
    (void)in_sizes; (void)n_in; (void)out_size;
    const float* x        = (const float*)d_in[0];
    const int*   node_in  = (const int*)d_in[1];
    const int*   node_out = (const int*)d_in[2];
    const int*   relation = (const int*)d_in[3];
    const float* ew       = (const float*)d_in[4];
    const float* ef       = (const float*)d_in[5];
    const float* l1_Wlin  = (const float*)d_in[6];
    const float* l1_blin  = (const float*)d_in[7];
    const float* l1_Wself = (const float*)d_in[8];
    const float* l1_bself = (const float*)d_in[9];
    const float* l1_Wedge = (const float*)d_in[10];
    const float* l1_bedge = (const float*)d_in[11];
    const float* l1_g     = (const float*)d_in[12];
    const float* l1_b     = (const float*)d_in[13];
    const float* l2_Wlin  = (const float*)d_in[14];
    const float* l2_blin  = (const float*)d_in[15];
    const float* l2_Wself = (const float*)d_in[16];
    const float* l2_bself = (const float*)d_in[17];
    const float* l2_Wedge = (const float*)d_in[18];
    const float* l2_bedge = (const float*)d_in[19];
    const float* l2_g     = (const float*)d_in[20];
    const float* l2_b     = (const float*)d_in[21];
    float* out = (float*)d_out;

    int gmm = (NN + 127) / 128;   // 391
    int nsb = (NR + SCAN_BLK - 1) / SCAN_BLK;  // 391

    static int configured = 0;
    if (!configured) {
        cudaFuncSetAttribute(mma_L1_k, cudaFuncAttributeMaxDynamicSharedMemorySize,
                             MMAL1_SMEM);
        cudaFuncSetAttribute(mma1_k, cudaFuncAttributeMaxDynamicSharedMemorySize,
                             MMA1_SMEM);
        configured = 1;
    }

    zero_k<<<512, 256>>>();
    xhalf_k<<<(NN * 32 + 255) / 256, 256>>>(x);
    prep_k<<<RR + 1, 128>>>(l1_Wedge, l1_Wlin, l1_bedge, l1_blin, l1_bself,
                            l2_Wedge, l2_Wlin, l2_bedge, l2_blin, l2_bself);
    prepBt_k<<<DD, 128>>>(l1_Wlin, l1_Wself);
    deg_k<<<EE / 256, 256>>>(node_out, relation, ew);
    scan1_k<<<nsb, 1024>>>();
    scan2_k<<<1, 512>>>();
    scan3_k<<<nsb, 1024>>>();
    place_k<<<EE / 256, 256>>>(node_in, node_out, relation, ew);
    agg1x_k<<<NR / 8, 256>>>(x, ef);
    mma_L1_k<<<gmm, 256, MMAL1_SMEM>>>();
    epi1_k<<<EPI1_BLOCKS, 256>>>();
    bnfin_k<<<1, 128>>>(0, (float)NN, l1_g, l1_b);
    mma1_k<<<dim3(gmm, 2), 256, MMA1_SMEM>>>(l2_Wlin, l2_Wself);
    agg2_k<<<AGG2_BLOCKS, 256>>>(out);
    bnfin_k<<<1, 128>>>(1, (float)M2, l2_g, l2_b);
    bnrelu_o_k<<<(M2 * 32) / 256, 256>>>(out);
}

// round 15
// speedup vs baseline: 1.3695x; 1.0077x over previous
#include <cuda_runtime.h>
#include <cuda_fp16.h>
#include <cstdint>

#define NN 50000
#define DD 128
#define RR 8
#define EE 800000
#define EDD 32
#define NR (NN*RR)
#define M2 (RR*NN)
#define K1 1408

typedef unsigned long long u64;

// ---------------- scratch ----------------
__device__ float  g_deg[NR];                 // indexed by tr = r*NN + no
__device__ __half g_aggef[NR*EDD];           // [r][no][32]
__device__ __half g_aggx[(size_t)NR*DD];     // [r][no][128]
__device__ __half g_xh[(size_t)NN*DD];       // x in half
__device__ __half g_hh[(size_t)NN*DD];       // relu(bn1(hpre)) in half
__device__ __half g_B1t[(size_t)DD*K1];      // [n][k] fused B1 transposed, half
__device__ __half g_B2t[(size_t)2*DD*DD];    // [sel][n][k]: Wlin2, Wself2
__device__ float  g_hpre[NN*DD];
__device__ float  g_hW2[NN*DD];
__device__ float  g_hs[NN*DD];
__device__ float  g_WeWlin1[RR*EDD*DD];
__device__ float  g_WeWlin2[EDD*DD];
__device__ float  g_beWlin1[RR*DD];
__device__ float  g_beWlin2[DD];
__device__ float  g_bias1[DD];
__device__ float  g_bias2[DD];
__device__ double g_s1a[DD], g_s2a[DD], g_s1b[DD], g_s2b[DD];
__device__ float  g_sc1[DD], g_sh1[DD], g_sc2[DD], g_sh2[DD];
// CSR by tr (packed)
__device__ int   g_cnt[NR];
__device__ int   g_off[NR];
__device__ int   g_cur[NR];
__device__ int   g_bsum[512];
__device__ int4  g_csr4[EE];                 // {nin, eid, ew_bits, 0}

// ---------------- helpers ----------------
__device__ __forceinline__ uint32_t smem_u32(const void* p) {
    uint32_t a;
    asm("{ .reg .u64 t; cvta.to.shared.u64 t, %1; cvt.u32.u64 %0, t; }" : "=r"(a) : "l"(p));
    return a;
}
__device__ __forceinline__ u64 pack2(float lo, float hi) {
    u64 r; asm("mov.b64 %0, {%1, %2};" : "=l"(r) : "f"(lo), "f"(hi)); return r;
}
__device__ __forceinline__ u64 dup2(float v) {
    u64 r; asm("mov.b64 %0, {%1, %1};" : "=l"(r) : "f"(v)); return r;
}
__device__ __forceinline__ void unpack2(u64 v, float& lo, float& hi) {
    asm("mov.b64 {%0, %1}, %2;" : "=f"(lo), "=f"(hi) : "l"(v));
}
__device__ __forceinline__ void fma2(u64& d, u64 a, u64 b) {
    asm("fma.rn.f32x2 %0, %1, %2, %0;" : "+l"(d) : "l"(a), "l"(b));
}
__device__ __forceinline__ void mma_f16(float* d, const uint32_t* a,
                                        uint32_t b0, uint32_t b1) {
    asm volatile(
        "mma.sync.aligned.m16n8k16.row.col.f32.f16.f16.f32 "
        "{%0,%1,%2,%3}, {%4,%5,%6,%7}, {%8,%9}, {%0,%1,%2,%3};"
        : "+f"(d[0]), "+f"(d[1]), "+f"(d[2]), "+f"(d[3])
        : "r"(a[0]), "r"(a[1]), "r"(a[2]), "r"(a[3]), "r"(b0), "r"(b1));
}
__device__ __forceinline__ void cpa16(uint32_t d, const void* s) {
    asm volatile("cp.async.ca.shared.global [%0], [%1], 16;" :: "r"(d), "l"(s) : "memory");
}

// ---------------- zero (small buffers only) ----------------
__global__ void zero_k() {
    size_t i = (size_t)blockIdx.x * blockDim.x + threadIdx.x;
    size_t stride = (size_t)gridDim.x * blockDim.x;
    float4 z = make_float4(0.f, 0.f, 0.f, 0.f);
    float4* d = (float4*)g_deg;
    for (size_t j = i; j < (size_t)NR / 4; j += stride) d[j] = z;
    int4* c = (int4*)g_cnt;
    int4 zi = make_int4(0, 0, 0, 0);
    for (size_t j = i; j < (size_t)NR / 4; j += stride) c[j] = zi;
    if (i < DD) { g_s1a[i] = 0.0; g_s2a[i] = 0.0; g_s1b[i] = 0.0; g_s2b[i] = 0.0; }
}

// ---------------- x -> half ----------------
__global__ __launch_bounds__(256) void xhalf_k(const float* __restrict__ x) {
    int i = blockIdx.x * 256 + threadIdx.x;
    if (i >= NN * 32) return;
    float4 v = ((const float4*)x)[i];
    __half2* dst = (__half2*)g_xh + (size_t)i * 2;
    dst[0] = __floats2half2_rn(v.x, v.y);
    dst[1] = __floats2half2_rn(v.z, v.w);
}

// ---------------- prep: folds ----------------
__global__ __launch_bounds__(128) void prep_k(
    const float* __restrict__ l1_We, const float* __restrict__ l1_Wlin,
    const float* __restrict__ l1_be, const float* __restrict__ l1_blin,
    const float* __restrict__ l1_bself,
    const float* __restrict__ l2_We, const float* __restrict__ l2_Wlin,
    const float* __restrict__ l2_be, const float* __restrict__ l2_blin,
    const float* __restrict__ l2_bself)
{
    __shared__ float sWe[EDD * DD];
    __shared__ float sbe[DD];
    int r = blockIdx.x;
    int d = threadIdx.x;
    const float* We = (r < RR) ? l1_We : l2_We;
    const float* Wl = (r < RR) ? l1_Wlin : l2_Wlin;
    const float* be = (r < RR) ? l1_be : l2_be;
    for (int i = d; i < EDD * DD; i += 128) sWe[i] = We[i];
    sbe[d] = be[d];
    __syncthreads();
    float acc[EDD];
#pragma unroll
    for (int i = 0; i < EDD; i++) acc[i] = 0.f;
    float accb = 0.f;
    int rowoff = (r < RR) ? r * DD : 0;
    for (int k = 0; k < DD; k++) {
        float wl = Wl[(size_t)(rowoff + k) * DD + d];
        accb += sbe[k] * wl;
#pragma unroll
        for (int i = 0; i < EDD; i++) acc[i] += sWe[i * DD + k] * wl;
    }
    if (r < RR) {
#pragma unroll
        for (int i = 0; i < EDD; i++) g_WeWlin1[(size_t)(r * EDD + i) * DD + d] = acc[i];
        g_beWlin1[r * DD + d] = accb;
    } else {
#pragma unroll
        for (int i = 0; i < EDD; i++) g_WeWlin2[(size_t)i * DD + d] = acc[i];
        g_beWlin2[d] = accb;
        g_bias1[d] = l1_blin[d] + l1_bself[d];
        g_bias2[d] = l2_blin[d] + l2_bself[d];
    }
}

// ---------------- prepBt: B1t[n][k] half, fused [Wlin1;WeWlin1;Wself1] ----
__global__ __launch_bounds__(128) void prepBt_k(const float* __restrict__ Wlin1,
                                                const float* __restrict__ Wself1) {
    int n = blockIdx.x;
    for (int k = threadIdx.x; k < K1; k += 128) {
        float v;
        if (k < 1024)      v = Wlin1[(size_t)k * DD + n];
        else if (k < 1280) v = g_WeWlin1[(size_t)(k - 1024) * DD + n];
        else               v = Wself1[(size_t)(k - 1280) * DD + n];
        g_B1t[(size_t)n * K1 + k] = __float2half_rn(v);
    }
}

// ---------------- prepBt2: B2t[sel][n][k] half (Wlin2 / Wself2) -----------
__global__ __launch_bounds__(128) void prepBt2_k(const float* __restrict__ Wlin2,
                                                 const float* __restrict__ Wself2) {
    int b = blockIdx.x;          // sel*128 + n
    int sel = b >> 7;
    int n = b & 127;
    const float* W = sel ? Wself2 : Wlin2;
    for (int k = threadIdx.x; k < DD; k += 128)
        g_B2t[(size_t)b * DD + k] = __float2half_rn(W[(size_t)k * DD + n]);
}

// ---------------- degree + histogram (by tr) ----------------
__global__ void deg_k(const int* __restrict__ nout, const int* __restrict__ rel,
                      const float* __restrict__ w) {
    int e = blockIdx.x * blockDim.x + threadIdx.x;
    if (e < EE) {
        int tr = rel[e] * NN + nout[e];
        atomicAdd(&g_deg[tr], w[e]);
        atomicAdd(&g_cnt[tr], 1);
    }
}

// ---------------- scan (exclusive prefix over g_cnt) ----------------
#define SCAN_BLK 1024
__global__ __launch_bounds__(1024) void scan1_k() {
    __shared__ int sh[SCAN_BLK];
    int t = threadIdx.x;
    int i = blockIdx.x * SCAN_BLK + t;
    sh[t] = (i < NR) ? g_cnt[i] : 0;
    __syncthreads();
    for (int s = 512; s > 0; s >>= 1) {
        if (t < s) sh[t] += sh[t + s];
        __syncthreads();
    }
    if (t == 0) g_bsum[blockIdx.x] = sh[0];
}
__global__ __launch_bounds__(512) void scan2_k() {
    __shared__ int sh[512];
    int t = threadIdx.x;
    int nb = (NR + SCAN_BLK - 1) / SCAN_BLK;
    int orig = (t < nb) ? g_bsum[t] : 0;
    sh[t] = orig;
    __syncthreads();
    for (int d = 1; d < 512; d <<= 1) {
        int x = (t >= d) ? sh[t - d] : 0;
        __syncthreads();
        sh[t] += x;
        __syncthreads();
    }
    if (t < nb) g_bsum[t] = sh[t] - orig;
}
__global__ __launch_bounds__(1024) void scan3_k() {
    __shared__ int sh[SCAN_BLK];
    int t = threadIdx.x;
    int i = blockIdx.x * SCAN_BLK + t;
    int orig = (i < NR) ? g_cnt[i] : 0;
    sh[t] = orig;
    __syncthreads();
    for (int d = 1; d < SCAN_BLK; d <<= 1) {
        int x = (t >= d) ? sh[t - d] : 0;
        __syncthreads();
        sh[t] += x;
        __syncthreads();
    }
    if (i < NR) {
        int excl = sh[t] - orig + g_bsum[blockIdx.x];
        g_off[i] = excl;
        g_cur[i] = excl;
    }
}
__global__ void place_k(const int* __restrict__ nin, const int* __restrict__ nout,
                        const int* __restrict__ rel, const float* __restrict__ w) {
    int e = blockIdx.x * blockDim.x + threadIdx.x;
    if (e < EE) {
        int tr = rel[e] * NN + nout[e];
        int pos = atomicAdd(&g_cur[tr], 1);
        g_csr4[pos] = make_int4(nin[e], e, __float_as_int(w[e] / g_deg[tr]), 0);
    }
}

// ---------------- agg1x: warp-per-tr CSR gather (x L2-resident) -----------
__global__ __launch_bounds__(256) void agg1x_k(const float* __restrict__ x,
                                               const float* __restrict__ ef) {
    int tid = threadIdx.x;
    int wid = tid >> 5;
    int lane = tid & 31;
    int c4 = lane << 2;
    int tr = blockIdx.x * 8 + wid;
    if (tr >= NR) return;

    int off = g_off[tr];
    int cnt = g_cnt[tr];
    float4 xacc = make_float4(0.f, 0.f, 0.f, 0.f);
    float eacc = 0.f;
    for (int j = 0; j < cnt; j++) {
        int4 cs = __ldg(&g_csr4[off + j]);
        float w = __int_as_float(cs.z);
        float4 xv = __ldg((const float4*)&x[(size_t)cs.x * DD + c4]);
        xacc.x += w * xv.x; xacc.y += w * xv.y;
        xacc.z += w * xv.z; xacc.w += w * xv.w;
        eacc += w * __ldg(&ef[(size_t)cs.y * EDD + lane]);
    }
    __half2* dst = (__half2*)&g_aggx[(size_t)tr * DD + c4];
    dst[0] = __floats2half2_rn(xacc.x, xacc.y);
    dst[1] = __floats2half2_rn(xacc.z, xacc.w);
    g_aggef[(size_t)tr * EDD + lane] = __float2half_rn(eacc);
}

// ---------------- mma_L1: hpre = [aggx|aggef|x] @ B1t, fp16 m16n8k16 -----
#define A_PADH 40
#define B_PADH 40
#define A_BYTES (128 * A_PADH * 2)           /* 10240 */
#define BH_BYTES (128 * B_PADH * 2)          /* 10240 */
#define STG_BYTES (A_BYTES + BH_BYTES)       /* 20480 */
#define MMAL1_SMEM (3 * STG_BYTES)           /* 61440 */
#define NCH_L1 44

__global__ void __launch_bounds__(256, 2) mma_L1_k() {
    extern __shared__ char smc[];
    int tid = threadIdx.x;
    int m0 = blockIdx.x * 128;
    uint32_t sb = smem_u32(smc);

    auto load_stage = [&](int s, int kc) {
        const __half* Asrc;
        int astride;
        if (kc < 32) {
            int r = kc >> 2;
            Asrc = g_aggx + (size_t)r * NN * DD + (kc & 3) * 32;
            astride = DD;
        } else if (kc < 40) {
            int r = kc - 32;
            Asrc = g_aggef + (size_t)r * NN * EDD;
            astride = EDD;
        } else {
            Asrc = g_xh + (kc - 40) * 32;
            astride = DD;
        }
#pragma unroll
        for (int j = 0; j < 2; j++) {
            int p = tid + j * 256;
            int row = p >> 2;
            int kq = (p & 3) * 8;
            uint32_t doff = sb + s * STG_BYTES + row * (A_PADH * 2) + kq * 2;
            int m = m0 + row;
            if (m < NN) cpa16(doff, Asrc + (size_t)m * astride + kq);
            else {
                float4 z = make_float4(0.f, 0.f, 0.f, 0.f);
                *(float4*)(smc + s * STG_BYTES + row * (A_PADH * 2) + kq * 2) = z;
            }
        }
        const __half* Bsrc = g_B1t + (size_t)kc * 32;
#pragma unroll
        for (int j = 0; j < 2; j++) {
            int p = tid + j * 256;
            int n = p >> 2;
            int kq = (p & 3) * 8;
            uint32_t doff = sb + s * STG_BYTES + A_BYTES + n * (B_PADH * 2) + kq * 2;
            cpa16(doff, Bsrc + (size_t)n * K1 + kq);
        }
        asm volatile("cp.async.commit_group;" ::: "memory");
    };

    int wid = tid >> 5, lane = tid & 31;
    int g = lane >> 2, t = lane & 3;
    int wm = (wid & 3) * 32, wn = (wid >> 2) * 64;

    float acc[2][8][4];
#pragma unroll
    for (int mi = 0; mi < 2; mi++)
#pragma unroll
        for (int ni = 0; ni < 8; ni++) {
            acc[mi][ni][0] = 0.f; acc[mi][ni][1] = 0.f;
            acc[mi][ni][2] = 0.f; acc[mi][ni][3] = 0.f;
        }

    load_stage(0, 0);
    load_stage(1, 1);

    for (int kc = 0; kc < NCH_L1; kc++) {
        if (kc + 2 < NCH_L1) {
            load_stage((kc + 2) % 3, kc + 2);
            asm volatile("cp.async.wait_group 2;" ::: "memory");
        } else if (kc + 1 < NCH_L1) {
            asm volatile("cp.async.wait_group 1;" ::: "memory");
        } else {
            asm volatile("cp.async.wait_group 0;" ::: "memory");
        }
        __syncthreads();
        const __half* hA = (const __half*)(smc + (kc % 3) * STG_BYTES);
        const __half* hB = (const __half*)(smc + (kc % 3) * STG_BYTES + A_BYTES);
#pragma unroll
        for (int ks = 0; ks < 2; ks++) {
            int kb = ks * 16;
            uint32_t a[2][4];
#pragma unroll
            for (int mi = 0; mi < 2; mi++) {
                int bm = wm + mi * 16;
                a[mi][0] = *(const uint32_t*)&hA[(bm + g) * A_PADH + kb + 2 * t];
                a[mi][1] = *(const uint32_t*)&hA[(bm + g + 8) * A_PADH + kb + 2 * t];
                a[mi][2] = *(const uint32_t*)&hA[(bm + g) * A_PADH + kb + 2 * t + 8];
                a[mi][3] = *(const uint32_t*)&hA[(bm + g + 8) * A_PADH + kb + 2 * t + 8];
            }
#pragma unroll
            for (int ni = 0; ni < 8; ni++) {
                int bn = wn + ni * 8;
                uint32_t b0 = *(const uint32_t*)&hB[(bn + g) * B_PADH + kb + 2 * t];
                uint32_t b1 = *(const uint32_t*)&hB[(bn + g) * B_PADH + kb + 2 * t + 8];
                mma_f16(acc[0][ni], a[0], b0, b1);
                mma_f16(acc[1][ni], a[1], b0, b1);
            }
        }
        __syncthreads();
    }

#pragma unroll
    for (int mi = 0; mi < 2; mi++) {
#pragma unroll
        for (int ni = 0; ni < 8; ni++) {
            int mg = m0 + wm + mi * 16 + g;
            int c = wn + ni * 8 + 2 * t;
            if (mg < NN)
                *(float2*)&g_hpre[(size_t)mg * DD + c] =
                    make_float2(acc[mi][ni][0], acc[mi][ni][1]);
            if (mg + 8 < NN)
                *(float2*)&g_hpre[(size_t)(mg + 8) * DD + c] =
                    make_float2(acc[mi][ni][2], acc[mi][ni][3]);
        }
    }
}

// ---------------- epi1: hpre += bias1 + mask*beW1 ; BN1 stats -------------
#define EPI1_BLOCKS 1184
__global__ __launch_bounds__(256) void epi1_k() {
    __shared__ __align__(16) float sBe[RR * DD];
    __shared__ float sBias[DD];
    __shared__ float sRed[2][DD];
    int tid = threadIdx.x;
    int wid = tid >> 5;
    int lane = tid & 31;
    int c4 = lane << 2;
    for (int i = tid; i < RR * DD; i += 256) sBe[i] = g_beWlin1[i];
    if (tid < DD) { sBias[tid] = g_bias1[tid]; sRed[0][tid] = 0.f; sRed[1][tid] = 0.f; }
    __syncthreads();

    float s1[4] = {0.f, 0.f, 0.f, 0.f};
    float s2[4] = {0.f, 0.f, 0.f, 0.f};

    for (int m = blockIdx.x * 8 + wid; m < NN; m += EPI1_BLOCKS * 8) {
        int cbit = (lane < RR) ? (g_cnt[lane * NN + m] > 0) : 0;
        unsigned mask8 = __ballot_sync(0xffffffffu, cbit) & 0xFFu;

        float4 v = *(float4*)&g_hpre[(size_t)m * DD + c4];
        v.x += sBias[c4 + 0]; v.y += sBias[c4 + 1];
        v.z += sBias[c4 + 2]; v.w += sBias[c4 + 3];
#pragma unroll
        for (int r = 0; r < RR; r++) {
            if ((mask8 >> r) & 1u) {
                float4 be = *(float4*)&sBe[r * DD + c4];
                v.x += be.x; v.y += be.y; v.z += be.z; v.w += be.w;
            }
        }
        *(float4*)&g_hpre[(size_t)m * DD + c4] = v;
        s1[0] += v.x; s1[1] += v.y; s1[2] += v.z; s1[3] += v.w;
        s2[0] += v.x * v.x; s2[1] += v.y * v.y;
        s2[2] += v.z * v.z; s2[3] += v.w * v.w;
    }

#pragma unroll
    for (int i = 0; i < 4; i++) {
        atomicAdd(&sRed[0][c4 + i], s1[i]);
        atomicAdd(&sRed[1][c4 + i], s2[i]);
    }
    __syncthreads();
    if (tid < DD) {
        atomicAdd(&g_s1a[tid], (double)sRed[0][tid]);
        atomicAdd(&g_s2a[tid], (double)sRed[1][tid]);
    }
}

// ---------------- BN finalize (float consts for consumers) ----------------
__global__ void bnfin_k(int sel, float nrows, const float* __restrict__ g,
                        const float* __restrict__ b) {
    int d = threadIdx.x;
    double s1 = sel ? g_s1b[d] : g_s1a[d];
    double s2 = sel ? g_s2b[d] : g_s2a[d];
    double m = s1 / (double)nrows;
    double var = s2 / (double)nrows - m * m;
    float sc = g[d] * rsqrtf((float)var + 1e-5f);
    float sh = b[d] - (float)m * sc;
    if (sel) { g_sc2[d] = sc; g_sh2[d] = sh; }
    else     { g_sc1[d] = sc; g_sh1[d] = sh; }
}

// ---------------- bnrelu_hh: g_hh = half(relu(bn1(hpre))) -----------------
__global__ __launch_bounds__(256) void bnrelu_hh_k() {
    int i = blockIdx.x * 256 + threadIdx.x;
    if (i >= NN * 32) return;
    int c = (i & 31) << 2;
    float4 v = ((const float4*)g_hpre)[i];
    v.x = fmaxf(0.f, v.x * g_sc1[c + 0] + g_sh1[c + 0]);
    v.y = fmaxf(0.f, v.y * g_sc1[c + 1] + g_sh1[c + 1]);
    v.z = fmaxf(0.f, v.z * g_sc1[c + 2] + g_sh1[c + 2]);
    v.w = fmaxf(0.f, v.w * g_sc1[c + 3] + g_sh1[c + 3]);
    __half2* dst = (__half2*)g_hh + (size_t)i * 2;
    dst[0] = __floats2half2_rn(v.x, v.y);
    dst[1] = __floats2half2_rn(v.z, v.w);
}

// ---------------- mma1: fp16, A = g_hh, B = B2t[sel] ----------------------
#define NCH_M1 4
__global__ void __launch_bounds__(256, 2) mma1_k() {
    extern __shared__ char smc[];
    int tid = threadIdx.x;
    int m0 = blockIdx.x * 128;
    int rsel = blockIdx.y;

    float* dst = rsel ? g_hs : g_hW2;
    const float* bias = rsel ? g_bias2 : nullptr;
    const __half* Bt = g_B2t + (size_t)rsel * DD * DD;

    uint32_t sb = smem_u32(smc);

    auto load_stage = [&](int s, int kc) {
        const __half* Asrc = g_hh + kc * 32;
#pragma unroll
        for (int j = 0; j < 2; j++) {
            int p = tid + j * 256;
            int row = p >> 2;
            int kq = (p & 3) * 8;
            uint32_t doff = sb + s * STG_BYTES + row * (A_PADH * 2) + kq * 2;
            int m = m0 + row;
            if (m < NN) cpa16(doff, Asrc + (size_t)m * DD + kq);
            else {
                float4 z = make_float4(0.f, 0.f, 0.f, 0.f);
                *(float4*)(smc + s * STG_BYTES + row * (A_PADH * 2) + kq * 2) = z;
            }
        }
        const __half* Bsrc = Bt + kc * 32;
#pragma unroll
        for (int j = 0; j < 2; j++) {
            int p = tid + j * 256;
            int n = p >> 2;
            int kq = (p & 3) * 8;
            uint32_t doff = sb + s * STG_BYTES + A_BYTES + n * (B_PADH * 2) + kq * 2;
            cpa16(doff, Bsrc + (size_t)n * DD + kq);
        }
        asm volatile("cp.async.commit_group;" ::: "memory");
    };

    int wid = tid >> 5, lane = tid & 31;
    int g = lane >> 2, t = lane & 3;
    int wm = (wid & 3) * 32, wn = (wid >> 2) * 64;

    float acc[2][8][4];
#pragma unroll
    for (int mi = 0; mi < 2; mi++)
#pragma unroll
        for (int ni = 0; ni < 8; ni++) {
            acc[mi][ni][0] = 0.f; acc[mi][ni][1] = 0.f;
            acc[mi][ni][2] = 0.f; acc[mi][ni][3] = 0.f;
        }

    load_stage(0, 0);
    load_stage(1, 1);

    for (int kc = 0; kc < NCH_M1; kc++) {
        if (kc + 2 < NCH_M1) {
            load_stage((kc + 2) % 3, kc + 2);
            asm volatile("cp.async.wait_group 2;" ::: "memory");
        } else if (kc + 1 < NCH_M1) {
            asm volatile("cp.async.wait_group 1;" ::: "memory");
        } else {
            asm volatile("cp.async.wait_group 0;" ::: "memory");
        }
        __syncthreads();
        const __half* hA = (const __half*)(smc + (kc % 3) * STG_BYTES);
        const __half* hB = (const __half*)(smc + (kc % 3) * STG_BYTES + A_BYTES);
#pragma unroll
        for (int ks = 0; ks < 2; ks++) {
            int kb = ks * 16;
            uint32_t a[2][4];
#pragma unroll
            for (int mi = 0; mi < 2; mi++) {
                int bm = wm + mi * 16;
                a[mi][0] = *(const uint32_t*)&hA[(bm + g) * A_PADH + kb + 2 * t];
                a[mi][1] = *(const uint32_t*)&hA[(bm + g + 8) * A_PADH + kb + 2 * t];
                a[mi][2] = *(const uint32_t*)&hA[(bm + g) * A_PADH + kb + 2 * t + 8];
                a[mi][3] = *(const uint32_t*)&hA[(bm + g + 8) * A_PADH + kb + 2 * t + 8];
            }
#pragma unroll
            for (int ni = 0; ni < 8; ni++) {
                int bn = wn + ni * 8;
                uint32_t b0 = *(const uint32_t*)&hB[(bn + g) * B_PADH + kb + 2 * t];
                uint32_t b1 = *(const uint32_t*)&hB[(bn + g) * B_PADH + kb + 2 * t + 8];
                mma_f16(acc[0][ni], a[0], b0, b1);
                mma_f16(acc[1][ni], a[1], b0, b1);
            }
        }
        __syncthreads();
    }

#pragma unroll
    for (int mi = 0; mi < 2; mi++) {
#pragma unroll
        for (int ni = 0; ni < 8; ni++) {
            int mg = m0 + wm + mi * 16 + g;
            int c = wn + ni * 8 + 2 * t;
            float2 v0 = make_float2(acc[mi][ni][0], acc[mi][ni][1]);
            float2 v1 = make_float2(acc[mi][ni][2], acc[mi][ni][3]);
            if (bias) {
                float b0 = bias[c], b1 = bias[c + 1];
                v0.x += b0; v0.y += b1; v1.x += b0; v1.y += b1;
            }
            if (mg < NN) *(float2*)&dst[(size_t)mg * DD + c] = v0;
            if (mg + 8 < NN) *(float2*)&dst[(size_t)(mg + 8) * DD + c] = v1;
        }
    }
}

// ---------------- agg2: warp-per-node layer-2 assembly + BN2 stats --------
#define AGG2_BLOCKS 1184
__global__ __launch_bounds__(256) void agg2_k(float* __restrict__ out) {
    __shared__ __align__(16) float sW2[EDD * DD];
    __shared__ __align__(16) float sBe2[DD];
    __shared__ float sRed[2][DD];
    int tid = threadIdx.x;
    int wid = tid >> 5;
    int lane = tid & 31;
    int c4 = lane << 2;
    for (int i = tid; i < EDD * DD; i += 256) sW2[i] = g_WeWlin2[i];
    if (tid < DD) { sBe2[tid] = g_beWlin2[tid]; sRed[0][tid] = 0.f; sRed[1][tid] = 0.f; }
    __syncthreads();

    float s1[4] = {0.f, 0.f, 0.f, 0.f};
    float s2[4] = {0.f, 0.f, 0.f, 0.f};

    for (int no = blockIdx.x * 8 + wid; no < NN; no += AGG2_BLOCKS * 8) {
        float4 hsv = __ldg((const float4*)&g_hs[(size_t)no * DD + c4]);
#pragma unroll
        for (int r = 0; r < RR; r++) {
            int tr = r * NN + no;
            int cnt = g_cnt[tr];
            if (cnt == 0) {
                *(float4*)&out[(size_t)tr * DD + c4] = hsv;
                s1[0] += hsv.x; s1[1] += hsv.y; s1[2] += hsv.z; s1[3] += hsv.w;
                s2[0] += hsv.x * hsv.x; s2[1] += hsv.y * hsv.y;
                s2[2] += hsv.z * hsv.z; s2[3] += hsv.w * hsv.w;
                continue;
            }
            int off = g_off[tr];
            float4 acc = hsv;
            {
                float4 be = *(float4*)&sBe2[c4];
                acc.x += be.x; acc.y += be.y; acc.z += be.z; acc.w += be.w;
            }
            for (int j = 0; j < cnt; j++) {
                int4 cs = __ldg(&g_csr4[off + j]);
                float w = __int_as_float(cs.z);
                float4 hv = __ldg((const float4*)&g_hW2[(size_t)cs.x * DD + c4]);
                acc.x += w * hv.x; acc.y += w * hv.y;
                acc.z += w * hv.z; acc.w += w * hv.w;
            }

            float aef = __half2float(g_aggef[(size_t)tr * EDD + lane]);
            u64 a01 = pack2(acc.x, acc.y), a23 = pack2(acc.z, acc.w);
#pragma unroll
            for (int i = 0; i < EDD; i++) {
                float a = __shfl_sync(0xffffffffu, aef, i);
                u64 ad = dup2(a);
                const u64* wp = (const u64*)&sW2[i * DD + c4];
                fma2(a01, ad, wp[0]);
                fma2(a23, ad, wp[1]);
            }
            unpack2(a01, acc.x, acc.y);
            unpack2(a23, acc.z, acc.w);

            *(float4*)&out[(size_t)tr * DD + c4] = acc;
            s1[0] += acc.x; s1[1] += acc.y; s1[2] += acc.z; s1[3] += acc.w;
            s2[0] += acc.x * acc.x; s2[1] += acc.y * acc.y;
            s2[2] += acc.z * acc.z; s2[3] += acc.w * acc.w;
        }
    }

#pragma unroll
    for (int i = 0; i < 4; i++) {
        atomicAdd(&sRed[0][c4 + i], s1[i]);
        atomicAdd(&sRed[1][c4 + i], s2[i]);
    }
    __syncthreads();
    if (tid < DD) {
        atomicAdd(&g_s1b[tid], (double)sRed[0][tid]);
        atomicAdd(&g_s2b[tid], (double)sRed[1][tid]);
    }
}

// ---------------- bnrelu_o: apply BN2 (float consts) ----------------------
__global__ __launch_bounds__(256) void bnrelu_o_k(float* __restrict__ out) {
    int i = blockIdx.x * 256 + threadIdx.x;
    if (i >= M2 * 32) return;
    int c = (i & 31) << 2;
    float4 v = ((const float4*)out)[i];
    v.x = fmaxf(0.f, v.x * g_sc2[c + 0] + g_sh2[c + 0]);
    v.y = fmaxf(0.f, v.y * g_sc2[c + 1] + g_sh2[c + 1]);
    v.z = fmaxf(0.f, v.z * g_sc2[c + 2] + g_sh2[c + 2]);
    v.w = fmaxf(0.f, v.w * g_sc2[c + 3] + g_sh2[c + 3]);
    ((float4*)out)[i] = v;
}

// ---------------- launch ----------------
extern "C" void kernel_launch(void* const* d_in, const int* in_sizes, int n_in,
                              void* d_out, int out_size) {
    (void)in_sizes; (void)n_in; (void)out_size;
    const float* x        = (const float*)d_in[0];
    const int*   node_in  = (const int*)d_in[1];
    const int*   node_out = (const int*)d_in[2];
    const int*   relation = (const int*)d_in[3];
    const float* ew       = (const float*)d_in[4];
    const float* ef       = (const float*)d_in[5];
    const float* l1_Wlin  = (const float*)d_in[6];
    const float* l1_blin  = (const float*)d_in[7];
    const float* l1_Wself = (const float*)d_in[8];
    const float* l1_bself = (const float*)d_in[9];
    const float* l1_Wedge = (const float*)d_in[10];
    const float* l1_bedge = (const float*)d_in[11];
    const float* l1_g     = (const float*)d_in[12];
    const float* l1_b     = (const float*)d_in[13];
    const float* l2_Wlin  = (const float*)d_in[14];
    const float* l2_blin  = (const float*)d_in[15];
    const float* l2_Wself = (const float*)d_in[16];
    const float* l2_bself = (const float*)d_in[17];
    const float* l2_Wedge = (const float*)d_in[18];
    const float* l2_bedge = (const float*)d_in[19];
    const float* l2_g     = (const float*)d_in[20];
    const float* l2_b     = (const float*)d_in[21];
    float* out = (float*)d_out;

    int gmm = (NN + 127) / 128;   // 391
    int nsb = (NR + SCAN_BLK - 1) / SCAN_BLK;  // 391

    static int configured = 0;
    if (!configured) {
        cudaFuncSetAttribute(mma_L1_k, cudaFuncAttributeMaxDynamicSharedMemorySize,
                             MMAL1_SMEM);
        cudaFuncSetAttribute(mma1_k, cudaFuncAttributeMaxDynamicSharedMemorySize,
                             MMAL1_SMEM);
        configured = 1;
    }

    zero_k<<<512, 256>>>();
    xhalf_k<<<(NN * 32 + 255) / 256, 256>>>(x);
    prep_k<<<RR + 1, 128>>>(l1_Wedge, l1_Wlin, l1_bedge, l1_blin, l1_bself,
                            l2_Wedge, l2_Wlin, l2_bedge, l2_blin, l2_bself);
    prepBt_k<<<DD, 128>>>(l1_Wlin, l1_Wself);
    prepBt2_k<<<2 * DD, 128>>>(l2_Wlin, l2_Wself);
    deg_k<<<EE / 256, 256>>>(node_out, relation, ew);
    scan1_k<<<nsb, 1024>>>();
    scan2_k<<<1, 512>>>();
    scan3_k<<<nsb, 1024>>>();
    place_k<<<EE / 256, 256>>>(node_in, node_out, relation, ew);
    agg1x_k<<<NR / 8, 256>>>(x, ef);
    mma_L1_k<<<gmm, 256, MMAL1_SMEM>>>();
    epi1_k<<<EPI1_BLOCKS, 256>>>();
    bnfin_k<<<1, 128>>>(0, (float)NN, l1_g, l1_b);
    bnrelu_hh_k<<<(NN * 32 + 255) / 256, 256>>>();
    mma1_k<<<dim3(gmm, 2), 256, MMAL1_SMEM>>>();
    agg2_k<<<AGG2_BLOCKS, 256>>>(out);
    bnfin_k<<<1, 128>>>(1, (float)M2, l2_g, l2_b);
    bnrelu_o_k<<<(M2 * 32) / 256, 256>>>(out);
}

// round 16
// speedup vs baseline: 1.4136x; 1.0322x over previous
#include <cuda_runtime.h>
#include <cuda_fp16.h>
#include <cstdint>

#define NN 50000
#define DD 128
#define RR 8
#define EE 800000
#define EDD 32
#define NR (NN*RR)
#define M2 (RR*NN)
#define K1 1408

typedef unsigned long long u64;

// ---------------- scratch ----------------
__device__ float  g_deg[NR];                 // indexed by tr = r*NN + no
__device__ __half g_aggef[NR*EDD];           // [r][no][32]
__device__ __half g_aggx[(size_t)NR*DD];     // [r][no][128]
__device__ __half g_xh[(size_t)NN*DD];       // x in half
__device__ __half g_hh[(size_t)NN*DD];       // relu(bn1(hpre)) in half
__device__ __half g_B1t[(size_t)DD*K1];      // [n][k] fused B1 transposed, half
__device__ __half g_B2t[(size_t)2*DD*DD];    // [sel][n][k]: Wlin2, Wself2
__device__ float  g_hpre[NN*DD];
__device__ float  g_hW2[NN*DD];
__device__ float  g_hs[NN*DD];
__device__ float  g_WeWlin1[RR*EDD*DD];
__device__ float  g_WeWlin2[EDD*DD];
__device__ float  g_beWlin1[RR*DD];
__device__ float  g_beWlin2[DD];
__device__ float  g_bias1[DD];
__device__ float  g_bias2[DD];
__device__ double g_s1a[DD], g_s2a[DD], g_s1b[DD], g_s2b[DD];
__device__ float  g_sc1[DD], g_sh1[DD], g_sc2[DD], g_sh2[DD];
// CSR by tr (packed)
__device__ int   g_cnt[NR];
__device__ int   g_off[NR];
__device__ int   g_cur[NR];
__device__ int   g_bsum[512];
__device__ int4  g_csr4[EE];                 // {nin, eid, ew_bits, 0}

// ---------------- helpers ----------------
__device__ __forceinline__ uint32_t smem_u32(const void* p) {
    uint32_t a;
    asm("{ .reg .u64 t; cvta.to.shared.u64 t, %1; cvt.u32.u64 %0, t; }" : "=r"(a) : "l"(p));
    return a;
}
__device__ __forceinline__ u64 pack2(float lo, float hi) {
    u64 r; asm("mov.b64 %0, {%1, %2};" : "=l"(r) : "f"(lo), "f"(hi)); return r;
}
__device__ __forceinline__ u64 dup2(float v) {
    u64 r; asm("mov.b64 %0, {%1, %1};" : "=l"(r) : "f"(v)); return r;
}
__device__ __forceinline__ void unpack2(u64 v, float& lo, float& hi) {
    asm("mov.b64 {%0, %1}, %2;" : "=f"(lo), "=f"(hi) : "l"(v));
}
__device__ __forceinline__ void fma2(u64& d, u64 a, u64 b) {
    asm("fma.rn.f32x2 %0, %1, %2, %0;" : "+l"(d) : "l"(a), "l"(b));
}
__device__ __forceinline__ void mma_f16(float* d, const uint32_t* a,
                                        uint32_t b0, uint32_t b1) {
    asm volatile(
        "mma.sync.aligned.m16n8k16.row.col.f32.f16.f16.f32 "
        "{%0,%1,%2,%3}, {%4,%5,%6,%7}, {%8,%9}, {%0,%1,%2,%3};"
        : "+f"(d[0]), "+f"(d[1]), "+f"(d[2]), "+f"(d[3])
        : "r"(a[0]), "r"(a[1]), "r"(a[2]), "r"(a[3]), "r"(b0), "r"(b1));
}
__device__ __forceinline__ void cpa16(uint32_t d, const void* s) {
    asm volatile("cp.async.ca.shared.global [%0], [%1], 16;" :: "r"(d), "l"(s) : "memory");
}

// ---------------- init: zero small buffers + x->half ----------------
__global__ __launch_bounds__(256) void init_k(const float* __restrict__ x) {
    size_t i = (size_t)blockIdx.x * blockDim.x + threadIdx.x;
    size_t stride = (size_t)gridDim.x * blockDim.x;
    float4 z = make_float4(0.f, 0.f, 0.f, 0.f);
    float4* d = (float4*)g_deg;
    for (size_t j = i; j < (size_t)NR / 4; j += stride) d[j] = z;
    int4* c = (int4*)g_cnt;
    int4 zi = make_int4(0, 0, 0, 0);
    for (size_t j = i; j < (size_t)NR / 4; j += stride) c[j] = zi;
    for (size_t j = i; j < (size_t)NN * 32; j += stride) {
        float4 v = ((const float4*)x)[j];
        __half2* dst = (__half2*)g_xh + j * 2;
        dst[0] = __floats2half2_rn(v.x, v.y);
        dst[1] = __floats2half2_rn(v.z, v.w);
    }
    if (i < DD) { g_s1a[i] = 0.0; g_s2a[i] = 0.0; g_s1b[i] = 0.0; g_s2b[i] = 0.0; }
}

// ---------------- prep: folds ----------------
__global__ __launch_bounds__(128) void prep_k(
    const float* __restrict__ l1_We, const float* __restrict__ l1_Wlin,
    const float* __restrict__ l1_be, const float* __restrict__ l1_blin,
    const float* __restrict__ l1_bself,
    const float* __restrict__ l2_We, const float* __restrict__ l2_Wlin,
    const float* __restrict__ l2_be, const float* __restrict__ l2_blin,
    const float* __restrict__ l2_bself)
{
    __shared__ float sWe[EDD * DD];
    __shared__ float sbe[DD];
    int r = blockIdx.x;
    int d = threadIdx.x;
    const float* We = (r < RR) ? l1_We : l2_We;
    const float* Wl = (r < RR) ? l1_Wlin : l2_Wlin;
    const float* be = (r < RR) ? l1_be : l2_be;
    for (int i = d; i < EDD * DD; i += 128) sWe[i] = We[i];
    sbe[d] = be[d];
    __syncthreads();
    float acc[EDD];
#pragma unroll
    for (int i = 0; i < EDD; i++) acc[i] = 0.f;
    float accb = 0.f;
    int rowoff = (r < RR) ? r * DD : 0;
    for (int k = 0; k < DD; k++) {
        float wl = Wl[(size_t)(rowoff + k) * DD + d];
        accb += sbe[k] * wl;
#pragma unroll
        for (int i = 0; i < EDD; i++) acc[i] += sWe[i * DD + k] * wl;
    }
    if (r < RR) {
#pragma unroll
        for (int i = 0; i < EDD; i++) g_WeWlin1[(size_t)(r * EDD + i) * DD + d] = acc[i];
        g_beWlin1[r * DD + d] = accb;
    } else {
#pragma unroll
        for (int i = 0; i < EDD; i++) g_WeWlin2[(size_t)i * DD + d] = acc[i];
        g_beWlin2[d] = accb;
        g_bias1[d] = l1_blin[d] + l1_bself[d];
        g_bias2[d] = l2_blin[d] + l2_bself[d];
    }
}

// ---------------- prepBt: tiled transpose -> B1t[n][k] half ----------------
// grid (44, 4), block (32, 8): tile 32k x 32n
__global__ __launch_bounds__(256) void prepBt_k(const float* __restrict__ Wlin1,
                                                const float* __restrict__ Wself1) {
    __shared__ float tile[32][33];
    int k0 = blockIdx.x * 32;
    int n0 = blockIdx.y * 32;
    int tx = threadIdx.x;        // 0..31
    int ty = threadIdx.y;        // 0..7
#pragma unroll
    for (int i = 0; i < 4; i++) {
        int k = k0 + ty + i * 8;
        int n = n0 + tx;
        float v;
        if (k < 1024)      v = Wlin1[(size_t)k * DD + n];
        else if (k < 1280) v = g_WeWlin1[(size_t)(k - 1024) * DD + n];
        else               v = Wself1[(size_t)(k - 1280) * DD + n];
        tile[ty + i * 8][tx] = v;
    }
    __syncthreads();
#pragma unroll
    for (int i = 0; i < 4; i++) {
        int n = n0 + ty + i * 8;
        int k = k0 + tx;
        g_B1t[(size_t)n * K1 + k] = __float2half_rn(tile[tx][ty + i * 8]);
    }
}

// ---------------- prepBt2: B2t[sel][n][k] half (Wlin2 / Wself2) -----------
__global__ __launch_bounds__(256) void prepBt2_k(const float* __restrict__ Wlin2,
                                                 const float* __restrict__ Wself2) {
    __shared__ float tile[32][33];
    int k0 = (blockIdx.x & 3) * 32;
    int n0 = blockIdx.y * 32;
    int sel = blockIdx.x >> 2;
    const float* W = sel ? Wself2 : Wlin2;
    int tx = threadIdx.x;
    int ty = threadIdx.y;
#pragma unroll
    for (int i = 0; i < 4; i++)
        tile[ty + i * 8][tx] = W[(size_t)(k0 + ty + i * 8) * DD + n0 + tx];
    __syncthreads();
#pragma unroll
    for (int i = 0; i < 4; i++) {
        int n = n0 + ty + i * 8;
        int k = k0 + tx;
        g_B2t[(size_t)sel * DD * DD + (size_t)n * DD + k] =
            __float2half_rn(tile[tx][ty + i * 8]);
    }
}

// ---------------- degree + histogram (by tr) ----------------
__global__ void deg_k(const int* __restrict__ nout, const int* __restrict__ rel,
                      const float* __restrict__ w) {
    int e = blockIdx.x * blockDim.x + threadIdx.x;
    if (e < EE) {
        int tr = rel[e] * NN + nout[e];
        atomicAdd(&g_deg[tr], w[e]);
        atomicAdd(&g_cnt[tr], 1);
    }
}

// ---------------- scan (exclusive prefix over g_cnt) ----------------
#define SCAN_BLK 1024
__global__ __launch_bounds__(1024) void scan1_k() {
    __shared__ int sh[SCAN_BLK];
    int t = threadIdx.x;
    int i = blockIdx.x * SCAN_BLK + t;
    sh[t] = (i < NR) ? g_cnt[i] : 0;
    __syncthreads();
    for (int s = 512; s > 0; s >>= 1) {
        if (t < s) sh[t] += sh[t + s];
        __syncthreads();
    }
    if (t == 0) g_bsum[blockIdx.x] = sh[0];
}
__global__ __launch_bounds__(512) void scan2_k() {
    __shared__ int sh[512];
    int t = threadIdx.x;
    int nb = (NR + SCAN_BLK - 1) / SCAN_BLK;
    int orig = (t < nb) ? g_bsum[t] : 0;
    sh[t] = orig;
    __syncthreads();
    for (int d = 1; d < 512; d <<= 1) {
        int x = (t >= d) ? sh[t - d] : 0;
        __syncthreads();
        sh[t] += x;
        __syncthreads();
    }
    if (t < nb) g_bsum[t] = sh[t] - orig;
}
__global__ __launch_bounds__(1024) void scan3_k() {
    __shared__ int sh[SCAN_BLK];
    int t = threadIdx.x;
    int i = blockIdx.x * SCAN_BLK + t;
    int orig = (i < NR) ? g_cnt[i] : 0;
    sh[t] = orig;
    __syncthreads();
    for (int d = 1; d < SCAN_BLK; d <<= 1) {
        int x = (t >= d) ? sh[t - d] : 0;
        __syncthreads();
        sh[t] += x;
        __syncthreads();
    }
    if (i < NR) {
        int excl = sh[t] - orig + g_bsum[blockIdx.x];
        g_off[i] = excl;
        g_cur[i] = excl;
    }
}
__global__ void place_k(const int* __restrict__ nin, const int* __restrict__ nout,
                        const int* __restrict__ rel, const float* __restrict__ w) {
    int e = blockIdx.x * blockDim.x + threadIdx.x;
    if (e < EE) {
        int tr = rel[e] * NN + nout[e];
        int pos = atomicAdd(&g_cur[tr], 1);
        g_csr4[pos] = make_int4(nin[e], e, __float_as_int(w[e] / g_deg[tr]), 0);
    }
}

// ---------------- agg1x: warp-per-tr CSR gather (g_xh half, ILP-2) --------
__global__ __launch_bounds__(256) void agg1x_k(const float* __restrict__ ef) {
    int tid = threadIdx.x;
    int wid = tid >> 5;
    int lane = tid & 31;
    int c4 = lane << 2;
    int tr = blockIdx.x * 8 + wid;
    if (tr >= NR) return;

    int off = g_off[tr];
    int cnt = g_cnt[tr];
    float4 xa = make_float4(0.f, 0.f, 0.f, 0.f);
    float4 xb = make_float4(0.f, 0.f, 0.f, 0.f);
    float ea = 0.f, eb = 0.f;
    int j = 0;
    for (; j + 2 <= cnt; j += 2) {
        int4 c0 = __ldg(&g_csr4[off + j]);
        int4 c1 = __ldg(&g_csr4[off + j + 1]);
        float w0 = __int_as_float(c0.z), w1 = __int_as_float(c1.z);
        uint2 r0 = __ldg((const uint2*)&g_xh[(size_t)c0.x * DD + c4]);
        uint2 r1 = __ldg((const uint2*)&g_xh[(size_t)c1.x * DD + c4]);
        float f0 = __ldg(&ef[(size_t)c0.y * EDD + lane]);
        float f1 = __ldg(&ef[(size_t)c1.y * EDD + lane]);
        float2 p00 = __half22float2(*(__half2*)&r0.x);
        float2 p01 = __half22float2(*(__half2*)&r0.y);
        float2 p10 = __half22float2(*(__half2*)&r1.x);
        float2 p11 = __half22float2(*(__half2*)&r1.y);
        xa.x += w0 * p00.x; xa.y += w0 * p00.y;
        xa.z += w0 * p01.x; xa.w += w0 * p01.y;
        xb.x += w1 * p10.x; xb.y += w1 * p10.y;
        xb.z += w1 * p11.x; xb.w += w1 * p11.y;
        ea += w0 * f0; eb += w1 * f1;
    }
    if (j < cnt) {
        int4 c0 = __ldg(&g_csr4[off + j]);
        float w0 = __int_as_float(c0.z);
        uint2 r0 = __ldg((const uint2*)&g_xh[(size_t)c0.x * DD + c4]);
        float2 p00 = __half22float2(*(__half2*)&r0.x);
        float2 p01 = __half22float2(*(__half2*)&r0.y);
        xa.x += w0 * p00.x; xa.y += w0 * p00.y;
        xa.z += w0 * p01.x; xa.w += w0 * p01.y;
        ea += w0 * __ldg(&ef[(size_t)c0.y * EDD + lane]);
    }
    xa.x += xb.x; xa.y += xb.y; xa.z += xb.z; xa.w += xb.w;
    __half2* dst = (__half2*)&g_aggx[(size_t)tr * DD + c4];
    dst[0] = __floats2half2_rn(xa.x, xa.y);
    dst[1] = __floats2half2_rn(xa.z, xa.w);
    g_aggef[(size_t)tr * EDD + lane] = __float2half_rn(ea + eb);
}

// ---------------- mma_L1: hpre = [aggx|aggef|x] @ B1t, fp16 m16n8k16 -----
#define A_PADH 40
#define B_PADH 40
#define A_BYTES (128 * A_PADH * 2)
#define BH_BYTES (128 * B_PADH * 2)
#define STG_BYTES (A_BYTES + BH_BYTES)
#define MMAL1_SMEM (3 * STG_BYTES)
#define NCH_L1 44

__global__ void __launch_bounds__(256, 2) mma_L1_k() {
    extern __shared__ char smc[];
    int tid = threadIdx.x;
    int m0 = blockIdx.x * 128;
    uint32_t sb = smem_u32(smc);

    auto load_stage = [&](int s, int kc) {
        const __half* Asrc;
        int astride;
        if (kc < 32) {
            int r = kc >> 2;
            Asrc = g_aggx + (size_t)r * NN * DD + (kc & 3) * 32;
            astride = DD;
        } else if (kc < 40) {
            int r = kc - 32;
            Asrc = g_aggef + (size_t)r * NN * EDD;
            astride = EDD;
        } else {
            Asrc = g_xh + (kc - 40) * 32;
            astride = DD;
        }
#pragma unroll
        for (int j = 0; j < 2; j++) {
            int p = tid + j * 256;
            int row = p >> 2;
            int kq = (p & 3) * 8;
            uint32_t doff = sb + s * STG_BYTES + row * (A_PADH * 2) + kq * 2;
            int m = m0 + row;
            if (m < NN) cpa16(doff, Asrc + (size_t)m * astride + kq);
            else {
                float4 z = make_float4(0.f, 0.f, 0.f, 0.f);
                *(float4*)(smc + s * STG_BYTES + row * (A_PADH * 2) + kq * 2) = z;
            }
        }
        const __half* Bsrc = g_B1t + (size_t)kc * 32;
#pragma unroll
        for (int j = 0; j < 2; j++) {
            int p = tid + j * 256;
            int n = p >> 2;
            int kq = (p & 3) * 8;
            uint32_t doff = sb + s * STG_BYTES + A_BYTES + n * (B_PADH * 2) + kq * 2;
            cpa16(doff, Bsrc + (size_t)n * K1 + kq);
        }
        asm volatile("cp.async.commit_group;" ::: "memory");
    };

    int wid = tid >> 5, lane = tid & 31;
    int g = lane >> 2, t = lane & 3;
    int wm = (wid & 3) * 32, wn = (wid >> 2) * 64;

    float acc[2][8][4];
#pragma unroll
    for (int mi = 0; mi < 2; mi++)
#pragma unroll
        for (int ni = 0; ni < 8; ni++) {
            acc[mi][ni][0] = 0.f; acc[mi][ni][1] = 0.f;
            acc[mi][ni][2] = 0.f; acc[mi][ni][3] = 0.f;
        }

    load_stage(0, 0);
    load_stage(1, 1);

    for (int kc = 0; kc < NCH_L1; kc++) {
        if (kc + 2 < NCH_L1) {
            load_stage((kc + 2) % 3, kc + 2);
            asm volatile("cp.async.wait_group 2;" ::: "memory");
        } else if (kc + 1 < NCH_L1) {
            asm volatile("cp.async.wait_group 1;" ::: "memory");
        } else {
            asm volatile("cp.async.wait_group 0;" ::: "memory");
        }
        __syncthreads();
        const __half* hA = (const __half*)(smc + (kc % 3) * STG_BYTES);
        const __half* hB = (const __half*)(smc + (kc % 3) * STG_BYTES + A_BYTES);
#pragma unroll
        for (int ks = 0; ks < 2; ks++) {
            int kb = ks * 16;
            uint32_t a[2][4];
#pragma unroll
            for (int mi = 0; mi < 2; mi++) {
                int bm = wm + mi * 16;
                a[mi][0] = *(const uint32_t*)&hA[(bm + g) * A_PADH + kb + 2 * t];
                a[mi][1] = *(const uint32_t*)&hA[(bm + g + 8) * A_PADH + kb + 2 * t];
                a[mi][2] = *(const uint32_t*)&hA[(bm + g) * A_PADH + kb + 2 * t + 8];
                a[mi][3] = *(const uint32_t*)&hA[(bm + g + 8) * A_PADH + kb + 2 * t + 8];
            }
#pragma unroll
            for (int ni = 0; ni < 8; ni++) {
                int bn = wn + ni * 8;
                uint32_t b0 = *(const uint32_t*)&hB[(bn + g) * B_PADH + kb + 2 * t];
                uint32_t b1 = *(const uint32_t*)&hB[(bn + g) * B_PADH + kb + 2 * t + 8];
                mma_f16(acc[0][ni], a[0], b0, b1);
                mma_f16(acc[1][ni], a[1], b0, b1);
            }
        }
        __syncthreads();
    }

#pragma unroll
    for (int mi = 0; mi < 2; mi++) {
#pragma unroll
        for (int ni = 0; ni < 8; ni++) {
            int mg = m0 + wm + mi * 16 + g;
            int c = wn + ni * 8 + 2 * t;
            if (mg < NN)
                *(float2*)&g_hpre[(size_t)mg * DD + c] =
                    make_float2(acc[mi][ni][0], acc[mi][ni][1]);
            if (mg + 8 < NN)
                *(float2*)&g_hpre[(size_t)(mg + 8) * DD + c] =
                    make_float2(acc[mi][ni][2], acc[mi][ni][3]);
        }
    }
}

// ---------------- epi1: hpre += bias1 + mask*beW1 ; BN1 stats -------------
#define EPI1_BLOCKS 1184
__global__ __launch_bounds__(256) void epi1_k() {
    __shared__ __align__(16) float sBe[RR * DD];
    __shared__ float sBias[DD];
    __shared__ float sRed[2][DD];
    int tid = threadIdx.x;
    int wid = tid >> 5;
    int lane = tid & 31;
    int c4 = lane << 2;
    for (int i = tid; i < RR * DD; i += 256) sBe[i] = g_beWlin1[i];
    if (tid < DD) { sBias[tid] = g_bias1[tid]; sRed[0][tid] = 0.f; sRed[1][tid] = 0.f; }
    __syncthreads();

    float s1[4] = {0.f, 0.f, 0.f, 0.f};
    float s2[4] = {0.f, 0.f, 0.f, 0.f};

    for (int m = blockIdx.x * 8 + wid; m < NN; m += EPI1_BLOCKS * 8) {
        int cbit = (lane < RR) ? (g_cnt[lane * NN + m] > 0) : 0;
        unsigned mask8 = __ballot_sync(0xffffffffu, cbit) & 0xFFu;

        float4 v = *(float4*)&g_hpre[(size_t)m * DD + c4];
        v.x += sBias[c4 + 0]; v.y += sBias[c4 + 1];
        v.z += sBias[c4 + 2]; v.w += sBias[c4 + 3];
#pragma unroll
        for (int r = 0; r < RR; r++) {
            if ((mask8 >> r) & 1u) {
                float4 be = *(float4*)&sBe[r * DD + c4];
                v.x += be.x; v.y += be.y; v.z += be.z; v.w += be.w;
            }
        }
        *(float4*)&g_hpre[(size_t)m * DD + c4] = v;
        s1[0] += v.x; s1[1] += v.y; s1[2] += v.z; s1[3] += v.w;
        s2[0] += v.x * v.x; s2[1] += v.y * v.y;
        s2[2] += v.z * v.z; s2[3] += v.w * v.w;
    }

#pragma unroll
    for (int i = 0; i < 4; i++) {
        atomicAdd(&sRed[0][c4 + i], s1[i]);
        atomicAdd(&sRed[1][c4 + i], s2[i]);
    }
    __syncthreads();
    if (tid < DD) {
        atomicAdd(&g_s1a[tid], (double)sRed[0][tid]);
        atomicAdd(&g_s2a[tid], (double)sRed[1][tid]);
    }
}

// ---------------- BN finalize (float consts for consumers) ----------------
__global__ void bnfin_k(int sel, float nrows, const float* __restrict__ g,
                        const float* __restrict__ b) {
    int d = threadIdx.x;
    double s1 = sel ? g_s1b[d] : g_s1a[d];
    double s2 = sel ? g_s2b[d] : g_s2a[d];
    double m = s1 / (double)nrows;
    double var = s2 / (double)nrows - m * m;
    float sc = g[d] * rsqrtf((float)var + 1e-5f);
    float sh = b[d] - (float)m * sc;
    if (sel) { g_sc2[d] = sc; g_sh2[d] = sh; }
    else     { g_sc1[d] = sc; g_sh1[d] = sh; }
}

// ---------------- bnrelu_hh: g_hh = half(relu(bn1(hpre))) -----------------
__global__ __launch_bounds__(256) void bnrelu_hh_k() {
    int i = blockIdx.x * 256 + threadIdx.x;
    if (i >= NN * 32) return;
    int c = (i & 31) << 2;
    float4 v = ((const float4*)g_hpre)[i];
    v.x = fmaxf(0.f, v.x * g_sc1[c + 0] + g_sh1[c + 0]);
    v.y = fmaxf(0.f, v.y * g_sc1[c + 1] + g_sh1[c + 1]);
    v.z = fmaxf(0.f, v.z * g_sc1[c + 2] + g_sh1[c + 2]);
    v.w = fmaxf(0.f, v.w * g_sc1[c + 3] + g_sh1[c + 3]);
    __half2* dst = (__half2*)g_hh + (size_t)i * 2;
    dst[0] = __floats2half2_rn(v.x, v.y);
    dst[1] = __floats2half2_rn(v.z, v.w);
}

// ---------------- mma1: fp16, A = g_hh, B = B2t[sel] ----------------------
#define NCH_M1 4
__global__ void __launch_bounds__(256, 2) mma1_k() {
    extern __shared__ char smc[];
    int tid = threadIdx.x;
    int m0 = blockIdx.x * 128;
    int rsel = blockIdx.y;

    float* dst = rsel ? g_hs : g_hW2;
    const float* bias = rsel ? g_bias2 : nullptr;
    const __half* Bt = g_B2t + (size_t)rsel * DD * DD;

    uint32_t sb = smem_u32(smc);

    auto load_stage = [&](int s, int kc) {
        const __half* Asrc = g_hh + kc * 32;
#pragma unroll
        for (int j = 0; j < 2; j++) {
            int p = tid + j * 256;
            int row = p >> 2;
            int kq = (p & 3) * 8;
            uint32_t doff = sb + s * STG_BYTES + row * (A_PADH * 2) + kq * 2;
            int m = m0 + row;
            if (m < NN) cpa16(doff, Asrc + (size_t)m * DD + kq);
            else {
                float4 z = make_float4(0.f, 0.f, 0.f, 0.f);
                *(float4*)(smc + s * STG_BYTES + row * (A_PADH * 2) + kq * 2) = z;
            }
        }
        const __half* Bsrc = Bt + kc * 32;
#pragma unroll
        for (int j = 0; j < 2; j++) {
            int p = tid + j * 256;
            int n = p >> 2;
            int kq = (p & 3) * 8;
            uint32_t doff = sb + s * STG_BYTES + A_BYTES + n * (B_PADH * 2) + kq * 2;
            cpa16(doff, Bsrc + (size_t)n * DD + kq);
        }
        asm volatile("cp.async.commit_group;" ::: "memory");
    };

    int wid = tid >> 5, lane = tid & 31;
    int g = lane >> 2, t = lane & 3;
    int wm = (wid & 3) * 32, wn = (wid >> 2) * 64;

    float acc[2][8][4];
#pragma unroll
    for (int mi = 0; mi < 2; mi++)
#pragma unroll
        for (int ni = 0; ni < 8; ni++) {
            acc[mi][ni][0] = 0.f; acc[mi][ni][1] = 0.f;
            acc[mi][ni][2] = 0.f; acc[mi][ni][3] = 0.f;
        }

    load_stage(0, 0);
    load_stage(1, 1);

    for (int kc = 0; kc < NCH_M1; kc++) {
        if (kc + 2 < NCH_M1) {
            load_stage((kc + 2) % 3, kc + 2);
            asm volatile("cp.async.wait_group 2;" ::: "memory");
        } else if (kc + 1 < NCH_M1) {
            asm volatile("cp.async.wait_group 1;" ::: "memory");
        } else {
            asm volatile("cp.async.wait_group 0;" ::: "memory");
        }
        __syncthreads();
        const __half* hA = (const __half*)(smc + (kc % 3) * STG_BYTES);
        const __half* hB = (const __half*)(smc + (kc % 3) * STG_BYTES + A_BYTES);
#pragma unroll
        for (int ks = 0; ks < 2; ks++) {
            int kb = ks * 16;
            uint32_t a[2][4];
#pragma unroll
            for (int mi = 0; mi < 2; mi++) {
                int bm = wm + mi * 16;
                a[mi][0] = *(const uint32_t*)&hA[(bm + g) * A_PADH + kb + 2 * t];
                a[mi][1] = *(const uint32_t*)&hA[(bm + g + 8) * A_PADH + kb + 2 * t];
                a[mi][2] = *(const uint32_t*)&hA[(bm + g) * A_PADH + kb + 2 * t + 8];
                a[mi][3] = *(const uint32_t*)&hA[(bm + g + 8) * A_PADH + kb + 2 * t + 8];
            }
#pragma unroll
            for (int ni = 0; ni < 8; ni++) {
                int bn = wn + ni * 8;
                uint32_t b0 = *(const uint32_t*)&hB[(bn + g) * B_PADH + kb + 2 * t];
                uint32_t b1 = *(const uint32_t*)&hB[(bn + g) * B_PADH + kb + 2 * t + 8];
                mma_f16(acc[0][ni], a[0], b0, b1);
                mma_f16(acc[1][ni], a[1], b0, b1);
            }
        }
        __syncthreads();
    }

#pragma unroll
    for (int mi = 0; mi < 2; mi++) {
#pragma unroll
        for (int ni = 0; ni < 8; ni++) {
            int mg = m0 + wm + mi * 16 + g;
            int c = wn + ni * 8 + 2 * t;
            float2 v0 = make_float2(acc[mi][ni][0], acc[mi][ni][1]);
            float2 v1 = make_float2(acc[mi][ni][2], acc[mi][ni][3]);
            if (bias) {
                float b0 = bias[c], b1 = bias[c + 1];
                v0.x += b0; v0.y += b1; v1.x += b0; v1.y += b1;
            }
            if (mg < NN) *(float2*)&dst[(size_t)mg * DD + c] = v0;
            if (mg + 8 < NN) *(float2*)&dst[(size_t)(mg + 8) * DD + c] = v1;
        }
    }
}

// ---------------- agg2: warp-per-node layer-2 assembly + BN2 stats --------
#define AGG2_BLOCKS 1184
__global__ __launch_bounds__(256) void agg2_k(float* __restrict__ out) {
    __shared__ __align__(16) float sW2[EDD * DD];
    __shared__ __align__(16) float sBe2[DD];
    __shared__ float sRed[2][DD];
    int tid = threadIdx.x;
    int wid = tid >> 5;
    int lane = tid & 31;
    int c4 = lane << 2;
    for (int i = tid; i < EDD * DD; i += 256) sW2[i] = g_WeWlin2[i];
    if (tid < DD) { sBe2[tid] = g_beWlin2[tid]; sRed[0][tid] = 0.f; sRed[1][tid] = 0.f; }
    __syncthreads();

    float s1[4] = {0.f, 0.f, 0.f, 0.f};
    float s2[4] = {0.f, 0.f, 0.f, 0.f};

    for (int no = blockIdx.x * 8 + wid; no < NN; no += AGG2_BLOCKS * 8) {
        float4 hsv = __ldg((const float4*)&g_hs[(size_t)no * DD + c4]);
#pragma unroll
        for (int r = 0; r < RR; r++) {
            int tr = r * NN + no;
            int cnt = g_cnt[tr];
            if (cnt == 0) {
                *(float4*)&out[(size_t)tr * DD + c4] = hsv;
                s1[0] += hsv.x; s1[1] += hsv.y; s1[2] += hsv.z; s1[3] += hsv.w;
                s2[0] += hsv.x * hsv.x; s2[1] += hsv.y * hsv.y;
                s2[2] += hsv.z * hsv.z; s2[3] += hsv.w * hsv.w;
                continue;
            }
            int off = g_off[tr];
            float4 acc = hsv;
            {
                float4 be = *(float4*)&sBe2[c4];
                acc.x += be.x; acc.y += be.y; acc.z += be.z; acc.w += be.w;
            }
            for (int j = 0; j < cnt; j++) {
                int4 cs = __ldg(&g_csr4[off + j]);
                float w = __int_as_float(cs.z);
                float4 hv = __ldg((const float4*)&g_hW2[(size_t)cs.x * DD + c4]);
                acc.x += w * hv.x; acc.y += w * hv.y;
                acc.z += w * hv.z; acc.w += w * hv.w;
            }

            float aef = __half2float(g_aggef[(size_t)tr * EDD + lane]);
            u64 a01 = pack2(acc.x, acc.y), a23 = pack2(acc.z, acc.w);
#pragma unroll
            for (int i = 0; i < EDD; i++) {
                float a = __shfl_sync(0xffffffffu, aef, i);
                u64 ad = dup2(a);
                const u64* wp = (const u64*)&sW2[i * DD + c4];
                fma2(a01, ad, wp[0]);
                fma2(a23, ad, wp[1]);
            }
            unpack2(a01, acc.x, acc.y);
            unpack2(a23, acc.z, acc.w);

            *(float4*)&out[(size_t)tr * DD + c4] = acc;
            s1[0] += acc.x; s1[1] += acc.y; s1[2] += acc.z; s1[3] += acc.w;
            s2[0] += acc.x * acc.x; s2[1] += acc.y * acc.y;
            s2[2] += acc.z * acc.z; s2[3] += acc.w * acc.w;
        }
    }

#pragma unroll
    for (int i = 0; i < 4; i++) {
        atomicAdd(&sRed[0][c4 + i], s1[i]);
        atomicAdd(&sRed[1][c4 + i], s2[i]);
    }
    __syncthreads();
    if (tid < DD) {
        atomicAdd(&g_s1b[tid], (double)sRed[0][tid]);
        atomicAdd(&g_s2b[tid], (double)sRed[1][tid]);
    }
}

// ---------------- bnrelu_o: apply BN2 (float consts) ----------------------
__global__ __launch_bounds__(256) void bnrelu_o_k(float* __restrict__ out) {
    int i = blockIdx.x * 256 + threadIdx.x;
    if (i >= M2 * 32) return;
    int c = (i & 31) << 2;
    float4 v = ((const float4*)out)[i];
    v.x = fmaxf(0.f, v.x * g_sc2[c + 0] + g_sh2[c + 0]);
    v.y = fmaxf(0.f, v.y * g_sc2[c + 1] + g_sh2[c + 1]);
    v.z = fmaxf(0.f, v.z * g_sc2[c + 2] + g_sh2[c + 2]);
    v.w = fmaxf(0.f, v.w * g_sc2[c + 3] + g_sh2[c + 3]);
    ((float4*)out)[i] = v;
}

// ---------------- launch ----------------
extern "C" void kernel_launch(void* const* d_in, const int* in_sizes, int n_in,
                              void* d_out, int out_size) {
    (void)in_sizes; (void)n_in; (void)out_size;
    const float* x        = (const float*)d_in[0];
    const int*   node_in  = (const int*)d_in[1];
    const int*   node_out = (const int*)d_in[2];
    const int*   relation = (const int*)d_in[3];
    const float* ew       = (const float*)d_in[4];
    const float* ef       = (const float*)d_in[5];
    const float* l1_Wlin  = (const float*)d_in[6];
    const float* l1_blin  = (const float*)d_in[7];
    const float* l1_Wself = (const float*)d_in[8];
    const float* l1_bself = (const float*)d_in[9];
    const float* l1_Wedge = (const float*)d_in[10];
    const float* l1_bedge = (const float*)d_in[11];
    const float* l1_g     = (const float*)d_in[12];
    const float* l1_b     = (const float*)d_in[13];
    const float* l2_Wlin  = (const float*)d_in[14];
    const float* l2_blin  = (const float*)d_in[15];
    const float* l2_Wself = (const float*)d_in[16];
    const float* l2_bself = (const float*)d_in[17];
    const float* l2_Wedge = (const float*)d_in[18];
    const float* l2_bedge = (const float*)d_in[19];
    const float* l2_g     = (const float*)d_in[20];
    const float* l2_b     = (const float*)d_in[21];
    float* out = (float*)d_out;

    int gmm = (NN + 127) / 128;   // 391
    int nsb = (NR + SCAN_BLK - 1) / SCAN_BLK;  // 391

    static int configured = 0;
    if (!configured) {
        cudaFuncSetAttribute(mma_L1_k, cudaFuncAttributeMaxDynamicSharedMemorySize,
                             MMAL1_SMEM);
        cudaFuncSetAttribute(mma1_k, cudaFuncAttributeMaxDynamicSharedMemorySize,
                             MMAL1_SMEM);
        configured = 1;
    }

    init_k<<<1024, 256>>>(x);
    prep_k<<<RR + 1, 128>>>(l1_Wedge, l1_Wlin, l1_bedge, l1_blin, l1_bself,
                            l2_Wedge, l2_Wlin, l2_bedge, l2_blin, l2_bself);
    prepBt_k<<<dim3(44, 4), dim3(32, 8)>>>(l1_Wlin, l1_Wself);
    prepBt2_k<<<dim3(8, 4), dim3(32, 8)>>>(l2_Wlin, l2_Wself);
    deg_k<<<EE / 256, 256>>>(node_out, relation, ew);
    scan1_k<<<nsb, 1024>>>();
    scan2_k<<<1, 512>>>();
    scan3_k<<<nsb, 1024>>>();
    place_k<<<EE / 256, 256>>>(node_in, node_out, relation, ew);
    agg1x_k<<<NR / 8, 256>>>(ef);
    mma_L1_k<<<gmm, 256, MMAL1_SMEM>>>();
    epi1_k<<<EPI1_BLOCKS, 256>>>();
    bnfin_k<<<1, 128>>>(0, (float)NN, l1_g, l1_b);
    bnrelu_hh_k<<<(NN * 32 + 255) / 256, 256>>>();
    mma1_k<<<dim3(gmm, 2), 256, MMAL1_SMEM>>>();
    agg2_k<<<AGG2_BLOCKS, 256>>>(out);
    bnfin_k<<<1, 128>>>(1, (float)M2, l2_g, l2_b);
    bnrelu_o_k<<<(M2 * 32) / 256, 256>>>(out);
}

// round 17
// speedup vs baseline: 1.4430x; 1.0208x over previous
#include <cuda_runtime.h>
#include <cuda_fp16.h>
#include <cstdint>

#define NN 50000
#define DD 128
#define RR 8
#define EE 800000
#define EDD 32
#define NR (NN*RR)
#define M2 (RR*NN)
#define K1 1408

typedef unsigned long long u64;

// ---------------- scratch ----------------
__device__ float  g_deg[NR];                 // indexed by tr = r*NN + no
__device__ __half g_aggef[NR*EDD];           // [r][no][32]
__device__ __half g_aggx[(size_t)NR*DD];     // [r][no][128]
__device__ __half g_xh[(size_t)NN*DD];       // x in half
__device__ __half g_hh[(size_t)NN*DD];       // relu(bn1(hpre)) in half
__device__ __half g_hW2h[(size_t)NN*DD];     // h @ Wlin2 in half
__device__ __half g_B1t[(size_t)DD*K1];      // [n][k] fused B1 transposed, half
__device__ __half g_B2t[(size_t)2*DD*DD];    // [sel][n][k]: Wlin2, Wself2
__device__ float  g_hpre[NN*DD];
__device__ float  g_hs[NN*DD];
__device__ float  g_WeWlin1[RR*EDD*DD];
__device__ float  g_WeWlin2[EDD*DD];
__device__ float  g_beWlin1[RR*DD];
__device__ float  g_beWlin2[DD];
__device__ float  g_bias1[DD];
__device__ float  g_bias2[DD];
__device__ double g_s1a[DD], g_s2a[DD], g_s1b[DD], g_s2b[DD];
__device__ float  g_sc1[DD], g_sh1[DD], g_sc2[DD], g_sh2[DD];
// CSR by tr (packed)
__device__ int   g_cnt[NR];
__device__ int   g_off[NR];
__device__ int   g_cur[NR];
__device__ int   g_bsum[512];
__device__ int4  g_csr4[EE];                 // {nin, eid, ew_bits, 0}

// ---------------- helpers ----------------
__device__ __forceinline__ uint32_t smem_u32(const void* p) {
    uint32_t a;
    asm("{ .reg .u64 t; cvta.to.shared.u64 t, %1; cvt.u32.u64 %0, t; }" : "=r"(a) : "l"(p));
    return a;
}
__device__ __forceinline__ u64 pack2(float lo, float hi) {
    u64 r; asm("mov.b64 %0, {%1, %2};" : "=l"(r) : "f"(lo), "f"(hi)); return r;
}
__device__ __forceinline__ u64 dup2(float v) {
    u64 r; asm("mov.b64 %0, {%1, %1};" : "=l"(r) : "f"(v)); return r;
}
__device__ __forceinline__ void unpack2(u64 v, float& lo, float& hi) {
    asm("mov.b64 {%0, %1}, %2;" : "=f"(lo), "=f"(hi) : "l"(v));
}
__device__ __forceinline__ void fma2(u64& d, u64 a, u64 b) {
    asm("fma.rn.f32x2 %0, %1, %2, %0;" : "+l"(d) : "l"(a), "l"(b));
}
__device__ __forceinline__ void mma_f16(float* d, const uint32_t* a,
                                        uint32_t b0, uint32_t b1) {
    asm volatile(
        "mma.sync.aligned.m16n8k16.row.col.f32.f16.f16.f32 "
        "{%0,%1,%2,%3}, {%4,%5,%6,%7}, {%8,%9}, {%0,%1,%2,%3};"
        : "+f"(d[0]), "+f"(d[1]), "+f"(d[2]), "+f"(d[3])
        : "r"(a[0]), "r"(a[1]), "r"(a[2]), "r"(a[3]), "r"(b0), "r"(b1));
}
__device__ __forceinline__ void cpa16(uint32_t d, const void* s) {
    asm volatile("cp.async.ca.shared.global [%0], [%1], 16;" :: "r"(d), "l"(s) : "memory");
}

// ---------------- init: zero small buffers + x->half ----------------
__global__ __launch_bounds__(256) void init_k(const float* __restrict__ x) {
    size_t i = (size_t)blockIdx.x * blockDim.x + threadIdx.x;
    size_t stride = (size_t)gridDim.x * blockDim.x;
    float4 z = make_float4(0.f, 0.f, 0.f, 0.f);
    float4* d = (float4*)g_deg;
    for (size_t j = i; j < (size_t)NR / 4; j += stride) d[j] = z;
    int4* c = (int4*)g_cnt;
    int4 zi = make_int4(0, 0, 0, 0);
    for (size_t j = i; j < (size_t)NR / 4; j += stride) c[j] = zi;
    for (size_t j = i; j < (size_t)NN * 32; j += stride) {
        float4 v = ((const float4*)x)[j];
        __half2* dst = (__half2*)g_xh + j * 2;
        dst[0] = __floats2half2_rn(v.x, v.y);
        dst[1] = __floats2half2_rn(v.z, v.w);
    }
    if (i < DD) { g_s1a[i] = 0.0; g_s2a[i] = 0.0; g_s1b[i] = 0.0; g_s2b[i] = 0.0; }
}

// ---------------- prep: folds ----------------
__global__ __launch_bounds__(128) void prep_k(
    const float* __restrict__ l1_We, const float* __restrict__ l1_Wlin,
    const float* __restrict__ l1_be, const float* __restrict__ l1_blin,
    const float* __restrict__ l1_bself,
    const float* __restrict__ l2_We, const float* __restrict__ l2_Wlin,
    const float* __restrict__ l2_be, const float* __restrict__ l2_blin,
    const float* __restrict__ l2_bself)
{
    __shared__ float sWe[EDD * DD];
    __shared__ float sbe[DD];
    int r = blockIdx.x;
    int d = threadIdx.x;
    const float* We = (r < RR) ? l1_We : l2_We;
    const float* Wl = (r < RR) ? l1_Wlin : l2_Wlin;
    const float* be = (r < RR) ? l1_be : l2_be;
    for (int i = d; i < EDD * DD; i += 128) sWe[i] = We[i];
    sbe[d] = be[d];
    __syncthreads();
    float acc[EDD];
#pragma unroll
    for (int i = 0; i < EDD; i++) acc[i] = 0.f;
    float accb = 0.f;
    int rowoff = (r < RR) ? r * DD : 0;
    for (int k = 0; k < DD; k++) {
        float wl = Wl[(size_t)(rowoff + k) * DD + d];
        accb += sbe[k] * wl;
#pragma unroll
        for (int i = 0; i < EDD; i++) acc[i] += sWe[i * DD + k] * wl;
    }
    if (r < RR) {
#pragma unroll
        for (int i = 0; i < EDD; i++) g_WeWlin1[(size_t)(r * EDD + i) * DD + d] = acc[i];
        g_beWlin1[r * DD + d] = accb;
    } else {
#pragma unroll
        for (int i = 0; i < EDD; i++) g_WeWlin2[(size_t)i * DD + d] = acc[i];
        g_beWlin2[d] = accb;
        g_bias1[d] = l1_blin[d] + l1_bself[d];
        g_bias2[d] = l2_blin[d] + l2_bself[d];
    }
}

// ---------------- prepBt: tiled transpose -> B1t[n][k] half ----------------
__global__ __launch_bounds__(256) void prepBt_k(const float* __restrict__ Wlin1,
                                                const float* __restrict__ Wself1) {
    __shared__ float tile[32][33];
    int k0 = blockIdx.x * 32;
    int n0 = blockIdx.y * 32;
    int tx = threadIdx.x;
    int ty = threadIdx.y;
#pragma unroll
    for (int i = 0; i < 4; i++) {
        int k = k0 + ty + i * 8;
        int n = n0 + tx;
        float v;
        if (k < 1024)      v = Wlin1[(size_t)k * DD + n];
        else if (k < 1280) v = g_WeWlin1[(size_t)(k - 1024) * DD + n];
        else               v = Wself1[(size_t)(k - 1280) * DD + n];
        tile[ty + i * 8][tx] = v;
    }
    __syncthreads();
#pragma unroll
    for (int i = 0; i < 4; i++) {
        int n = n0 + ty + i * 8;
        int k = k0 + tx;
        g_B1t[(size_t)n * K1 + k] = __float2half_rn(tile[tx][ty + i * 8]);
    }
}

// ---------------- prepBt2: B2t[sel][n][k] half (Wlin2 / Wself2) -----------
__global__ __launch_bounds__(256) void prepBt2_k(const float* __restrict__ Wlin2,
                                                 const float* __restrict__ Wself2) {
    __shared__ float tile[32][33];
    int k0 = (blockIdx.x & 3) * 32;
    int n0 = blockIdx.y * 32;
    int sel = blockIdx.x >> 2;
    const float* W = sel ? Wself2 : Wlin2;
    int tx = threadIdx.x;
    int ty = threadIdx.y;
#pragma unroll
    for (int i = 0; i < 4; i++)
        tile[ty + i * 8][tx] = W[(size_t)(k0 + ty + i * 8) * DD + n0 + tx];
    __syncthreads();
#pragma unroll
    for (int i = 0; i < 4; i++) {
        int n = n0 + ty + i * 8;
        int k = k0 + tx;
        g_B2t[(size_t)sel * DD * DD + (size_t)n * DD + k] =
            __float2half_rn(tile[tx][ty + i * 8]);
    }
}

// ---------------- degree + histogram (by tr) ----------------
__global__ void deg_k(const int* __restrict__ nout, const int* __restrict__ rel,
                      const float* __restrict__ w) {
    int e = blockIdx.x * blockDim.x + threadIdx.x;
    if (e < EE) {
        int tr = rel[e] * NN + nout[e];
        atomicAdd(&g_deg[tr], w[e]);
        atomicAdd(&g_cnt[tr], 1);
    }
}

// ---------------- scan (exclusive prefix over g_cnt) ----------------
#define SCAN_BLK 1024
__global__ __launch_bounds__(1024) void scan1_k() {
    __shared__ int sh[SCAN_BLK];
    int t = threadIdx.x;
    int i = blockIdx.x * SCAN_BLK + t;
    sh[t] = (i < NR) ? g_cnt[i] : 0;
    __syncthreads();
    for (int s = 512; s > 0; s >>= 1) {
        if (t < s) sh[t] += sh[t + s];
        __syncthreads();
    }
    if (t == 0) g_bsum[blockIdx.x] = sh[0];
}
__global__ __launch_bounds__(512) void scan2_k() {
    __shared__ int sh[512];
    int t = threadIdx.x;
    int nb = (NR + SCAN_BLK - 1) / SCAN_BLK;
    int orig = (t < nb) ? g_bsum[t] : 0;
    sh[t] = orig;
    __syncthreads();
    for (int d = 1; d < 512; d <<= 1) {
        int x = (t >= d) ? sh[t - d] : 0;
        __syncthreads();
        sh[t] += x;
        __syncthreads();
    }
    if (t < nb) g_bsum[t] = sh[t] - orig;
}
__global__ __launch_bounds__(1024) void scan3_k() {
    __shared__ int sh[SCAN_BLK];
    int t = threadIdx.x;
    int i = blockIdx.x * SCAN_BLK + t;
    int orig = (i < NR) ? g_cnt[i] : 0;
    sh[t] = orig;
    __syncthreads();
    for (int d = 1; d < SCAN_BLK; d <<= 1) {
        int x = (t >= d) ? sh[t - d] : 0;
        __syncthreads();
        sh[t] += x;
        __syncthreads();
    }
    if (i < NR) {
        int excl = sh[t] - orig + g_bsum[blockIdx.x];
        g_off[i] = excl;
        g_cur[i] = excl;
    }
}
__global__ void place_k(const int* __restrict__ nin, const int* __restrict__ nout,
                        const int* __restrict__ rel, const float* __restrict__ w) {
    int e = blockIdx.x * blockDim.x + threadIdx.x;
    if (e < EE) {
        int tr = rel[e] * NN + nout[e];
        int pos = atomicAdd(&g_cur[tr], 1);
        g_csr4[pos] = make_int4(nin[e], e, __float_as_int(w[e] / g_deg[tr]), 0);
    }
}

// ---------------- agg1x: warp-per-tr CSR gather (g_xh half, ILP-2) --------
__global__ __launch_bounds__(256) void agg1x_k(const float* __restrict__ ef) {
    int tid = threadIdx.x;
    int wid = tid >> 5;
    int lane = tid & 31;
    int c4 = lane << 2;
    int tr = blockIdx.x * 8 + wid;
    if (tr >= NR) return;

    int off = g_off[tr];
    int cnt = g_cnt[tr];
    float4 xa = make_float4(0.f, 0.f, 0.f, 0.f);
    float4 xb = make_float4(0.f, 0.f, 0.f, 0.f);
    float ea = 0.f, eb = 0.f;
    int j = 0;
    for (; j + 2 <= cnt; j += 2) {
        int4 c0 = __ldg(&g_csr4[off + j]);
        int4 c1 = __ldg(&g_csr4[off + j + 1]);
        float w0 = __int_as_float(c0.z), w1 = __int_as_float(c1.z);
        uint2 r0 = __ldg((const uint2*)&g_xh[(size_t)c0.x * DD + c4]);
        uint2 r1 = __ldg((const uint2*)&g_xh[(size_t)c1.x * DD + c4]);
        float f0 = __ldg(&ef[(size_t)c0.y * EDD + lane]);
        float f1 = __ldg(&ef[(size_t)c1.y * EDD + lane]);
        float2 p00 = __half22float2(*(__half2*)&r0.x);
        float2 p01 = __half22float2(*(__half2*)&r0.y);
        float2 p10 = __half22float2(*(__half2*)&r1.x);
        float2 p11 = __half22float2(*(__half2*)&r1.y);
        xa.x += w0 * p00.x; xa.y += w0 * p00.y;
        xa.z += w0 * p01.x; xa.w += w0 * p01.y;
        xb.x += w1 * p10.x; xb.y += w1 * p10.y;
        xb.z += w1 * p11.x; xb.w += w1 * p11.y;
        ea += w0 * f0; eb += w1 * f1;
    }
    if (j < cnt) {
        int4 c0 = __ldg(&g_csr4[off + j]);
        float w0 = __int_as_float(c0.z);
        uint2 r0 = __ldg((const uint2*)&g_xh[(size_t)c0.x * DD + c4]);
        float2 p00 = __half22float2(*(__half2*)&r0.x);
        float2 p01 = __half22float2(*(__half2*)&r0.y);
        xa.x += w0 * p00.x; xa.y += w0 * p00.y;
        xa.z += w0 * p01.x; xa.w += w0 * p01.y;
        ea += w0 * __ldg(&ef[(size_t)c0.y * EDD + lane]);
    }
    xa.x += xb.x; xa.y += xb.y; xa.z += xb.z; xa.w += xb.w;
    __half2* dst = (__half2*)&g_aggx[(size_t)tr * DD + c4];
    dst[0] = __floats2half2_rn(xa.x, xa.y);
    dst[1] = __floats2half2_rn(xa.z, xa.w);
    g_aggef[(size_t)tr * EDD + lane] = __float2half_rn(ea + eb);
}

// ---------------- mma_L1: hpre = [aggx|aggef|x] @ B1t, fp16 m16n8k16 -----
#define A_PADH 40
#define B_PADH 40
#define A_BYTES (128 * A_PADH * 2)
#define BH_BYTES (128 * B_PADH * 2)
#define STG_BYTES (A_BYTES + BH_BYTES)
#define MMAL1_SMEM (3 * STG_BYTES)
#define NCH_L1 44

__global__ void __launch_bounds__(256, 2) mma_L1_k() {
    extern __shared__ char smc[];
    int tid = threadIdx.x;
    int m0 = blockIdx.x * 128;
    uint32_t sb = smem_u32(smc);

    auto load_stage = [&](int s, int kc) {
        const __half* Asrc;
        int astride;
        if (kc < 32) {
            int r = kc >> 2;
            Asrc = g_aggx + (size_t)r * NN * DD + (kc & 3) * 32;
            astride = DD;
        } else if (kc < 40) {
            int r = kc - 32;
            Asrc = g_aggef + (size_t)r * NN * EDD;
            astride = EDD;
        } else {
            Asrc = g_xh + (kc - 40) * 32;
            astride = DD;
        }
#pragma unroll
        for (int j = 0; j < 2; j++) {
            int p = tid + j * 256;
            int row = p >> 2;
            int kq = (p & 3) * 8;
            uint32_t doff = sb + s * STG_BYTES + row * (A_PADH * 2) + kq * 2;
            int m = m0 + row;
            if (m < NN) cpa16(doff, Asrc + (size_t)m * astride + kq);
            else {
                float4 z = make_float4(0.f, 0.f, 0.f, 0.f);
                *(float4*)(smc + s * STG_BYTES + row * (A_PADH * 2) + kq * 2) = z;
            }
        }
        const __half* Bsrc = g_B1t + (size_t)kc * 32;
#pragma unroll
        for (int j = 0; j < 2; j++) {
            int p = tid + j * 256;
            int n = p >> 2;
            int kq = (p & 3) * 8;
            uint32_t doff = sb + s * STG_BYTES + A_BYTES + n * (B_PADH * 2) + kq * 2;
            cpa16(doff, Bsrc + (size_t)n * K1 + kq);
        }
        asm volatile("cp.async.commit_group;" ::: "memory");
    };

    int wid = tid >> 5, lane = tid & 31;
    int g = lane >> 2, t = lane & 3;
    int wm = (wid & 3) * 32, wn = (wid >> 2) * 64;

    float acc[2][8][4];
#pragma unroll
    for (int mi = 0; mi < 2; mi++)
#pragma unroll
        for (int ni = 0; ni < 8; ni++) {
            acc[mi][ni][0] = 0.f; acc[mi][ni][1] = 0.f;
            acc[mi][ni][2] = 0.f; acc[mi][ni][3] = 0.f;
        }

    load_stage(0, 0);
    load_stage(1, 1);

    for (int kc = 0; kc < NCH_L1; kc++) {
        if (kc + 2 < NCH_L1) {
            load_stage((kc + 2) % 3, kc + 2);
            asm volatile("cp.async.wait_group 2;" ::: "memory");
        } else if (kc + 1 < NCH_L1) {
            asm volatile("cp.async.wait_group 1;" ::: "memory");
        } else {
            asm volatile("cp.async.wait_group 0;" ::: "memory");
        }
        __syncthreads();
        const __half* hA = (const __half*)(smc + (kc % 3) * STG_BYTES);
        const __half* hB = (const __half*)(smc + (kc % 3) * STG_BYTES + A_BYTES);
#pragma unroll
        for (int ks = 0; ks < 2; ks++) {
            int kb = ks * 16;
            uint32_t a[2][4];
#pragma unroll
            for (int mi = 0; mi < 2; mi++) {
                int bm = wm + mi * 16;
                a[mi][0] = *(const uint32_t*)&hA[(bm + g) * A_PADH + kb + 2 * t];
                a[mi][1] = *(const uint32_t*)&hA[(bm + g + 8) * A_PADH + kb + 2 * t];
                a[mi][2] = *(const uint32_t*)&hA[(bm + g) * A_PADH + kb + 2 * t + 8];
                a[mi][3] = *(const uint32_t*)&hA[(bm + g + 8) * A_PADH + kb + 2 * t + 8];
            }
#pragma unroll
            for (int ni = 0; ni < 8; ni++) {
                int bn = wn + ni * 8;
                uint32_t b0 = *(const uint32_t*)&hB[(bn + g) * B_PADH + kb + 2 * t];
                uint32_t b1 = *(const uint32_t*)&hB[(bn + g) * B_PADH + kb + 2 * t + 8];
                mma_f16(acc[0][ni], a[0], b0, b1);
                mma_f16(acc[1][ni], a[1], b0, b1);
            }
        }
        __syncthreads();
    }

#pragma unroll
    for (int mi = 0; mi < 2; mi++) {
#pragma unroll
        for (int ni = 0; ni < 8; ni++) {
            int mg = m0 + wm + mi * 16 + g;
            int c = wn + ni * 8 + 2 * t;
            if (mg < NN)
                *(float2*)&g_hpre[(size_t)mg * DD + c] =
                    make_float2(acc[mi][ni][0], acc[mi][ni][1]);
            if (mg + 8 < NN)
                *(float2*)&g_hpre[(size_t)(mg + 8) * DD + c] =
                    make_float2(acc[mi][ni][2], acc[mi][ni][3]);
        }
    }
}

// ---------------- epi1: hpre += bias1 + mask*beW1 ; BN1 stats -------------
#define EPI1_BLOCKS 1184
__global__ __launch_bounds__(256) void epi1_k() {
    __shared__ __align__(16) float sBe[RR * DD];
    __shared__ float sBias[DD];
    __shared__ float sRed[2][DD];
    int tid = threadIdx.x;
    int wid = tid >> 5;
    int lane = tid & 31;
    int c4 = lane << 2;
    for (int i = tid; i < RR * DD; i += 256) sBe[i] = g_beWlin1[i];
    if (tid < DD) { sBias[tid] = g_bias1[tid]; sRed[0][tid] = 0.f; sRed[1][tid] = 0.f; }
    __syncthreads();

    float s1[4] = {0.f, 0.f, 0.f, 0.f};
    float s2[4] = {0.f, 0.f, 0.f, 0.f};

    for (int m = blockIdx.x * 8 + wid; m < NN; m += EPI1_BLOCKS * 8) {
        int cbit = (lane < RR) ? (g_cnt[lane * NN + m] > 0) : 0;
        unsigned mask8 = __ballot_sync(0xffffffffu, cbit) & 0xFFu;

        float4 v = *(float4*)&g_hpre[(size_t)m * DD + c4];
        v.x += sBias[c4 + 0]; v.y += sBias[c4 + 1];
        v.z += sBias[c4 + 2]; v.w += sBias[c4 + 3];
#pragma unroll
        for (int r = 0; r < RR; r++) {
            if ((mask8 >> r) & 1u) {
                float4 be = *(float4*)&sBe[r * DD + c4];
                v.x += be.x; v.y += be.y; v.z += be.z; v.w += be.w;
            }
        }
        *(float4*)&g_hpre[(size_t)m * DD + c4] = v;
        s1[0] += v.x; s1[1] += v.y; s1[2] += v.z; s1[3] += v.w;
        s2[0] += v.x * v.x; s2[1] += v.y * v.y;
        s2[2] += v.z * v.z; s2[3] += v.w * v.w;
    }

#pragma unroll
    for (int i = 0; i < 4; i++) {
        atomicAdd(&sRed[0][c4 + i], s1[i]);
        atomicAdd(&sRed[1][c4 + i], s2[i]);
    }
    __syncthreads();
    if (tid < DD) {
        atomicAdd(&g_s1a[tid], (double)sRed[0][tid]);
        atomicAdd(&g_s2a[tid], (double)sRed[1][tid]);
    }
}

// ---------------- BN finalize (float consts for consumers) ----------------
__global__ void bnfin_k(int sel, float nrows, const float* __restrict__ g,
                        const float* __restrict__ b) {
    int d = threadIdx.x;
    double s1 = sel ? g_s1b[d] : g_s1a[d];
    double s2 = sel ? g_s2b[d] : g_s2a[d];
    double m = s1 / (double)nrows;
    double var = s2 / (double)nrows - m * m;
    float sc = g[d] * rsqrtf((float)var + 1e-5f);
    float sh = b[d] - (float)m * sc;
    if (sel) { g_sc2[d] = sc; g_sh2[d] = sh; }
    else     { g_sc1[d] = sc; g_sh1[d] = sh; }
}

// ---------------- bnrelu_hh: g_hh = half(relu(bn1(hpre))) -----------------
__global__ __launch_bounds__(256) void bnrelu_hh_k() {
    int i = blockIdx.x * 256 + threadIdx.x;
    if (i >= NN * 32) return;
    int c = (i & 31) << 2;
    float4 v = ((const float4*)g_hpre)[i];
    v.x = fmaxf(0.f, v.x * g_sc1[c + 0] + g_sh1[c + 0]);
    v.y = fmaxf(0.f, v.y * g_sc1[c + 1] + g_sh1[c + 1]);
    v.z = fmaxf(0.f, v.z * g_sc1[c + 2] + g_sh1[c + 2]);
    v.w = fmaxf(0.f, v.w * g_sc1[c + 3] + g_sh1[c + 3]);
    __half2* dst = (__half2*)g_hh + (size_t)i * 2;
    dst[0] = __floats2half2_rn(v.x, v.y);
    dst[1] = __floats2half2_rn(v.z, v.w);
}

// ---------------- mma1: fp16, A = g_hh, B = B2t[sel] ----------------------
// rsel=0: dst g_hW2h (half); rsel=1: dst g_hs (float, +bias2)
#define NCH_M1 4
__global__ void __launch_bounds__(256, 2) mma1_k() {
    extern __shared__ char smc[];
    int tid = threadIdx.x;
    int m0 = blockIdx.x * 128;
    int rsel = blockIdx.y;

    const float* bias = rsel ? g_bias2 : nullptr;
    const __half* Bt = g_B2t + (size_t)rsel * DD * DD;

    uint32_t sb = smem_u32(smc);

    auto load_stage = [&](int s, int kc) {
        const __half* Asrc = g_hh + kc * 32;
#pragma unroll
        for (int j = 0; j < 2; j++) {
            int p = tid + j * 256;
            int row = p >> 2;
            int kq = (p & 3) * 8;
            uint32_t doff = sb + s * STG_BYTES + row * (A_PADH * 2) + kq * 2;
            int m = m0 + row;
            if (m < NN) cpa16(doff, Asrc + (size_t)m * DD + kq);
            else {
                float4 z = make_float4(0.f, 0.f, 0.f, 0.f);
                *(float4*)(smc + s * STG_BYTES + row * (A_PADH * 2) + kq * 2) = z;
            }
        }
        const __half* Bsrc = Bt + kc * 32;
#pragma unroll
        for (int j = 0; j < 2; j++) {
            int p = tid + j * 256;
            int n = p >> 2;
            int kq = (p & 3) * 8;
            uint32_t doff = sb + s * STG_BYTES + A_BYTES + n * (B_PADH * 2) + kq * 2;
            cpa16(doff, Bsrc + (size_t)n * DD + kq);
        }
        asm volatile("cp.async.commit_group;" ::: "memory");
    };

    int wid = tid >> 5, lane = tid & 31;
    int g = lane >> 2, t = lane & 3;
    int wm = (wid & 3) * 32, wn = (wid >> 2) * 64;

    float acc[2][8][4];
#pragma unroll
    for (int mi = 0; mi < 2; mi++)
#pragma unroll
        for (int ni = 0; ni < 8; ni++) {
            acc[mi][ni][0] = 0.f; acc[mi][ni][1] = 0.f;
            acc[mi][ni][2] = 0.f; acc[mi][ni][3] = 0.f;
        }

    load_stage(0, 0);
    load_stage(1, 1);

    for (int kc = 0; kc < NCH_M1; kc++) {
        if (kc + 2 < NCH_M1) {
            load_stage((kc + 2) % 3, kc + 2);
            asm volatile("cp.async.wait_group 2;" ::: "memory");
        } else if (kc + 1 < NCH_M1) {
            asm volatile("cp.async.wait_group 1;" ::: "memory");
        } else {
            asm volatile("cp.async.wait_group 0;" ::: "memory");
        }
        __syncthreads();
        const __half* hA = (const __half*)(smc + (kc % 3) * STG_BYTES);
        const __half* hB = (const __half*)(smc + (kc % 3) * STG_BYTES + A_BYTES);
#pragma unroll
        for (int ks = 0; ks < 2; ks++) {
            int kb = ks * 16;
            uint32_t a[2][4];
#pragma unroll
            for (int mi = 0; mi < 2; mi++) {
                int bm = wm + mi * 16;
                a[mi][0] = *(const uint32_t*)&hA[(bm + g) * A_PADH + kb + 2 * t];
                a[mi][1] = *(const uint32_t*)&hA[(bm + g + 8) * A_PADH + kb + 2 * t];
                a[mi][2] = *(const uint32_t*)&hA[(bm + g) * A_PADH + kb + 2 * t + 8];
                a[mi][3] = *(const uint32_t*)&hA[(bm + g + 8) * A_PADH + kb + 2 * t + 8];
            }
#pragma unroll
            for (int ni = 0; ni < 8; ni++) {
                int bn = wn + ni * 8;
                uint32_t b0 = *(const uint32_t*)&hB[(bn + g) * B_PADH + kb + 2 * t];
                uint32_t b1 = *(const uint32_t*)&hB[(bn + g) * B_PADH + kb + 2 * t + 8];
                mma_f16(acc[0][ni], a[0], b0, b1);
                mma_f16(acc[1][ni], a[1], b0, b1);
            }
        }
        __syncthreads();
    }

#pragma unroll
    for (int mi = 0; mi < 2; mi++) {
#pragma unroll
        for (int ni = 0; ni < 8; ni++) {
            int mg = m0 + wm + mi * 16 + g;
            int c = wn + ni * 8 + 2 * t;
            if (rsel) {
                float b0 = bias[c], b1 = bias[c + 1];
                if (mg < NN)
                    *(float2*)&g_hs[(size_t)mg * DD + c] =
                        make_float2(acc[mi][ni][0] + b0, acc[mi][ni][1] + b1);
                if (mg + 8 < NN)
                    *(float2*)&g_hs[(size_t)(mg + 8) * DD + c] =
                        make_float2(acc[mi][ni][2] + b0, acc[mi][ni][3] + b1);
            } else {
                if (mg < NN)
                    *(__half2*)&g_hW2h[(size_t)mg * DD + c] =
                        __floats2half2_rn(acc[mi][ni][0], acc[mi][ni][1]);
                if (mg + 8 < NN)
                    *(__half2*)&g_hW2h[(size_t)(mg + 8) * DD + c] =
                        __floats2half2_rn(acc[mi][ni][2], acc[mi][ni][3]);
            }
        }
    }
}

// ---------------- agg2: warp-per-node layer-2 assembly + BN2 stats --------
// gathers hW2 in HALF (halved L2 stream); fast path for empty rows.
#define AGG2_BLOCKS 1184
__global__ __launch_bounds__(256) void agg2_k(float* __restrict__ out) {
    __shared__ __align__(16) float sW2[EDD * DD];
    __shared__ __align__(16) float sBe2[DD];
    __shared__ float sRed[2][DD];
    int tid = threadIdx.x;
    int wid = tid >> 5;
    int lane = tid & 31;
    int c4 = lane << 2;
    for (int i = tid; i < EDD * DD; i += 256) sW2[i] = g_WeWlin2[i];
    if (tid < DD) { sBe2[tid] = g_beWlin2[tid]; sRed[0][tid] = 0.f; sRed[1][tid] = 0.f; }
    __syncthreads();

    float s1[4] = {0.f, 0.f, 0.f, 0.f};
    float s2[4] = {0.f, 0.f, 0.f, 0.f};

    for (int no = blockIdx.x * 8 + wid; no < NN; no += AGG2_BLOCKS * 8) {
        float4 hsv = __ldg((const float4*)&g_hs[(size_t)no * DD + c4]);
#pragma unroll
        for (int r = 0; r < RR; r++) {
            int tr = r * NN + no;
            int cnt = g_cnt[tr];
            if (cnt == 0) {
                *(float4*)&out[(size_t)tr * DD + c4] = hsv;
                s1[0] += hsv.x; s1[1] += hsv.y; s1[2] += hsv.z; s1[3] += hsv.w;
                s2[0] += hsv.x * hsv.x; s2[1] += hsv.y * hsv.y;
                s2[2] += hsv.z * hsv.z; s2[3] += hsv.w * hsv.w;
                continue;
            }
            int off = g_off[tr];
            float4 acc = hsv;
            {
                float4 be = *(float4*)&sBe2[c4];
                acc.x += be.x; acc.y += be.y; acc.z += be.z; acc.w += be.w;
            }
            for (int j = 0; j < cnt; j++) {
                int4 cs = __ldg(&g_csr4[off + j]);
                float w = __int_as_float(cs.z);
                uint2 hv = __ldg((const uint2*)&g_hW2h[(size_t)cs.x * DD + c4]);
                float2 p0 = __half22float2(*(__half2*)&hv.x);
                float2 p1 = __half22float2(*(__half2*)&hv.y);
                acc.x += w * p0.x; acc.y += w * p0.y;
                acc.z += w * p1.x; acc.w += w * p1.y;
            }

            float aef = __half2float(g_aggef[(size_t)tr * EDD + lane]);
            u64 a01 = pack2(acc.x, acc.y), a23 = pack2(acc.z, acc.w);
#pragma unroll
            for (int i = 0; i < EDD; i++) {
                float a = __shfl_sync(0xffffffffu, aef, i);
                u64 ad = dup2(a);
                const u64* wp = (const u64*)&sW2[i * DD + c4];
                fma2(a01, ad, wp[0]);
                fma2(a23, ad, wp[1]);
            }
            unpack2(a01, acc.x, acc.y);
            unpack2(a23, acc.z, acc.w);

            *(float4*)&out[(size_t)tr * DD + c4] = acc;
            s1[0] += acc.x; s1[1] += acc.y; s1[2] += acc.z; s1[3] += acc.w;
            s2[0] += acc.x * acc.x; s2[1] += acc.y * acc.y;
            s2[2] += acc.z * acc.z; s2[3] += acc.w * acc.w;
        }
    }

#pragma unroll
    for (int i = 0; i < 4; i++) {
        atomicAdd(&sRed[0][c4 + i], s1[i]);
        atomicAdd(&sRed[1][c4 + i], s2[i]);
    }
    __syncthreads();
    if (tid < DD) {
        atomicAdd(&g_s1b[tid], (double)sRed[0][tid]);
        atomicAdd(&g_s2b[tid], (double)sRed[1][tid]);
    }
}

// ---------------- bnrelu_o: apply BN2 (float consts) ----------------------
__global__ __launch_bounds__(256) void bnrelu_o_k(float* __restrict__ out) {
    int i = blockIdx.x * 256 + threadIdx.x;
    if (i >= M2 * 32) return;
    int c = (i & 31) << 2;
    float4 v = ((const float4*)out)[i];
    v.x = fmaxf(0.f, v.x * g_sc2[c + 0] + g_sh2[c + 0]);
    v.y = fmaxf(0.f, v.y * g_sc2[c + 1] + g_sh2[c + 1]);
    v.z = fmaxf(0.f, v.z * g_sc2[c + 2] + g_sh2[c + 2]);
    v.w = fmaxf(0.f, v.w * g_sc2[c + 3] + g_sh2[c + 3]);
    ((float4*)out)[i] = v;
}

// ---------------- launch ----------------
extern "C" void kernel_launch(void* const* d_in, const int* in_sizes, int n_in,
                              void* d_out, int out_size) {
    (void)in_sizes; (void)n_in; (void)out_size;
    const float* x        = (const float*)d_in[0];
    const int*   node_in  = (const int*)d_in[1];
    const int*   node_out = (const int*)d_in[2];
    const int*   relation = (const int*)d_in[3];
    const float* ew       = (const float*)d_in[4];
    const float* ef       = (const float*)d_in[5];
    const float* l1_Wlin  = (const float*)d_in[6];
    const float* l1_blin  = (const float*)d_in[7];
    const float* l1_Wself = (const float*)d_in[8];
    const float* l1_bself = (const float*)d_in[9];
    const float* l1_Wedge = (const float*)d_in[10];
    const float* l1_bedge = (const float*)d_in[11];
    const float* l1_g     = (const float*)d_in[12];
    const float* l1_b     = (const float*)d_in[13];
    const float* l2_Wlin  = (const float*)d_in[14];
    const float* l2_blin  = (const float*)d_in[15];
    const float* l2_Wself = (const float*)d_in[16];
    const float* l2_bself = (const float*)d_in[17];
    const float* l2_Wedge = (const float*)d_in[18];
    const float* l2_bedge = (const float*)d_in[19];
    const float* l2_g     = (const float*)d_in[20];
    const float* l2_b     = (const float*)d_in[21];
    float* out = (float*)d_out;

    int gmm = (NN + 127) / 128;   // 391
    int nsb = (NR + SCAN_BLK - 1) / SCAN_BLK;  // 391

    static int configured = 0;
    if (!configured) {
        cudaFuncSetAttribute(mma_L1_k, cudaFuncAttributeMaxDynamicSharedMemorySize,
                             MMAL1_SMEM);
        cudaFuncSetAttribute(mma1_k, cudaFuncAttributeMaxDynamicSharedMemorySize,
                             MMAL1_SMEM);
        configured = 1;
    }

    init_k<<<1024, 256>>>(x);
    prep_k<<<RR + 1, 128>>>(l1_Wedge, l1_Wlin, l1_bedge, l1_blin, l1_bself,
                            l2_Wedge, l2_Wlin, l2_bedge, l2_blin, l2_bself);
    prepBt_k<<<dim3(44, 4), dim3(32, 8)>>>(l1_Wlin, l1_Wself);
    prepBt2_k<<<dim3(8, 4), dim3(32, 8)>>>(l2_Wlin, l2_Wself);
    deg_k<<<EE / 256, 256>>>(node_out, relation, ew);
    scan1_k<<<nsb, 1024>>>();
    scan2_k<<<1, 512>>>();
    scan3_k<<<nsb, 1024>>>();
    place_k<<<EE / 256, 256>>>(node_in, node_out, relation, ew);
    agg1x_k<<<NR / 8, 256>>>(ef);
    mma_L1_k<<<gmm, 256, MMAL1_SMEM>>>();
    epi1_k<<<EPI1_BLOCKS, 256>>>();
    bnfin_k<<<1, 128>>>(0, (float)NN, l1_g, l1_b);
    bnrelu_hh_k<<<(NN * 32 + 255) / 256, 256>>>();
    mma1_k<<<dim3(gmm, 2), 256, MMAL1_SMEM>>>();
    agg2_k<<<AGG2_BLOCKS, 256>>>(out);
    bnfin_k<<<1, 128>>>(1, (float)M2, l2_g, l2_b);
    bnrelu_o_k<<<(M2 * 32) / 256, 256>>>(out);
}